// round 2
// baseline (speedup 1.0000x reference)
#include <cuda_runtime.h>
#include <math.h>

// Problem constants
#define BB   4
#define TT   2048
#define DD   1024
#define HH   16
#define HDD  64
#define MTOT (BB*TT)   // 8192

// Scratch (static __device__ globals: allocation-free per harness rules)
__device__ float g_q [(size_t)BB*HH*TT*HDD];   // [B,H,T,HD]
__device__ float g_k [(size_t)BB*HH*TT*HDD];
__device__ float g_v [(size_t)BB*HH*TT*HDD];
__device__ float g_ao[(size_t)BB*TT*DD];       // [B,T,D] attention output (pre-proj)

// ============================================================================
// GEMM: C[M,N] = A[M,K] * W[N,K]^T   (both K-major, fp32)
// Tile 128x128xBK16, 256 threads, 8x8 microtile with scattered mapping:
//   rows r = ty + 16*i, cols c = tx + 16*j  -> conflict-free scalar LDS.
// ============================================================================

// QKV projection: writes permuted into [B,H,T,HD]
__global__ __launch_bounds__(256) void qkv_gemm_kernel(
    const float* __restrict__ x,
    const float* __restrict__ Wq,
    const float* __restrict__ Wk,
    const float* __restrict__ Wv)
{
    __shared__ float As[128][17];
    __shared__ float Bs[128][17];

    const int which = blockIdx.z;
    const float* __restrict__ Wp = (which == 0) ? Wq : (which == 1) ? Wk : Wv;
    float* __restrict__ outp     = (which == 0) ? g_q : (which == 1) ? g_k : g_v;

    const int tid = threadIdx.x;
    const int tx = tid & 15;
    const int ty = tid >> 4;
    const int m0 = blockIdx.y * 128;
    const int n0 = blockIdx.x * 128;

    float acc[8][8];
    #pragma unroll
    for (int i = 0; i < 8; i++)
        #pragma unroll
        for (int j = 0; j < 8; j++) acc[i][j] = 0.0f;

    for (int k0 = 0; k0 < DD; k0 += 16) {
        #pragma unroll
        for (int s = 0; s < 2; s++) {
            int idx = tid + s * 256;
            int r  = idx >> 2;          // 0..127
            int kq = (idx & 3) << 2;    // 0,4,8,12 (16-wide K tile)
            float4 va = *(const float4*)(x  + (size_t)(m0 + r) * DD + k0 + kq);
            As[r][kq+0] = va.x; As[r][kq+1] = va.y; As[r][kq+2] = va.z; As[r][kq+3] = va.w;
            float4 vb = *(const float4*)(Wp + (size_t)(n0 + r) * DD + k0 + kq);
            Bs[r][kq+0] = vb.x; Bs[r][kq+1] = vb.y; Bs[r][kq+2] = vb.z; Bs[r][kq+3] = vb.w;
        }
        __syncthreads();
        #pragma unroll
        for (int k = 0; k < 16; k++) {
            float a[8], b[8];
            #pragma unroll
            for (int i = 0; i < 8; i++) a[i] = As[ty + 16*i][k];
            #pragma unroll
            for (int j = 0; j < 8; j++) b[j] = Bs[tx + 16*j][k];
            #pragma unroll
            for (int i = 0; i < 8; i++)
                #pragma unroll
                for (int j = 0; j < 8; j++) acc[i][j] = fmaf(a[i], b[j], acc[i][j]);
        }
        __syncthreads();
    }

    #pragma unroll
    for (int i = 0; i < 8; i++) {
        int row = m0 + ty + 16*i;
        int bb  = row >> 11;       // row / 2048
        int t   = row & 2047;
        #pragma unroll
        for (int j = 0; j < 8; j++) {
            int col = n0 + tx + 16*j;
            int h = col >> 6;
            int e = col & 63;
            outp[(((size_t)bb*HH + h)*TT + t)*HDD + e] = acc[i][j];
        }
    }
}

// Output projection: out = g_ao @ Wo^T + bo, written row-major to d_out
__global__ __launch_bounds__(256) void out_gemm_kernel(
    const float* __restrict__ Wo,
    const float* __restrict__ bo,
    float* __restrict__ outp)
{
    __shared__ float As[128][17];
    __shared__ float Bs[128][17];

    const int tid = threadIdx.x;
    const int tx = tid & 15;
    const int ty = tid >> 4;
    const int m0 = blockIdx.y * 128;
    const int n0 = blockIdx.x * 128;

    float acc[8][8];
    #pragma unroll
    for (int i = 0; i < 8; i++)
        #pragma unroll
        for (int j = 0; j < 8; j++) acc[i][j] = 0.0f;

    for (int k0 = 0; k0 < DD; k0 += 16) {
        #pragma unroll
        for (int s = 0; s < 2; s++) {
            int idx = tid + s * 256;
            int r  = idx >> 2;
            int kq = (idx & 3) << 2;
            float4 va = *(const float4*)(g_ao + (size_t)(m0 + r) * DD + k0 + kq);
            As[r][kq+0] = va.x; As[r][kq+1] = va.y; As[r][kq+2] = va.z; As[r][kq+3] = va.w;
            float4 vb = *(const float4*)(Wo + (size_t)(n0 + r) * DD + k0 + kq);
            Bs[r][kq+0] = vb.x; Bs[r][kq+1] = vb.y; Bs[r][kq+2] = vb.z; Bs[r][kq+3] = vb.w;
        }
        __syncthreads();
        #pragma unroll
        for (int k = 0; k < 16; k++) {
            float a[8], b[8];
            #pragma unroll
            for (int i = 0; i < 8; i++) a[i] = As[ty + 16*i][k];
            #pragma unroll
            for (int j = 0; j < 8; j++) b[j] = Bs[tx + 16*j][k];
            #pragma unroll
            for (int i = 0; i < 8; i++)
                #pragma unroll
                for (int j = 0; j < 8; j++) acc[i][j] = fmaf(a[i], b[j], acc[i][j]);
        }
        __syncthreads();
    }

    #pragma unroll
    for (int i = 0; i < 8; i++) {
        int row = m0 + ty + 16*i;
        #pragma unroll
        for (int j = 0; j < 8; j++) {
            int col = n0 + tx + 16*j;
            outp[(size_t)row*DD + col] = acc[i][j] + bo[col];
        }
    }
}

// ============================================================================
// Flash-style causal attention (fp32): per CTA one (b,h) and a 64-query tile.
// 256 threads (16x16), 4x4 microtiles, online softmax via 16-lane shuffles.
// ============================================================================
#define QS 65   // Qs row stride
#define KS 65   // Ks row stride
#define PS 65   // Ps row stride
#define VS 68   // Vs row stride (float4-aligned writes)
#define ATTN_SMEM_FLOATS (64*QS + 64*KS + 64*PS + 64*VS)
#define ATTN_SMEM_BYTES  (ATTN_SMEM_FLOATS * 4)

__global__ __launch_bounds__(256) void attn_kernel()
{
    extern __shared__ float sm[];
    float* Qs = sm;
    float* Ks = sm + 64*QS;
    float* Ps = sm + 64*QS + 64*KS;
    float* Vs = sm + 64*QS + 64*KS + 64*PS;

    const int bh = blockIdx.y;          // b*H + h
    const int h  = bh & (HH-1);
    const int b  = bh >> 4;
    const int qt = blockIdx.x;          // query tile 0..31
    const int q0 = qt * 64;

    const int tid = threadIdx.x;
    const int tx = tid & 15;
    const int ty = tid >> 4;

    const float* __restrict__ qb = g_q + (size_t)bh * TT * HDD;
    const float* __restrict__ kb = g_k + (size_t)bh * TT * HDD;
    const float* __restrict__ vb = g_v + (size_t)bh * TT * HDD;

    // Tile fill indexing: 64 rows x 64 cols = 16 float4/row; 4 threads per row,
    // each thread loads a contiguous 16-col chunk as 4 float4s.
    const int lr = tid >> 2;                 // row 0..63
    const int lc0 = (tid & 3) * 16;          // col chunk base: 0,16,32,48

    // Load Q tile once, pre-scaled by 1/sqrt(HD)=0.125
    {
        const float sc = 0.125f;
        #pragma unroll
        for (int s = 0; s < 4; s++) {
            int kq = lc0 + s * 4;
            float4 v4 = *(const float4*)(qb + (size_t)(q0 + lr) * HDD + kq);
            Qs[lr*QS + kq+0] = v4.x * sc;
            Qs[lr*QS + kq+1] = v4.y * sc;
            Qs[lr*QS + kq+2] = v4.z * sc;
            Qs[lr*QS + kq+3] = v4.w * sc;
        }
    }

    float o[4][4];
    float m[4], l[4];
    #pragma unroll
    for (int i = 0; i < 4; i++) {
        m[i] = -1e30f; l[i] = 0.0f;
        #pragma unroll
        for (int j = 0; j < 4; j++) o[i][j] = 0.0f;
    }
    __syncthreads();  // Q visible before first S tile

    for (int jt = 0; jt <= qt; jt++) {
        const int j0 = jt * 64;

        // Load K and V tiles (full 64x64 each)
        {
            #pragma unroll
            for (int s = 0; s < 4; s++) {
                int kq = lc0 + s * 4;
                float4 k4 = *(const float4*)(kb + (size_t)(j0 + lr) * HDD + kq);
                Ks[lr*KS + kq+0] = k4.x; Ks[lr*KS + kq+1] = k4.y;
                Ks[lr*KS + kq+2] = k4.z; Ks[lr*KS + kq+3] = k4.w;
                float4 v4 = *(const float4*)(vb + (size_t)(j0 + lr) * HDD + kq);
                *(float4*)(Vs + lr*VS + kq) = v4;
            }
        }
        __syncthreads();

        // S = Q * K^T  (4x4 per thread, scattered mapping)
        float s[4][4];
        #pragma unroll
        for (int i = 0; i < 4; i++)
            #pragma unroll
            for (int j = 0; j < 4; j++) s[i][j] = 0.0f;

        #pragma unroll 16
        for (int k = 0; k < 64; k++) {
            float a[4], c[4];
            #pragma unroll
            for (int i = 0; i < 4; i++) a[i] = Qs[(ty + 16*i)*QS + k];
            #pragma unroll
            for (int j = 0; j < 4; j++) c[j] = Ks[(tx + 16*j)*KS + k];
            #pragma unroll
            for (int i = 0; i < 4; i++)
                #pragma unroll
                for (int j = 0; j < 4; j++) s[i][j] = fmaf(a[i], c[j], s[i][j]);
        }

        const bool diag = (jt == qt);

        // Online softmax per owned row (16 lanes of equal ty share a row set)
        #pragma unroll
        for (int i = 0; i < 4; i++) {
            const int qr = q0 + ty + 16*i;
            float mx = -1e30f;
            #pragma unroll
            for (int j = 0; j < 4; j++) {
                if (diag) {
                    int kc = j0 + tx + 16*j;
                    if (kc > qr) s[i][j] = -1e30f;
                }
                mx = fmaxf(mx, s[i][j]);
            }
            #pragma unroll
            for (int off = 8; off >= 1; off >>= 1)
                mx = fmaxf(mx, __shfl_xor_sync(0xffffffffu, mx, off));
            float mnew = fmaxf(m[i], mx);
            float f = __expf(m[i] - mnew);
            float rs = 0.0f;
            #pragma unroll
            for (int j = 0; j < 4; j++) {
                float p = __expf(s[i][j] - mnew);
                s[i][j] = p;
                rs += p;
            }
            #pragma unroll
            for (int off = 8; off >= 1; off >>= 1)
                rs += __shfl_xor_sync(0xffffffffu, rs, off);
            l[i] = l[i] * f + rs;
            m[i] = mnew;
            #pragma unroll
            for (int j = 0; j < 4; j++) o[i][j] *= f;
        }

        // Stage P transposed: Ps[c][r]
        #pragma unroll
        for (int i = 0; i < 4; i++)
            #pragma unroll
            for (int j = 0; j < 4; j++)
                Ps[(tx + 16*j)*PS + (ty + 16*i)] = s[i][j];
        __syncthreads();

        // O += P * V
        #pragma unroll 16
        for (int k = 0; k < 64; k++) {
            float p[4], vv[4];
            #pragma unroll
            for (int i = 0; i < 4; i++) p[i]  = Ps[k*PS + ty + 16*i];
            #pragma unroll
            for (int j = 0; j < 4; j++) vv[j] = Vs[k*VS + tx + 16*j];
            #pragma unroll
            for (int i = 0; i < 4; i++)
                #pragma unroll
                for (int j = 0; j < 4; j++) o[i][j] = fmaf(p[i], vv[j], o[i][j]);
        }
        __syncthreads();  // protect Ks/Vs/Ps before next iteration's loads
    }

    // Epilogue: normalize and write to [B,T,D] with head-concat layout
    #pragma unroll
    for (int i = 0; i < 4; i++) {
        float inv = 1.0f / l[i];
        int t = q0 + ty + 16*i;
        #pragma unroll
        for (int j = 0; j < 4; j++) {
            int e = tx + 16*j;
            g_ao[((size_t)b*TT + t)*DD + h*HDD + e] = o[i][j] * inv;
        }
    }
}

// ============================================================================
// Launch
// ============================================================================
extern "C" void kernel_launch(void* const* d_in, const int* in_sizes, int n_in,
                              void* d_out, int out_size)
{
    const float* x  = (const float*)d_in[0];
    const float* Wq = (const float*)d_in[1];
    const float* Wk = (const float*)d_in[2];
    const float* Wv = (const float*)d_in[3];
    const float* Wo = (const float*)d_in[4];
    const float* bo = (const float*)d_in[5];
    float* out = (float*)d_out;

    cudaFuncSetAttribute(attn_kernel, cudaFuncAttributeMaxDynamicSharedMemorySize,
                         ATTN_SMEM_BYTES);

    // 1) QKV projections: grid (N/128, M/128, 3)
    qkv_gemm_kernel<<<dim3(DD/128, MTOT/128, 3), 256>>>(x, Wq, Wk, Wv);

    // 2) Causal flash attention: grid (T/64, B*H)
    attn_kernel<<<dim3(TT/64, BB*HH), 256, ATTN_SMEM_BYTES>>>();

    // 3) Output projection + bias
    out_gemm_kernel<<<dim3(DD/128, MTOT/128), 256>>>(Wo, bo, out);
}

// round 4
// speedup vs baseline: 1.5962x; 1.5962x over previous
#include <cuda_runtime.h>
#include <cuda_bf16.h>
#include <cstdint>
#include <math.h>

// Problem constants
#define BB   4
#define TT   2048
#define DD   1024
#define HH   16
#define HDD  64
#define MTOT (BB*TT)   // 8192

typedef __nv_bfloat16  bf16;
typedef __nv_bfloat162 bf162;

// Scratch
__device__ float g_q [(size_t)BB*HH*TT*HDD];   // [B,H,T,HD]
__device__ float g_k [(size_t)BB*HH*TT*HDD];
__device__ float g_v [(size_t)BB*HH*TT*HDD];
__device__ float g_ao[(size_t)BB*TT*DD];       // [B,T,D]

// ============================================================================
// Tensor-core GEMM with split-bf16 (hi/lo) 3-MMA emulation of fp32.
// C[M,N] = A[M,K] * W[N,K]^T, tile 128x128x32, 256 threads = 8 warps (2m x 4n),
// each warp: 64x32 via 4x4 m16n8k16 mma tiles, fp32 accumulators.
// ============================================================================
#define LDKB 40   // smem row stride in bf16 (80B: 16B-aligned, ldmatrix conflict-free)

__device__ __forceinline__ uint32_t smem_u32(const void* p) {
    return (uint32_t)__cvta_generic_to_shared(p);
}
__device__ __forceinline__ void ldsm_x4(uint32_t r[4], uint32_t addr) {
    asm volatile("ldmatrix.sync.aligned.m8n8.x4.shared.b16 {%0,%1,%2,%3}, [%4];"
                 : "=r"(r[0]), "=r"(r[1]), "=r"(r[2]), "=r"(r[3]) : "r"(addr));
}
__device__ __forceinline__ void ldsm_x2(uint32_t r[2], uint32_t addr) {
    asm volatile("ldmatrix.sync.aligned.m8n8.x2.shared.b16 {%0,%1}, [%2];"
                 : "=r"(r[0]), "=r"(r[1]) : "r"(addr));
}
__device__ __forceinline__ void mma16816(float d[4], const uint32_t a[4], const uint32_t b[2]) {
    asm volatile(
        "mma.sync.aligned.m16n8k16.row.col.f32.bf16.bf16.f32 "
        "{%0,%1,%2,%3}, {%4,%5,%6,%7}, {%8,%9}, {%0,%1,%2,%3};"
        : "+f"(d[0]), "+f"(d[1]), "+f"(d[2]), "+f"(d[3])
        : "r"(a[0]), "r"(a[1]), "r"(a[2]), "r"(a[3]), "r"(b[0]), "r"(b[1]));
}

__device__ __forceinline__ void split2(float x, float y, bf162& h, bf162& l) {
    bf16 hx = __float2bfloat16(x);
    bf16 hy = __float2bfloat16(y);
    h = __halves2bfloat162(hx, hy);
    l = __halves2bfloat162(__float2bfloat16(x - __bfloat162float(hx)),
                           __float2bfloat16(y - __bfloat162float(hy)));
}

__device__ __forceinline__ void gemm_mainloop(
    const float* __restrict__ A, const float* __restrict__ W,
    int m0, int n0,
    bf16* __restrict__ Ah, bf16* __restrict__ Al,
    bf16* __restrict__ Bh, bf16* __restrict__ Bl,
    float acc[4][4][4])
{
    const int tid  = threadIdx.x;
    const int lane = tid & 31;
    const int warp = tid >> 5;
    const int wm = warp >> 2;            // 0..1
    const int wn = warp & 3;             // 0..3

    // ldmatrix per-lane source coordinates
    const int a_r = lane & 15;           // rows 0..15 of the 16x16 A tile
    const int a_c = (lane >> 4) << 3;    // lanes 0-15: k+0, lanes 16-31: k+8
    const int b_r = lane & 7;            // rows 0..7 (n) of the W tile
    const int b_c = ((lane >> 3) & 1) << 3; // lanes 0-7: k+0, 8-15: k+8

    for (int k0 = 0; k0 < DD; k0 += 32) {
        // Load 128x32 fp32 of A and W; convert to bf16 hi/lo pairs in SMEM.
        #pragma unroll
        for (int s = 0; s < 4; s++) {
            int idx = tid + s * 256;
            int r = idx >> 3;            // 0..127
            int c = (idx & 7) << 2;      // 0,4,...,28
            float4 va = *(const float4*)(A + (size_t)(m0 + r) * DD + k0 + c);
            bf162 h0, l0, h1, l1;
            split2(va.x, va.y, h0, l0);
            split2(va.z, va.w, h1, l1);
            *(bf162*)(Ah + r*LDKB + c)     = h0;
            *(bf162*)(Ah + r*LDKB + c + 2) = h1;
            *(bf162*)(Al + r*LDKB + c)     = l0;
            *(bf162*)(Al + r*LDKB + c + 2) = l1;
            float4 vb = *(const float4*)(W + (size_t)(n0 + r) * DD + k0 + c);
            split2(vb.x, vb.y, h0, l0);
            split2(vb.z, vb.w, h1, l1);
            *(bf162*)(Bh + r*LDKB + c)     = h0;
            *(bf162*)(Bh + r*LDKB + c + 2) = h1;
            *(bf162*)(Bl + r*LDKB + c)     = l0;
            *(bf162*)(Bl + r*LDKB + c + 2) = l1;
        }
        __syncthreads();

        #pragma unroll
        for (int kk = 0; kk < 32; kk += 16) {
            uint32_t ah[4][4], al[4][4];
            #pragma unroll
            for (int mt = 0; mt < 4; mt++) {
                const bf16* pa = Ah + (wm*64 + mt*16 + a_r)*LDKB + kk + a_c;
                ldsm_x4(ah[mt], smem_u32(pa));
                const bf16* pl = Al + (wm*64 + mt*16 + a_r)*LDKB + kk + a_c;
                ldsm_x4(al[mt], smem_u32(pl));
            }
            #pragma unroll
            for (int nt = 0; nt < 4; nt++) {
                uint32_t bh[2], bl[2];
                ldsm_x2(bh, smem_u32(Bh + (wn*32 + nt*8 + b_r)*LDKB + kk + b_c));
                ldsm_x2(bl, smem_u32(Bl + (wn*32 + nt*8 + b_r)*LDKB + kk + b_c));
                #pragma unroll
                for (int mt = 0; mt < 4; mt++) {
                    mma16816(acc[mt][nt], ah[mt], bh);   // hi*hi
                    mma16816(acc[mt][nt], ah[mt], bl);   // hi*lo
                    mma16816(acc[mt][nt], al[mt], bh);   // lo*hi
                }
            }
        }
        __syncthreads();
    }
}

// QKV projection: writes permuted into [B,H,T,HD]
__global__ __launch_bounds__(256) void qkv_gemm_tc(
    const float* __restrict__ x,
    const float* __restrict__ Wq,
    const float* __restrict__ Wk,
    const float* __restrict__ Wv)
{
    __shared__ bf16 Ah[128*LDKB], Al[128*LDKB], Bh[128*LDKB], Bl[128*LDKB];

    const int which = blockIdx.z;
    const float* __restrict__ Wp = (which == 0) ? Wq : (which == 1) ? Wk : Wv;
    float* __restrict__ outp     = (which == 0) ? g_q : (which == 1) ? g_k : g_v;

    const int m0 = blockIdx.y * 128;
    const int n0 = blockIdx.x * 128;

    float acc[4][4][4];
    #pragma unroll
    for (int i = 0; i < 4; i++)
        #pragma unroll
        for (int j = 0; j < 4; j++)
            #pragma unroll
            for (int r = 0; r < 4; r++) acc[i][j][r] = 0.0f;

    gemm_mainloop(x, Wp, m0, n0, Ah, Al, Bh, Bl, acc);

    const int lane = threadIdx.x & 31;
    const int warp = threadIdx.x >> 5;
    const int wm = warp >> 2, wn = warp & 3;
    const int g = lane >> 2, t = lane & 3;
    const int bb = m0 >> 11;   // 128-row CTA block never crosses a 2048 boundary

    #pragma unroll
    for (int mt = 0; mt < 4; mt++) {
        #pragma unroll
        for (int nt = 0; nt < 4; nt++) {
            int row = m0 + wm*64 + mt*16 + g;
            int col = n0 + wn*32 + nt*8 + 2*t;
            int h = col >> 6, e = col & 63;
            float2 v01 = make_float2(acc[mt][nt][0], acc[mt][nt][1]);
            float2 v23 = make_float2(acc[mt][nt][2], acc[mt][nt][3]);
            int t0 = row & 2047;
            int t1 = (row + 8) & 2047;
            *(float2*)&outp[(((size_t)bb*HH + h)*TT + t0)*HDD + e] = v01;
            *(float2*)&outp[(((size_t)bb*HH + h)*TT + t1)*HDD + e] = v23;
        }
    }
}

// Output projection: out = g_ao @ Wo^T + bo
__global__ __launch_bounds__(256) void out_gemm_tc(
    const float* __restrict__ Wo,
    const float* __restrict__ bo,
    float* __restrict__ outp)
{
    __shared__ bf16 Ah[128*LDKB], Al[128*LDKB], Bh[128*LDKB], Bl[128*LDKB];

    const int m0 = blockIdx.y * 128;
    const int n0 = blockIdx.x * 128;

    float acc[4][4][4];
    #pragma unroll
    for (int i = 0; i < 4; i++)
        #pragma unroll
        for (int j = 0; j < 4; j++)
            #pragma unroll
            for (int r = 0; r < 4; r++) acc[i][j][r] = 0.0f;

    gemm_mainloop(g_ao, Wo, m0, n0, Ah, Al, Bh, Bl, acc);

    const int lane = threadIdx.x & 31;
    const int warp = threadIdx.x >> 5;
    const int wm = warp >> 2, wn = warp & 3;
    const int g = lane >> 2, t = lane & 3;

    #pragma unroll
    for (int mt = 0; mt < 4; mt++) {
        #pragma unroll
        for (int nt = 0; nt < 4; nt++) {
            int row = m0 + wm*64 + mt*16 + g;
            int col = n0 + wn*32 + nt*8 + 2*t;
            float bx = bo[col], by = bo[col+1];
            float2 v01 = make_float2(acc[mt][nt][0] + bx, acc[mt][nt][1] + by);
            float2 v23 = make_float2(acc[mt][nt][2] + bx, acc[mt][nt][3] + by);
            *(float2*)&outp[(size_t)row*DD + col]       = v01;
            *(float2*)&outp[(size_t)(row+8)*DD + col]   = v23;
        }
    }
}

// ============================================================================
// Flash-style causal attention (fp32) — unchanged from R2 (passing).
// ============================================================================
#define QS 65
#define KS 65
#define PS 65
#define VS 68
#define ATTN_SMEM_FLOATS (64*QS + 64*KS + 64*PS + 64*VS)
#define ATTN_SMEM_BYTES  (ATTN_SMEM_FLOATS * 4)

__global__ __launch_bounds__(256) void attn_kernel()
{
    extern __shared__ float sm[];
    float* Qs = sm;
    float* Ks = sm + 64*QS;
    float* Ps = sm + 64*QS + 64*KS;
    float* Vs = sm + 64*QS + 64*KS + 64*PS;

    const int bh = blockIdx.y;
    const int h  = bh & (HH-1);
    const int b  = bh >> 4;
    const int qt = blockIdx.x;
    const int q0 = qt * 64;

    const int tid = threadIdx.x;
    const int tx = tid & 15;
    const int ty = tid >> 4;

    const float* __restrict__ qb = g_q + (size_t)bh * TT * HDD;
    const float* __restrict__ kb = g_k + (size_t)bh * TT * HDD;
    const float* __restrict__ vb = g_v + (size_t)bh * TT * HDD;

    const int lr = tid >> 2;
    const int lc0 = (tid & 3) * 16;

    {
        const float sc = 0.125f;
        #pragma unroll
        for (int s = 0; s < 4; s++) {
            int kq = lc0 + s * 4;
            float4 v4 = *(const float4*)(qb + (size_t)(q0 + lr) * HDD + kq);
            Qs[lr*QS + kq+0] = v4.x * sc;
            Qs[lr*QS + kq+1] = v4.y * sc;
            Qs[lr*QS + kq+2] = v4.z * sc;
            Qs[lr*QS + kq+3] = v4.w * sc;
        }
    }

    float o[4][4];
    float m[4], l[4];
    #pragma unroll
    for (int i = 0; i < 4; i++) {
        m[i] = -1e30f; l[i] = 0.0f;
        #pragma unroll
        for (int j = 0; j < 4; j++) o[i][j] = 0.0f;
    }
    __syncthreads();

    for (int jt = 0; jt <= qt; jt++) {
        const int j0 = jt * 64;

        {
            #pragma unroll
            for (int s = 0; s < 4; s++) {
                int kq = lc0 + s * 4;
                float4 k4 = *(const float4*)(kb + (size_t)(j0 + lr) * HDD + kq);
                Ks[lr*KS + kq+0] = k4.x; Ks[lr*KS + kq+1] = k4.y;
                Ks[lr*KS + kq+2] = k4.z; Ks[lr*KS + kq+3] = k4.w;
                float4 v4 = *(const float4*)(vb + (size_t)(j0 + lr) * HDD + kq);
                *(float4*)(Vs + lr*VS + kq) = v4;
            }
        }
        __syncthreads();

        float s[4][4];
        #pragma unroll
        for (int i = 0; i < 4; i++)
            #pragma unroll
            for (int j = 0; j < 4; j++) s[i][j] = 0.0f;

        #pragma unroll 16
        for (int k = 0; k < 64; k++) {
            float a[4], c[4];
            #pragma unroll
            for (int i = 0; i < 4; i++) a[i] = Qs[(ty + 16*i)*QS + k];
            #pragma unroll
            for (int j = 0; j < 4; j++) c[j] = Ks[(tx + 16*j)*KS + k];
            #pragma unroll
            for (int i = 0; i < 4; i++)
                #pragma unroll
                for (int j = 0; j < 4; j++) s[i][j] = fmaf(a[i], c[j], s[i][j]);
        }

        const bool diag = (jt == qt);

        #pragma unroll
        for (int i = 0; i < 4; i++) {
            const int qr = q0 + ty + 16*i;
            float mx = -1e30f;
            #pragma unroll
            for (int j = 0; j < 4; j++) {
                if (diag) {
                    int kc = j0 + tx + 16*j;
                    if (kc > qr) s[i][j] = -1e30f;
                }
                mx = fmaxf(mx, s[i][j]);
            }
            #pragma unroll
            for (int off = 8; off >= 1; off >>= 1)
                mx = fmaxf(mx, __shfl_xor_sync(0xffffffffu, mx, off));
            float mnew = fmaxf(m[i], mx);
            float f = __expf(m[i] - mnew);
            float rs = 0.0f;
            #pragma unroll
            for (int j = 0; j < 4; j++) {
                float p = __expf(s[i][j] - mnew);
                s[i][j] = p;
                rs += p;
            }
            #pragma unroll
            for (int off = 8; off >= 1; off >>= 1)
                rs += __shfl_xor_sync(0xffffffffu, rs, off);
            l[i] = l[i] * f + rs;
            m[i] = mnew;
            #pragma unroll
            for (int j = 0; j < 4; j++) o[i][j] *= f;
        }

        #pragma unroll
        for (int i = 0; i < 4; i++)
            #pragma unroll
            for (int j = 0; j < 4; j++)
                Ps[(tx + 16*j)*PS + (ty + 16*i)] = s[i][j];
        __syncthreads();

        #pragma unroll 16
        for (int k = 0; k < 64; k++) {
            float p[4], vv[4];
            #pragma unroll
            for (int i = 0; i < 4; i++) p[i]  = Ps[k*PS + ty + 16*i];
            #pragma unroll
            for (int j = 0; j < 4; j++) vv[j] = Vs[k*VS + tx + 16*j];
            #pragma unroll
            for (int i = 0; i < 4; i++)
                #pragma unroll
                for (int j = 0; j < 4; j++) o[i][j] = fmaf(p[i], vv[j], o[i][j]);
        }
        __syncthreads();
    }

    #pragma unroll
    for (int i = 0; i < 4; i++) {
        float inv = 1.0f / l[i];
        int t = q0 + ty + 16*i;
        #pragma unroll
        for (int j = 0; j < 4; j++) {
            int e = tx + 16*j;
            g_ao[((size_t)b*TT + t)*DD + h*HDD + e] = o[i][j] * inv;
        }
    }
}

// ============================================================================
// Launch
// ============================================================================
extern "C" void kernel_launch(void* const* d_in, const int* in_sizes, int n_in,
                              void* d_out, int out_size)
{
    const float* x  = (const float*)d_in[0];
    const float* Wq = (const float*)d_in[1];
    const float* Wk = (const float*)d_in[2];
    const float* Wv = (const float*)d_in[3];
    const float* Wo = (const float*)d_in[4];
    const float* bo = (const float*)d_in[5];
    float* out = (float*)d_out;

    cudaFuncSetAttribute(attn_kernel, cudaFuncAttributeMaxDynamicSharedMemorySize,
                         ATTN_SMEM_BYTES);

    qkv_gemm_tc<<<dim3(DD/128, MTOT/128, 3), 256>>>(x, Wq, Wk, Wv);
    attn_kernel<<<dim3(TT/64, BB*HH), 256, ATTN_SMEM_BYTES>>>();
    out_gemm_tc<<<dim3(DD/128, MTOT/128), 256>>>(Wo, bo, out);
}

// round 5
// speedup vs baseline: 2.7613x; 1.7299x over previous
#include <cuda_runtime.h>
#include <cuda_bf16.h>
#include <cstdint>
#include <math.h>

// Problem constants
#define BB   4
#define TT   2048
#define DD   1024
#define HH   16
#define HDD  64
#define MTOT (BB*TT)   // 8192

typedef __nv_bfloat16  bf16;
typedef __nv_bfloat162 bf162;

// Scratch
__device__ float g_q [(size_t)BB*HH*TT*HDD];   // [B,H,T,HD]
__device__ float g_k [(size_t)BB*HH*TT*HDD];
__device__ float g_v [(size_t)BB*HH*TT*HDD];
__device__ float g_ao[(size_t)BB*TT*DD];       // [B,T,D]

// ============================================================================
// Common MMA helpers (split-bf16 hi/lo, 3-MMA fp32 emulation)
// ============================================================================
__device__ __forceinline__ uint32_t smem_u32(const void* p) {
    return (uint32_t)__cvta_generic_to_shared(p);
}
__device__ __forceinline__ void ldsm_x4(uint32_t r[4], uint32_t addr) {
    asm volatile("ldmatrix.sync.aligned.m8n8.x4.shared.b16 {%0,%1,%2,%3}, [%4];"
                 : "=r"(r[0]), "=r"(r[1]), "=r"(r[2]), "=r"(r[3]) : "r"(addr));
}
__device__ __forceinline__ void ldsm_x2(uint32_t r[2], uint32_t addr) {
    asm volatile("ldmatrix.sync.aligned.m8n8.x2.shared.b16 {%0,%1}, [%2];"
                 : "=r"(r[0]), "=r"(r[1]) : "r"(addr));
}
__device__ __forceinline__ void mma16816(float d[4], const uint32_t a[4], const uint32_t b[2]) {
    asm volatile(
        "mma.sync.aligned.m16n8k16.row.col.f32.bf16.bf16.f32 "
        "{%0,%1,%2,%3}, {%4,%5,%6,%7}, {%8,%9}, {%0,%1,%2,%3};"
        : "+f"(d[0]), "+f"(d[1]), "+f"(d[2]), "+f"(d[3])
        : "r"(a[0]), "r"(a[1]), "r"(a[2]), "r"(a[3]), "r"(b[0]), "r"(b[1]));
}
__device__ __forceinline__ void split2(float x, float y, bf162& h, bf162& l) {
    bf16 hx = __float2bfloat16(x);
    bf16 hy = __float2bfloat16(y);
    h = __halves2bfloat162(hx, hy);
    l = __halves2bfloat162(__float2bfloat16(x - __bfloat162float(hx)),
                           __float2bfloat16(y - __bfloat162float(hy)));
}
__device__ __forceinline__ void split_pack(float x, float y, uint32_t& h, uint32_t& l) {
    bf162 hv, lv;
    split2(x, y, hv, lv);
    h = *(uint32_t*)&hv;
    l = *(uint32_t*)&lv;
}

// ============================================================================
// Tensor-core GEMM (unchanged from R4, passing @451us)
// ============================================================================
#define LDKB 40

__device__ __forceinline__ void gemm_mainloop(
    const float* __restrict__ A, const float* __restrict__ W,
    int m0, int n0,
    bf16* __restrict__ Ah, bf16* __restrict__ Al,
    bf16* __restrict__ Bh, bf16* __restrict__ Bl,
    float acc[4][4][4])
{
    const int tid  = threadIdx.x;
    const int lane = tid & 31;
    const int warp = tid >> 5;
    const int wm = warp >> 2;
    const int wn = warp & 3;

    const int a_r = lane & 15;
    const int a_c = (lane >> 4) << 3;
    const int b_r = lane & 7;
    const int b_c = ((lane >> 3) & 1) << 3;

    for (int k0 = 0; k0 < DD; k0 += 32) {
        #pragma unroll
        for (int s = 0; s < 4; s++) {
            int idx = tid + s * 256;
            int r = idx >> 3;
            int c = (idx & 7) << 2;
            float4 va = *(const float4*)(A + (size_t)(m0 + r) * DD + k0 + c);
            bf162 h0, l0, h1, l1;
            split2(va.x, va.y, h0, l0);
            split2(va.z, va.w, h1, l1);
            *(bf162*)(Ah + r*LDKB + c)     = h0;
            *(bf162*)(Ah + r*LDKB + c + 2) = h1;
            *(bf162*)(Al + r*LDKB + c)     = l0;
            *(bf162*)(Al + r*LDKB + c + 2) = l1;
            float4 vb = *(const float4*)(W + (size_t)(n0 + r) * DD + k0 + c);
            split2(vb.x, vb.y, h0, l0);
            split2(vb.z, vb.w, h1, l1);
            *(bf162*)(Bh + r*LDKB + c)     = h0;
            *(bf162*)(Bh + r*LDKB + c + 2) = h1;
            *(bf162*)(Bl + r*LDKB + c)     = l0;
            *(bf162*)(Bl + r*LDKB + c + 2) = l1;
        }
        __syncthreads();

        #pragma unroll
        for (int kk = 0; kk < 32; kk += 16) {
            uint32_t ah[4][4], al[4][4];
            #pragma unroll
            for (int mt = 0; mt < 4; mt++) {
                ldsm_x4(ah[mt], smem_u32(Ah + (wm*64 + mt*16 + a_r)*LDKB + kk + a_c));
                ldsm_x4(al[mt], smem_u32(Al + (wm*64 + mt*16 + a_r)*LDKB + kk + a_c));
            }
            #pragma unroll
            for (int nt = 0; nt < 4; nt++) {
                uint32_t bh[2], bl[2];
                ldsm_x2(bh, smem_u32(Bh + (wn*32 + nt*8 + b_r)*LDKB + kk + b_c));
                ldsm_x2(bl, smem_u32(Bl + (wn*32 + nt*8 + b_r)*LDKB + kk + b_c));
                #pragma unroll
                for (int mt = 0; mt < 4; mt++) {
                    mma16816(acc[mt][nt], ah[mt], bh);
                    mma16816(acc[mt][nt], ah[mt], bl);
                    mma16816(acc[mt][nt], al[mt], bh);
                }
            }
        }
        __syncthreads();
    }
}

__global__ __launch_bounds__(256) void qkv_gemm_tc(
    const float* __restrict__ x,
    const float* __restrict__ Wq,
    const float* __restrict__ Wk,
    const float* __restrict__ Wv)
{
    __shared__ bf16 Ah[128*LDKB], Al[128*LDKB], Bh[128*LDKB], Bl[128*LDKB];

    const int which = blockIdx.z;
    const float* __restrict__ Wp = (which == 0) ? Wq : (which == 1) ? Wk : Wv;
    float* __restrict__ outp     = (which == 0) ? g_q : (which == 1) ? g_k : g_v;

    const int m0 = blockIdx.y * 128;
    const int n0 = blockIdx.x * 128;

    float acc[4][4][4];
    #pragma unroll
    for (int i = 0; i < 4; i++)
        #pragma unroll
        for (int j = 0; j < 4; j++)
            #pragma unroll
            for (int r = 0; r < 4; r++) acc[i][j][r] = 0.0f;

    gemm_mainloop(x, Wp, m0, n0, Ah, Al, Bh, Bl, acc);

    const int lane = threadIdx.x & 31;
    const int warp = threadIdx.x >> 5;
    const int wm = warp >> 2, wn = warp & 3;
    const int g = lane >> 2, t = lane & 3;
    const int bb = m0 >> 11;

    #pragma unroll
    for (int mt = 0; mt < 4; mt++) {
        #pragma unroll
        for (int nt = 0; nt < 4; nt++) {
            int row = m0 + wm*64 + mt*16 + g;
            int col = n0 + wn*32 + nt*8 + 2*t;
            int h = col >> 6, e = col & 63;
            float2 v01 = make_float2(acc[mt][nt][0], acc[mt][nt][1]);
            float2 v23 = make_float2(acc[mt][nt][2], acc[mt][nt][3]);
            int t0 = row & 2047;
            int t1 = (row + 8) & 2047;
            *(float2*)&outp[(((size_t)bb*HH + h)*TT + t0)*HDD + e] = v01;
            *(float2*)&outp[(((size_t)bb*HH + h)*TT + t1)*HDD + e] = v23;
        }
    }
}

__global__ __launch_bounds__(256) void out_gemm_tc(
    const float* __restrict__ Wo,
    const float* __restrict__ bo,
    float* __restrict__ outp)
{
    __shared__ bf16 Ah[128*LDKB], Al[128*LDKB], Bh[128*LDKB], Bl[128*LDKB];

    const int m0 = blockIdx.y * 128;
    const int n0 = blockIdx.x * 128;

    float acc[4][4][4];
    #pragma unroll
    for (int i = 0; i < 4; i++)
        #pragma unroll
        for (int j = 0; j < 4; j++)
            #pragma unroll
            for (int r = 0; r < 4; r++) acc[i][j][r] = 0.0f;

    gemm_mainloop(g_ao, Wo, m0, n0, Ah, Al, Bh, Bl, acc);

    const int lane = threadIdx.x & 31;
    const int warp = threadIdx.x >> 5;
    const int wm = warp >> 2, wn = warp & 3;
    const int g = lane >> 2, t = lane & 3;

    #pragma unroll
    for (int mt = 0; mt < 4; mt++) {
        #pragma unroll
        for (int nt = 0; nt < 4; nt++) {
            int row = m0 + wm*64 + mt*16 + g;
            int col = n0 + wn*32 + nt*8 + 2*t;
            float bx = bo[col], by = bo[col+1];
            float2 v01 = make_float2(acc[mt][nt][0] + bx, acc[mt][nt][1] + by);
            float2 v23 = make_float2(acc[mt][nt][2] + bx, acc[mt][nt][3] + by);
            *(float2*)&outp[(size_t)row*DD + col]       = v01;
            *(float2*)&outp[(size_t)(row+8)*DD + col]   = v23;
        }
    }
}

// ============================================================================
// Tensor-core flash attention, split-bf16 3-MMA for QK^T and P*V.
// CTA: 128 threads (4 warps), 64-query tile of one (b,h). Warp w owns rows
// [w*16, w*16+16). K/V tiles of 64 keys. V staged transposed [e][s].
// SMEM stride 72 bf16 (144B): ldmatrix conflict-free (9r mod 8 distinct).
// ============================================================================
#define AQS 72
#define ATTN_SMEM_BYTES (6 * 64 * AQS * 2)   // Qh,Ql,Kh,Kl,Vh,Vl = 55296 B

__global__ __launch_bounds__(128) void attn_tc()
{
    extern __shared__ bf16 asmem[];
    bf16* Qh = asmem;
    bf16* Ql = Qh + 64*AQS;
    bf16* Kh = Ql + 64*AQS;
    bf16* Kl = Kh + 64*AQS;
    bf16* Vh = Kl + 64*AQS;   // transposed: [e][s]
    bf16* Vl = Vh + 64*AQS;

    const int bh = blockIdx.y;
    const int h  = bh & (HH-1);
    const int b  = bh >> 4;
    const int qt = blockIdx.x;
    const int q0 = qt * 64;

    const int tid  = threadIdx.x;
    const int lane = tid & 31;
    const int w    = tid >> 5;       // warp 0..3
    const int g    = lane >> 2;      // 0..7
    const int t    = lane & 3;       // 0..3

    const float* __restrict__ qb = g_q + (size_t)bh * TT * HDD;
    const float* __restrict__ kb = g_k + (size_t)bh * TT * HDD;
    const float* __restrict__ vb = g_v + (size_t)bh * TT * HDD;

    // Stage Q once (pre-scaled by 1/8)
    for (int idx = tid; idx < 64*16; idx += 128) {
        int r = idx >> 4;
        int c = (idx & 15) << 2;
        float4 v4 = *(const float4*)(qb + (size_t)(q0 + r) * HDD + c);
        bf162 h0, l0, h1, l1;
        split2(v4.x * 0.125f, v4.y * 0.125f, h0, l0);
        split2(v4.z * 0.125f, v4.w * 0.125f, h1, l1);
        *(bf162*)(Qh + r*AQS + c)     = h0;
        *(bf162*)(Qh + r*AQS + c + 2) = h1;
        *(bf162*)(Ql + r*AQS + c)     = l0;
        *(bf162*)(Ql + r*AQS + c + 2) = l1;
    }

    float o[8][4];
    float m[2], l[2];
    #pragma unroll
    for (int et = 0; et < 8; et++)
        #pragma unroll
        for (int r = 0; r < 4; r++) o[et][r] = 0.0f;
    m[0] = m[1] = -1e30f;
    l[0] = l[1] = 0.0f;

    const int a_r = lane & 15;
    const int a_c = (lane >> 4) << 3;
    const int b_r = lane & 7;
    const int b_c = ((lane >> 3) & 1) << 3;

    for (int jt = 0; jt <= qt; jt++) {
        const int j0 = jt * 64;
        __syncthreads();   // previous iter's MMAs done with K/V smem

        // Stage K (row-major hi/lo)
        for (int idx = tid; idx < 64*16; idx += 128) {
            int r = idx >> 4;
            int c = (idx & 15) << 2;
            float4 k4 = *(const float4*)(kb + (size_t)(j0 + r) * HDD + c);
            bf162 h0, l0, h1, l1;
            split2(k4.x, k4.y, h0, l0);
            split2(k4.z, k4.w, h1, l1);
            *(bf162*)(Kh + r*AQS + c)     = h0;
            *(bf162*)(Kh + r*AQS + c + 2) = h1;
            *(bf162*)(Kl + r*AQS + c)     = l0;
            *(bf162*)(Kl + r*AQS + c + 2) = l1;
        }
        // Stage V transposed: Vh/Vl[e][s]. Index mapping keeps STS coalesced.
        for (int idx = tid; idx < 64*16; idx += 128) {
            int r = idx & 63;            // key index s (consecutive per lane)
            int c = (idx >> 6) << 2;     // head-dim base e
            float4 v4 = *(const float4*)(vb + (size_t)(j0 + r) * HDD + c);
            bf16 hx;
            hx = __float2bfloat16(v4.x);
            Vh[(c+0)*AQS + r] = hx;
            Vl[(c+0)*AQS + r] = __float2bfloat16(v4.x - __bfloat162float(hx));
            hx = __float2bfloat16(v4.y);
            Vh[(c+1)*AQS + r] = hx;
            Vl[(c+1)*AQS + r] = __float2bfloat16(v4.y - __bfloat162float(hx));
            hx = __float2bfloat16(v4.z);
            Vh[(c+2)*AQS + r] = hx;
            Vl[(c+2)*AQS + r] = __float2bfloat16(v4.z - __bfloat162float(hx));
            hx = __float2bfloat16(v4.w);
            Vh[(c+3)*AQS + r] = hx;
            Vl[(c+3)*AQS + r] = __float2bfloat16(v4.w - __bfloat162float(hx));
        }
        __syncthreads();

        // S = Q K^T  (warp: 16 rows x 64 cols, 8 n-tiles)
        float s[8][4];
        #pragma unroll
        for (int nt = 0; nt < 8; nt++)
            #pragma unroll
            for (int r = 0; r < 4; r++) s[nt][r] = 0.0f;

        #pragma unroll
        for (int kk = 0; kk < 4; kk++) {
            uint32_t qah[4], qal[4];
            ldsm_x4(qah, smem_u32(Qh + (w*16 + a_r)*AQS + kk*16 + a_c));
            ldsm_x4(qal, smem_u32(Ql + (w*16 + a_r)*AQS + kk*16 + a_c));
            #pragma unroll
            for (int nt = 0; nt < 8; nt++) {
                uint32_t kbh[2], kbl[2];
                ldsm_x2(kbh, smem_u32(Kh + (nt*8 + b_r)*AQS + kk*16 + b_c));
                ldsm_x2(kbl, smem_u32(Kl + (nt*8 + b_r)*AQS + kk*16 + b_c));
                mma16816(s[nt], qah, kbh);
                mma16816(s[nt], qah, kbl);
                mma16816(s[nt], qal, kbh);
            }
        }

        // Causal mask on diagonal tile
        const int r0 = q0 + w*16 + g;
        const int r1 = r0 + 8;
        if (jt == qt) {
            #pragma unroll
            for (int nt = 0; nt < 8; nt++) {
                int c0 = j0 + nt*8 + 2*t;
                if (c0     > r0) s[nt][0] = -1e30f;
                if (c0 + 1 > r0) s[nt][1] = -1e30f;
                if (c0     > r1) s[nt][2] = -1e30f;
                if (c0 + 1 > r1) s[nt][3] = -1e30f;
            }
        }

        // Online softmax (rows r0, r1; reduce over the 4 t-lanes)
        float mx0 = -1e30f, mx1 = -1e30f;
        #pragma unroll
        for (int nt = 0; nt < 8; nt++) {
            mx0 = fmaxf(mx0, fmaxf(s[nt][0], s[nt][1]));
            mx1 = fmaxf(mx1, fmaxf(s[nt][2], s[nt][3]));
        }
        #pragma unroll
        for (int off = 1; off <= 2; off <<= 1) {
            mx0 = fmaxf(mx0, __shfl_xor_sync(0xffffffffu, mx0, off));
            mx1 = fmaxf(mx1, __shfl_xor_sync(0xffffffffu, mx1, off));
        }
        float mn0 = fmaxf(m[0], mx0);
        float mn1 = fmaxf(m[1], mx1);
        float f0 = __expf(m[0] - mn0);
        float f1 = __expf(m[1] - mn1);
        float rs0 = 0.0f, rs1 = 0.0f;
        #pragma unroll
        for (int nt = 0; nt < 8; nt++) {
            s[nt][0] = __expf(s[nt][0] - mn0);
            s[nt][1] = __expf(s[nt][1] - mn0);
            s[nt][2] = __expf(s[nt][2] - mn1);
            s[nt][3] = __expf(s[nt][3] - mn1);
            rs0 += s[nt][0] + s[nt][1];
            rs1 += s[nt][2] + s[nt][3];
        }
        #pragma unroll
        for (int off = 1; off <= 2; off <<= 1) {
            rs0 += __shfl_xor_sync(0xffffffffu, rs0, off);
            rs1 += __shfl_xor_sync(0xffffffffu, rs1, off);
        }
        l[0] = l[0] * f0 + rs0;
        l[1] = l[1] * f1 + rs1;
        m[0] = mn0;
        m[1] = mn1;
        #pragma unroll
        for (int et = 0; et < 8; et++) {
            o[et][0] *= f0; o[et][1] *= f0;
            o[et][2] *= f1; o[et][3] *= f1;
        }

        // P*V: A fragment built in registers from s (S-frag layout == A-frag layout)
        #pragma unroll
        for (int kt = 0; kt < 4; kt++) {
            uint32_t pah[4], pal[4];
            split_pack(s[2*kt][0],   s[2*kt][1],   pah[0], pal[0]);
            split_pack(s[2*kt][2],   s[2*kt][3],   pah[1], pal[1]);
            split_pack(s[2*kt+1][0], s[2*kt+1][1], pah[2], pal[2]);
            split_pack(s[2*kt+1][2], s[2*kt+1][3], pah[3], pal[3]);
            #pragma unroll
            for (int et = 0; et < 8; et++) {
                uint32_t vbh[2], vbl[2];
                ldsm_x2(vbh, smem_u32(Vh + (et*8 + b_r)*AQS + kt*16 + b_c));
                ldsm_x2(vbl, smem_u32(Vl + (et*8 + b_r)*AQS + kt*16 + b_c));
                mma16816(o[et], pah, vbh);
                mma16816(o[et], pah, vbl);
                mma16816(o[et], pal, vbh);
            }
        }
    }

    // Epilogue: normalize, write head-concat layout [B,T,D]
    float inv0 = 1.0f / l[0];
    float inv1 = 1.0f / l[1];
    int tq = q0 + w*16 + g;
    #pragma unroll
    for (int et = 0; et < 8; et++) {
        int col = h*HDD + et*8 + 2*t;
        float2 v01 = make_float2(o[et][0] * inv0, o[et][1] * inv0);
        float2 v23 = make_float2(o[et][2] * inv1, o[et][3] * inv1);
        *(float2*)&g_ao[((size_t)b*TT + tq)*DD + col]     = v01;
        *(float2*)&g_ao[((size_t)b*TT + tq + 8)*DD + col] = v23;
    }
}

// ============================================================================
// Launch
// ============================================================================
extern "C" void kernel_launch(void* const* d_in, const int* in_sizes, int n_in,
                              void* d_out, int out_size)
{
    const float* x  = (const float*)d_in[0];
    const float* Wq = (const float*)d_in[1];
    const float* Wk = (const float*)d_in[2];
    const float* Wv = (const float*)d_in[3];
    const float* Wo = (const float*)d_in[4];
    const float* bo = (const float*)d_in[5];
    float* out = (float*)d_out;

    cudaFuncSetAttribute(attn_tc, cudaFuncAttributeMaxDynamicSharedMemorySize,
                         ATTN_SMEM_BYTES);

    qkv_gemm_tc<<<dim3(DD/128, MTOT/128, 3), 256>>>(x, Wq, Wk, Wv);
    attn_tc<<<dim3(TT/64, BB*HH), 128, ATTN_SMEM_BYTES>>>();
    out_gemm_tc<<<dim3(DD/128, MTOT/128), 256>>>(Wo, bo, out);
}

// round 6
// speedup vs baseline: 3.1036x; 1.1240x over previous
#include <cuda_runtime.h>
#include <cuda_bf16.h>
#include <cstdint>
#include <math.h>

#define BB   4
#define TT   2048
#define DD   1024
#define HH   16
#define HDD  64
#define MTOT (BB*TT)   // 8192

typedef __nv_bfloat16  bf16;
typedef __nv_bfloat162 bf162;

// ---- bf16 hi/lo split globals (split computed ONCE) ----
__device__ bf16 g_xh [(size_t)MTOT*DD],  g_xl [(size_t)MTOT*DD];
__device__ bf16 g_wqh[(size_t)DD*DD],    g_wql[(size_t)DD*DD];
__device__ bf16 g_wkh[(size_t)DD*DD],    g_wkl[(size_t)DD*DD];
__device__ bf16 g_wvh[(size_t)DD*DD],    g_wvl[(size_t)DD*DD];
__device__ bf16 g_woh[(size_t)DD*DD],    g_wol[(size_t)DD*DD];
__device__ bf16 g_qh [(size_t)MTOT*DD],  g_ql [(size_t)MTOT*DD];   // [B,H,T,HD] (prescaled 1/8)
__device__ bf16 g_kh [(size_t)MTOT*DD],  g_kl [(size_t)MTOT*DD];   // [B,H,T,HD]
__device__ bf16 g_vth[(size_t)MTOT*DD],  g_vtl[(size_t)MTOT*DD];   // [B,H,HD,T] transposed
__device__ bf16 g_aoh[(size_t)MTOT*DD],  g_aol[(size_t)MTOT*DD];   // [B,T,D]

// ============================================================================
// Helpers
// ============================================================================
__device__ __forceinline__ uint32_t smem_u32(const void* p) {
    return (uint32_t)__cvta_generic_to_shared(p);
}
__device__ __forceinline__ void ldsm_x4(uint32_t r[4], uint32_t addr) {
    asm volatile("ldmatrix.sync.aligned.m8n8.x4.shared.b16 {%0,%1,%2,%3}, [%4];"
                 : "=r"(r[0]), "=r"(r[1]), "=r"(r[2]), "=r"(r[3]) : "r"(addr));
}
__device__ __forceinline__ void ldsm_x2(uint32_t r[2], uint32_t addr) {
    asm volatile("ldmatrix.sync.aligned.m8n8.x2.shared.b16 {%0,%1}, [%2];"
                 : "=r"(r[0]), "=r"(r[1]) : "r"(addr));
}
__device__ __forceinline__ void mma16816(float d[4], const uint32_t a[4], const uint32_t b[2]) {
    asm volatile(
        "mma.sync.aligned.m16n8k16.row.col.f32.bf16.bf16.f32 "
        "{%0,%1,%2,%3}, {%4,%5,%6,%7}, {%8,%9}, {%0,%1,%2,%3};"
        : "+f"(d[0]), "+f"(d[1]), "+f"(d[2]), "+f"(d[3])
        : "r"(a[0]), "r"(a[1]), "r"(a[2]), "r"(a[3]), "r"(b[0]), "r"(b[1]));
}
__device__ __forceinline__ void split2(float x, float y, bf162& h, bf162& l) {
    bf16 hx = __float2bfloat16(x);
    bf16 hy = __float2bfloat16(y);
    h = __halves2bfloat162(hx, hy);
    l = __halves2bfloat162(__float2bfloat16(x - __bfloat162float(hx)),
                           __float2bfloat16(y - __bfloat162float(hy)));
}
__device__ __forceinline__ void split_pack(float x, float y, uint32_t& h, uint32_t& l) {
    bf162 hv, lv;
    split2(x, y, hv, lv);
    h = *(uint32_t*)&hv;
    l = *(uint32_t*)&lv;
}
__device__ __forceinline__ void cp16(uint32_t s, const void* g) {
    asm volatile("cp.async.ca.shared.global [%0], [%1], 16;\n" :: "r"(s), "l"(g));
}
#define CP_COMMIT() asm volatile("cp.async.commit_group;\n" ::: "memory")
template<int N> __device__ __forceinline__ void cp_wait() {
    asm volatile("cp.async.wait_group %0;\n" :: "n"(N) : "memory");
}

// ============================================================================
// Convert kernel: fp32 -> bf16 hi/lo split
// ============================================================================
__global__ __launch_bounds__(256) void convert_split_k(
    const float4* __restrict__ src, bf16* __restrict__ ho, bf16* __restrict__ lo, int n4)
{
    int i = blockIdx.x * 256 + threadIdx.x;
    if (i < n4) {
        float4 v = src[i];
        bf162 h0, l0, h1, l1;
        split2(v.x, v.y, h0, l0);
        split2(v.z, v.w, h1, l1);
        *(bf162*)(ho + (size_t)i*4)     = h0;
        *(bf162*)(ho + (size_t)i*4 + 2) = h1;
        *(bf162*)(lo + (size_t)i*4)     = l0;
        *(bf162*)(lo + (size_t)i*4 + 2) = l1;
    }
}

// ============================================================================
// Pipelined bf16 GEMM mainloop: C[M,N] = A[M,K]*W[N,K]^T, 3-MMA hi/lo.
// Tile 128x128x32, 3-stage cp.async pipeline, 1 sync per stage.
// ============================================================================
#define LDKB 40
#define STG_ARR (128*LDKB)      // bf16 per array per stage
#define STG4    (4*STG_ARR)     // bf16 per stage (Ah,Al,Bh,Bl)
#define GEMM_SMEM_BYTES (3*STG4*2)   // 122880

__device__ __forceinline__ void gemm_load_stage(
    const bf16* __restrict__ Ahg, const bf16* __restrict__ Alg,
    const bf16* __restrict__ Bhg, const bf16* __restrict__ Blg,
    int m0, int n0, int k0, bf16* base, int tid)
{
    const bf16* gp[4] = {Ahg, Alg, Bhg, Blg};
    #pragma unroll
    for (int a = 0; a < 4; a++) {
        int row0 = (a < 2) ? m0 : n0;
        bf16* sb = base + a*STG_ARR;
        #pragma unroll
        for (int s = 0; s < 2; s++) {
            int idx = tid + s*256;
            int r = idx >> 2;
            int c = (idx & 3) * 8;
            cp16(smem_u32(sb + r*LDKB + c), gp[a] + (size_t)(row0 + r)*DD + k0 + c);
        }
    }
}

__device__ __forceinline__ void gemm_mainloop_bf16(
    const bf16* __restrict__ Ahg, const bf16* __restrict__ Alg,
    const bf16* __restrict__ Bhg, const bf16* __restrict__ Blg,
    int m0, int n0, bf16* smem, float acc[4][4][4])
{
    const int tid  = threadIdx.x;
    const int lane = tid & 31;
    const int warp = tid >> 5;
    const int wm = warp >> 2;
    const int wn = warp & 3;

    const int a_r = lane & 15;
    const int a_c = (lane >> 4) << 3;
    const int b_r = lane & 7;
    const int b_c = ((lane >> 3) & 1) << 3;

    const int NST = DD / 32;   // 32 stages

    gemm_load_stage(Ahg, Alg, Bhg, Blg, m0, n0, 0,  smem,        tid); CP_COMMIT();
    gemm_load_stage(Ahg, Alg, Bhg, Blg, m0, n0, 32, smem + STG4, tid); CP_COMMIT();

    for (int i = 0; i < NST; i++) {
        cp_wait<1>();          // stage i complete
        __syncthreads();       // visible to all; all warps done with buf (i-1)%3
        if (i + 2 < NST)       // prefetch into buf (i+2)%3 == (i-1)%3 (now safe)
            gemm_load_stage(Ahg, Alg, Bhg, Blg, m0, n0, (i+2)*32,
                            smem + ((i+2)%3)*STG4, tid);
        CP_COMMIT();           // always commit (possibly empty) to keep counts uniform

        bf16* Ahs = smem + (i%3)*STG4;
        bf16* Als = Ahs + STG_ARR;
        bf16* Bhs = Als + STG_ARR;
        bf16* Bls = Bhs + STG_ARR;

        #pragma unroll
        for (int kk = 0; kk < 32; kk += 16) {
            uint32_t ah[4][4], al[4][4];
            #pragma unroll
            for (int mt = 0; mt < 4; mt++) {
                ldsm_x4(ah[mt], smem_u32(Ahs + (wm*64 + mt*16 + a_r)*LDKB + kk + a_c));
                ldsm_x4(al[mt], smem_u32(Als + (wm*64 + mt*16 + a_r)*LDKB + kk + a_c));
            }
            #pragma unroll
            for (int nt = 0; nt < 4; nt++) {
                uint32_t bh[2], bl[2];
                ldsm_x2(bh, smem_u32(Bhs + (wn*32 + nt*8 + b_r)*LDKB + kk + b_c));
                ldsm_x2(bl, smem_u32(Bls + (wn*32 + nt*8 + b_r)*LDKB + kk + b_c));
                #pragma unroll
                for (int mt = 0; mt < 4; mt++) {
                    mma16816(acc[mt][nt], ah[mt], bh);
                    mma16816(acc[mt][nt], ah[mt], bl);
                    mma16816(acc[mt][nt], al[mt], bh);
                }
            }
        }
    }
}

// QKV projection: writes bf16 hi/lo Q (prescaled), K, V-transposed
__global__ __launch_bounds__(256) void qkv_gemm_tc(int which_unused)
{
    extern __shared__ bf16 gsm[];

    const int which = blockIdx.z;
    const bf16* Bhg = (which == 0) ? g_wqh : (which == 1) ? g_wkh : g_wvh;
    const bf16* Blg = (which == 0) ? g_wql : (which == 1) ? g_wkl : g_wvl;

    const int m0 = blockIdx.y * 128;
    const int n0 = blockIdx.x * 128;

    float acc[4][4][4];
    #pragma unroll
    for (int i = 0; i < 4; i++)
        #pragma unroll
        for (int j = 0; j < 4; j++)
            #pragma unroll
            for (int r = 0; r < 4; r++) acc[i][j][r] = 0.0f;

    gemm_mainloop_bf16(g_xh, g_xl, Bhg, Blg, m0, n0, gsm, acc);

    const int lane = threadIdx.x & 31;
    const int warp = threadIdx.x >> 5;
    const int wm = warp >> 2, wn = warp & 3;
    const int g = lane >> 2, t = lane & 3;
    const int bb = m0 >> 11;

    #pragma unroll
    for (int mt = 0; mt < 4; mt++) {
        #pragma unroll
        for (int nt = 0; nt < 4; nt++) {
            int row = m0 + wm*64 + mt*16 + g;
            int col = n0 + wn*32 + nt*8 + 2*t;
            int hh = col >> 6, e = col & 63;
            int t0 = row & 2047;
            int t1 = (row + 8) & 2047;
            if (which == 2) {
                // V transposed [B,H,HD,T], bf16 hi/lo scalar stores
                size_t basep = ((size_t)bb*HH + hh) * HDD;
                float vals[4] = {acc[mt][nt][0], acc[mt][nt][1], acc[mt][nt][2], acc[mt][nt][3]};
                int ts[4] = {t0, t0, t1, t1};
                int es[4] = {e, e+1, e, e+1};
                #pragma unroll
                for (int q = 0; q < 4; q++) {
                    bf16 hv = __float2bfloat16(vals[q]);
                    g_vth[(basep + es[q])*TT + ts[q]] = hv;
                    g_vtl[(basep + es[q])*TT + ts[q]] =
                        __float2bfloat16(vals[q] - __bfloat162float(hv));
                }
            } else {
                float sc = (which == 0) ? 0.125f : 1.0f;
                bf16* hp = (which == 0) ? g_qh : g_kh;
                bf16* lp = (which == 0) ? g_ql : g_kl;
                uint32_t hv, lv;
                size_t a0 = (((size_t)bb*HH + hh)*TT + t0)*HDD + e;
                size_t a1 = (((size_t)bb*HH + hh)*TT + t1)*HDD + e;
                split_pack(acc[mt][nt][0]*sc, acc[mt][nt][1]*sc, hv, lv);
                *(uint32_t*)&hp[a0] = hv;
                *(uint32_t*)&lp[a0] = lv;
                split_pack(acc[mt][nt][2]*sc, acc[mt][nt][3]*sc, hv, lv);
                *(uint32_t*)&hp[a1] = hv;
                *(uint32_t*)&lp[a1] = lv;
            }
        }
    }
}

// Output projection: out = ao @ Wo^T + bo (fp32 out)
__global__ __launch_bounds__(256) void out_gemm_tc(
    const float* __restrict__ bo, float* __restrict__ outp)
{
    extern __shared__ bf16 gsm[];

    const int m0 = blockIdx.y * 128;
    const int n0 = blockIdx.x * 128;

    float acc[4][4][4];
    #pragma unroll
    for (int i = 0; i < 4; i++)
        #pragma unroll
        for (int j = 0; j < 4; j++)
            #pragma unroll
            for (int r = 0; r < 4; r++) acc[i][j][r] = 0.0f;

    gemm_mainloop_bf16(g_aoh, g_aol, g_woh, g_wol, m0, n0, gsm, acc);

    const int lane = threadIdx.x & 31;
    const int warp = threadIdx.x >> 5;
    const int wm = warp >> 2, wn = warp & 3;
    const int g = lane >> 2, t = lane & 3;

    #pragma unroll
    for (int mt = 0; mt < 4; mt++) {
        #pragma unroll
        for (int nt = 0; nt < 4; nt++) {
            int row = m0 + wm*64 + mt*16 + g;
            int col = n0 + wn*32 + nt*8 + 2*t;
            float bx = bo[col], by = bo[col+1];
            float2 v01 = make_float2(acc[mt][nt][0] + bx, acc[mt][nt][1] + by);
            float2 v23 = make_float2(acc[mt][nt][2] + bx, acc[mt][nt][3] + by);
            *(float2*)&outp[(size_t)row*DD + col]     = v01;
            *(float2*)&outp[(size_t)(row+8)*DD + col] = v23;
        }
    }
}

// ============================================================================
// Tensor-core flash attention: precomputed bf16 hi/lo Q/K/V^T, pure copies.
// ============================================================================
#define AQS 72
#define ATTN_SMEM_BYTES (6 * 64 * AQS * 2)

__global__ __launch_bounds__(128) void attn_tc()
{
    extern __shared__ bf16 asmem[];
    bf16* Qh = asmem;
    bf16* Ql = Qh + 64*AQS;
    bf16* Kh = Ql + 64*AQS;
    bf16* Kl = Kh + 64*AQS;
    bf16* Vh = Kl + 64*AQS;   // [e][s]
    bf16* Vl = Vh + 64*AQS;

    const int bh = blockIdx.y;
    const int hh = bh & (HH-1);
    const int b  = bh >> 4;
    const int qt = blockIdx.x;
    const int q0 = qt * 64;

    const int tid  = threadIdx.x;
    const int lane = tid & 31;
    const int w    = tid >> 5;
    const int g    = lane >> 2;
    const int t    = lane & 3;

    const bf16* __restrict__ qhb = g_qh  + (size_t)bh * TT * HDD;
    const bf16* __restrict__ qlb = g_ql  + (size_t)bh * TT * HDD;
    const bf16* __restrict__ khb = g_kh  + (size_t)bh * TT * HDD;
    const bf16* __restrict__ klb = g_kl  + (size_t)bh * TT * HDD;
    const bf16* __restrict__ vhb = g_vth + (size_t)bh * HDD * TT;
    const bf16* __restrict__ vlb = g_vtl + (size_t)bh * HDD * TT;

    // Stage Q once (already prescaled)
    for (int idx = tid; idx < 512; idx += 128) {
        int r = idx >> 3;
        int c = (idx & 7) * 8;
        *(uint4*)(Qh + r*AQS + c) = *(const uint4*)(qhb + (size_t)(q0 + r)*HDD + c);
        *(uint4*)(Ql + r*AQS + c) = *(const uint4*)(qlb + (size_t)(q0 + r)*HDD + c);
    }

    float o[8][4];
    float m[2], l[2];
    #pragma unroll
    for (int et = 0; et < 8; et++)
        #pragma unroll
        for (int r = 0; r < 4; r++) o[et][r] = 0.0f;
    m[0] = m[1] = -1e30f;
    l[0] = l[1] = 0.0f;

    const int a_r = lane & 15;
    const int a_c = (lane >> 4) << 3;
    const int b_r = lane & 7;
    const int b_c = ((lane >> 3) & 1) << 3;

    for (int jt = 0; jt <= qt; jt++) {
        const int j0 = jt * 64;
        __syncthreads();

        // Stage K (row-major) and V^T ([e][s]) — pure bf16 copies
        for (int idx = tid; idx < 512; idx += 128) {
            int r = idx >> 3;
            int c = (idx & 7) * 8;
            *(uint4*)(Kh + r*AQS + c) = *(const uint4*)(khb + (size_t)(j0 + r)*HDD + c);
            *(uint4*)(Kl + r*AQS + c) = *(const uint4*)(klb + (size_t)(j0 + r)*HDD + c);
            *(uint4*)(Vh + r*AQS + c) = *(const uint4*)(vhb + (size_t)r*TT + j0 + c);
            *(uint4*)(Vl + r*AQS + c) = *(const uint4*)(vlb + (size_t)r*TT + j0 + c);
        }
        __syncthreads();

        // S = Q K^T
        float s[8][4];
        #pragma unroll
        for (int nt = 0; nt < 8; nt++)
            #pragma unroll
            for (int r = 0; r < 4; r++) s[nt][r] = 0.0f;

        #pragma unroll
        for (int kk = 0; kk < 4; kk++) {
            uint32_t qah[4], qal[4];
            ldsm_x4(qah, smem_u32(Qh + (w*16 + a_r)*AQS + kk*16 + a_c));
            ldsm_x4(qal, smem_u32(Ql + (w*16 + a_r)*AQS + kk*16 + a_c));
            #pragma unroll
            for (int nt = 0; nt < 8; nt++) {
                uint32_t kbh[2], kbl[2];
                ldsm_x2(kbh, smem_u32(Kh + (nt*8 + b_r)*AQS + kk*16 + b_c));
                ldsm_x2(kbl, smem_u32(Kl + (nt*8 + b_r)*AQS + kk*16 + b_c));
                mma16816(s[nt], qah, kbh);
                mma16816(s[nt], qah, kbl);
                mma16816(s[nt], qal, kbh);
            }
        }

        const int r0 = q0 + w*16 + g;
        const int r1 = r0 + 8;
        if (jt == qt) {
            #pragma unroll
            for (int nt = 0; nt < 8; nt++) {
                int c0 = j0 + nt*8 + 2*t;
                if (c0     > r0) s[nt][0] = -1e30f;
                if (c0 + 1 > r0) s[nt][1] = -1e30f;
                if (c0     > r1) s[nt][2] = -1e30f;
                if (c0 + 1 > r1) s[nt][3] = -1e30f;
            }
        }

        float mx0 = -1e30f, mx1 = -1e30f;
        #pragma unroll
        for (int nt = 0; nt < 8; nt++) {
            mx0 = fmaxf(mx0, fmaxf(s[nt][0], s[nt][1]));
            mx1 = fmaxf(mx1, fmaxf(s[nt][2], s[nt][3]));
        }
        #pragma unroll
        for (int off = 1; off <= 2; off <<= 1) {
            mx0 = fmaxf(mx0, __shfl_xor_sync(0xffffffffu, mx0, off));
            mx1 = fmaxf(mx1, __shfl_xor_sync(0xffffffffu, mx1, off));
        }
        float mn0 = fmaxf(m[0], mx0);
        float mn1 = fmaxf(m[1], mx1);
        float f0 = __expf(m[0] - mn0);
        float f1 = __expf(m[1] - mn1);
        float rs0 = 0.0f, rs1 = 0.0f;
        #pragma unroll
        for (int nt = 0; nt < 8; nt++) {
            s[nt][0] = __expf(s[nt][0] - mn0);
            s[nt][1] = __expf(s[nt][1] - mn0);
            s[nt][2] = __expf(s[nt][2] - mn1);
            s[nt][3] = __expf(s[nt][3] - mn1);
            rs0 += s[nt][0] + s[nt][1];
            rs1 += s[nt][2] + s[nt][3];
        }
        #pragma unroll
        for (int off = 1; off <= 2; off <<= 1) {
            rs0 += __shfl_xor_sync(0xffffffffu, rs0, off);
            rs1 += __shfl_xor_sync(0xffffffffu, rs1, off);
        }
        l[0] = l[0] * f0 + rs0;
        l[1] = l[1] * f1 + rs1;
        m[0] = mn0;
        m[1] = mn1;
        #pragma unroll
        for (int et = 0; et < 8; et++) {
            o[et][0] *= f0; o[et][1] *= f0;
            o[et][2] *= f1; o[et][3] *= f1;
        }

        // P*V (register-built A fragments)
        #pragma unroll
        for (int kt = 0; kt < 4; kt++) {
            uint32_t pah[4], pal[4];
            split_pack(s[2*kt][0],   s[2*kt][1],   pah[0], pal[0]);
            split_pack(s[2*kt][2],   s[2*kt][3],   pah[1], pal[1]);
            split_pack(s[2*kt+1][0], s[2*kt+1][1], pah[2], pal[2]);
            split_pack(s[2*kt+1][2], s[2*kt+1][3], pah[3], pal[3]);
            #pragma unroll
            for (int et = 0; et < 8; et++) {
                uint32_t vbh[2], vbl[2];
                ldsm_x2(vbh, smem_u32(Vh + (et*8 + b_r)*AQS + kt*16 + b_c));
                ldsm_x2(vbl, smem_u32(Vl + (et*8 + b_r)*AQS + kt*16 + b_c));
                mma16816(o[et], pah, vbh);
                mma16816(o[et], pah, vbl);
                mma16816(o[et], pal, vbh);
            }
        }
    }

    // Epilogue: normalize, write bf16 hi/lo head-concat [B,T,D]
    float inv0 = 1.0f / l[0];
    float inv1 = 1.0f / l[1];
    int tq = q0 + w*16 + g;
    #pragma unroll
    for (int et = 0; et < 8; et++) {
        int col = hh*HDD + et*8 + 2*t;
        uint32_t hv, lv;
        size_t a0 = ((size_t)b*TT + tq)*DD + col;
        size_t a1 = ((size_t)b*TT + tq + 8)*DD + col;
        split_pack(o[et][0]*inv0, o[et][1]*inv0, hv, lv);
        *(uint32_t*)&g_aoh[a0] = hv;
        *(uint32_t*)&g_aol[a0] = lv;
        split_pack(o[et][2]*inv1, o[et][3]*inv1, hv, lv);
        *(uint32_t*)&g_aoh[a1] = hv;
        *(uint32_t*)&g_aol[a1] = lv;
    }
}

// ============================================================================
// Launch
// ============================================================================
extern "C" void kernel_launch(void* const* d_in, const int* in_sizes, int n_in,
                              void* d_out, int out_size)
{
    const float* x  = (const float*)d_in[0];
    const float* Wq = (const float*)d_in[1];
    const float* Wk = (const float*)d_in[2];
    const float* Wv = (const float*)d_in[3];
    const float* Wo = (const float*)d_in[4];
    const float* bo = (const float*)d_in[5];
    float* out = (float*)d_out;

    static bf16 *xh_p = nullptr;
    bf16 *xh, *xl, *wqh, *wql, *wkh, *wkl, *wvh, *wvl, *woh, *wol;
    cudaGetSymbolAddress((void**)&xh,  g_xh);
    cudaGetSymbolAddress((void**)&xl,  g_xl);
    cudaGetSymbolAddress((void**)&wqh, g_wqh);
    cudaGetSymbolAddress((void**)&wql, g_wql);
    cudaGetSymbolAddress((void**)&wkh, g_wkh);
    cudaGetSymbolAddress((void**)&wkl, g_wkl);
    cudaGetSymbolAddress((void**)&wvh, g_wvh);
    cudaGetSymbolAddress((void**)&wvl, g_wvl);
    cudaGetSymbolAddress((void**)&woh, g_woh);
    cudaGetSymbolAddress((void**)&wol, g_wol);
    (void)xh_p;

    cudaFuncSetAttribute(qkv_gemm_tc, cudaFuncAttributeMaxDynamicSharedMemorySize,
                         GEMM_SMEM_BYTES);
    cudaFuncSetAttribute(out_gemm_tc, cudaFuncAttributeMaxDynamicSharedMemorySize,
                         GEMM_SMEM_BYTES);
    cudaFuncSetAttribute(attn_tc, cudaFuncAttributeMaxDynamicSharedMemorySize,
                         ATTN_SMEM_BYTES);

    // 0) one-time-per-call splits (cheap: ~48MB traffic)
    int nx = MTOT*DD/4, nw = DD*DD/4;
    convert_split_k<<<(nx+255)/256, 256>>>((const float4*)x,  xh,  xl,  nx);
    convert_split_k<<<(nw+255)/256, 256>>>((const float4*)Wq, wqh, wql, nw);
    convert_split_k<<<(nw+255)/256, 256>>>((const float4*)Wk, wkh, wkl, nw);
    convert_split_k<<<(nw+255)/256, 256>>>((const float4*)Wv, wvh, wvl, nw);
    convert_split_k<<<(nw+255)/256, 256>>>((const float4*)Wo, woh, wol, nw);

    // 1) QKV projections
    qkv_gemm_tc<<<dim3(DD/128, MTOT/128, 3), 256, GEMM_SMEM_BYTES>>>(0);

    // 2) Attention
    attn_tc<<<dim3(TT/64, BB*HH), 128, ATTN_SMEM_BYTES>>>();

    // 3) Output projection
    out_gemm_tc<<<dim3(DD/128, MTOT/128), 256, GEMM_SMEM_BYTES>>>(bo, out);
}

// round 7
// speedup vs baseline: 3.1201x; 1.0053x over previous
#include <cuda_runtime.h>
#include <cuda_bf16.h>
#include <cstdint>
#include <math.h>

#define BB   4
#define TT   2048
#define DD   1024
#define HH   16
#define HDD  64
#define MTOT (BB*TT)   // 8192

typedef __nv_bfloat16  bf16;
typedef __nv_bfloat162 bf162;

// ---- bf16 hi/lo split globals (split computed ONCE) ----
__device__ bf16 g_xh [(size_t)MTOT*DD],  g_xl [(size_t)MTOT*DD];
__device__ bf16 g_wqh[(size_t)DD*DD],    g_wql[(size_t)DD*DD];
__device__ bf16 g_wkh[(size_t)DD*DD],    g_wkl[(size_t)DD*DD];
__device__ bf16 g_wvh[(size_t)DD*DD],    g_wvl[(size_t)DD*DD];
__device__ bf16 g_woh[(size_t)DD*DD],    g_wol[(size_t)DD*DD];
__device__ bf16 g_qh [(size_t)MTOT*DD],  g_ql [(size_t)MTOT*DD];   // [B,H,T,HD] (prescaled 1/8)
__device__ bf16 g_kh [(size_t)MTOT*DD],  g_kl [(size_t)MTOT*DD];   // [B,H,T,HD]
__device__ bf16 g_vth[(size_t)MTOT*DD],  g_vtl[(size_t)MTOT*DD];   // [B,H,HD,T] transposed
__device__ bf16 g_aoh[(size_t)MTOT*DD],  g_aol[(size_t)MTOT*DD];   // [B,T,D]

// ============================================================================
// Helpers
// ============================================================================
__device__ __forceinline__ uint32_t smem_u32(const void* p) {
    return (uint32_t)__cvta_generic_to_shared(p);
}
__device__ __forceinline__ void ldsm_x4(uint32_t r[4], uint32_t addr) {
    asm volatile("ldmatrix.sync.aligned.m8n8.x4.shared.b16 {%0,%1,%2,%3}, [%4];"
                 : "=r"(r[0]), "=r"(r[1]), "=r"(r[2]), "=r"(r[3]) : "r"(addr));
}
__device__ __forceinline__ void ldsm_x2(uint32_t r[2], uint32_t addr) {
    asm volatile("ldmatrix.sync.aligned.m8n8.x2.shared.b16 {%0,%1}, [%2];"
                 : "=r"(r[0]), "=r"(r[1]) : "r"(addr));
}
__device__ __forceinline__ void mma16816(float d[4], const uint32_t a[4], const uint32_t b[2]) {
    asm volatile(
        "mma.sync.aligned.m16n8k16.row.col.f32.bf16.bf16.f32 "
        "{%0,%1,%2,%3}, {%4,%5,%6,%7}, {%8,%9}, {%0,%1,%2,%3};"
        : "+f"(d[0]), "+f"(d[1]), "+f"(d[2]), "+f"(d[3])
        : "r"(a[0]), "r"(a[1]), "r"(a[2]), "r"(a[3]), "r"(b[0]), "r"(b[1]));
}
__device__ __forceinline__ void split2(float x, float y, bf162& h, bf162& l) {
    bf16 hx = __float2bfloat16(x);
    bf16 hy = __float2bfloat16(y);
    h = __halves2bfloat162(hx, hy);
    l = __halves2bfloat162(__float2bfloat16(x - __bfloat162float(hx)),
                           __float2bfloat16(y - __bfloat162float(hy)));
}
__device__ __forceinline__ void split_pack(float x, float y, uint32_t& h, uint32_t& l) {
    bf162 hv, lv;
    split2(x, y, hv, lv);
    h = *(uint32_t*)&hv;
    l = *(uint32_t*)&lv;
}
__device__ __forceinline__ void cp16(uint32_t s, const void* g) {
    asm volatile("cp.async.ca.shared.global [%0], [%1], 16;\n" :: "r"(s), "l"(g));
}
#define CP_COMMIT() asm volatile("cp.async.commit_group;\n" ::: "memory")
template<int N> __device__ __forceinline__ void cp_wait() {
    asm volatile("cp.async.wait_group %0;\n" :: "n"(N) : "memory");
}

// ============================================================================
// Convert kernel: fp32 -> bf16 hi/lo split
// ============================================================================
__global__ __launch_bounds__(256) void convert_split_k(
    const float4* __restrict__ src, bf16* __restrict__ ho, bf16* __restrict__ lo, int n4)
{
    int i = blockIdx.x * 256 + threadIdx.x;
    if (i < n4) {
        float4 v = src[i];
        bf162 h0, l0, h1, l1;
        split2(v.x, v.y, h0, l0);
        split2(v.z, v.w, h1, l1);
        *(bf162*)(ho + (size_t)i*4)     = h0;
        *(bf162*)(ho + (size_t)i*4 + 2) = h1;
        *(bf162*)(lo + (size_t)i*4)     = l0;
        *(bf162*)(lo + (size_t)i*4 + 2) = l1;
    }
}

// ============================================================================
// Pipelined bf16 GEMM mainloop (128x128x32, 3-stage cp.async)
// ============================================================================
#define LDKB 40
#define STG_ARR (128*LDKB)
#define STG4    (4*STG_ARR)
#define GEMM_SMEM_BYTES (3*STG4*2)   // 122880

__device__ __forceinline__ void gemm_load_stage(
    const bf16* __restrict__ Ahg, const bf16* __restrict__ Alg,
    const bf16* __restrict__ Bhg, const bf16* __restrict__ Blg,
    int m0, int n0, int k0, bf16* base, int tid)
{
    const bf16* gp[4] = {Ahg, Alg, Bhg, Blg};
    #pragma unroll
    for (int a = 0; a < 4; a++) {
        int row0 = (a < 2) ? m0 : n0;
        bf16* sb = base + a*STG_ARR;
        #pragma unroll
        for (int s = 0; s < 2; s++) {
            int idx = tid + s*256;
            int r = idx >> 2;
            int c = (idx & 3) * 8;
            cp16(smem_u32(sb + r*LDKB + c), gp[a] + (size_t)(row0 + r)*DD + k0 + c);
        }
    }
}

__device__ __forceinline__ void gemm_mainloop_bf16(
    const bf16* __restrict__ Ahg, const bf16* __restrict__ Alg,
    const bf16* __restrict__ Bhg, const bf16* __restrict__ Blg,
    int m0, int n0, bf16* smem, float acc[4][4][4])
{
    const int tid  = threadIdx.x;
    const int lane = tid & 31;
    const int warp = tid >> 5;
    const int wm = warp >> 2;
    const int wn = warp & 3;

    const int a_r = lane & 15;
    const int a_c = (lane >> 4) << 3;
    const int b_r = lane & 7;
    const int b_c = ((lane >> 3) & 1) << 3;

    const int NST = DD / 32;

    gemm_load_stage(Ahg, Alg, Bhg, Blg, m0, n0, 0,  smem,        tid); CP_COMMIT();
    gemm_load_stage(Ahg, Alg, Bhg, Blg, m0, n0, 32, smem + STG4, tid); CP_COMMIT();

    for (int i = 0; i < NST; i++) {
        cp_wait<1>();
        __syncthreads();
        if (i + 2 < NST)
            gemm_load_stage(Ahg, Alg, Bhg, Blg, m0, n0, (i+2)*32,
                            smem + ((i+2)%3)*STG4, tid);
        CP_COMMIT();

        bf16* Ahs = smem + (i%3)*STG4;
        bf16* Als = Ahs + STG_ARR;
        bf16* Bhs = Als + STG_ARR;
        bf16* Bls = Bhs + STG_ARR;

        #pragma unroll
        for (int kk = 0; kk < 32; kk += 16) {
            uint32_t ah[4][4], al[4][4];
            #pragma unroll
            for (int mt = 0; mt < 4; mt++) {
                ldsm_x4(ah[mt], smem_u32(Ahs + (wm*64 + mt*16 + a_r)*LDKB + kk + a_c));
                ldsm_x4(al[mt], smem_u32(Als + (wm*64 + mt*16 + a_r)*LDKB + kk + a_c));
            }
            #pragma unroll
            for (int nt = 0; nt < 4; nt++) {
                uint32_t bh[2], bl[2];
                ldsm_x2(bh, smem_u32(Bhs + (wn*32 + nt*8 + b_r)*LDKB + kk + b_c));
                ldsm_x2(bl, smem_u32(Bls + (wn*32 + nt*8 + b_r)*LDKB + kk + b_c));
                #pragma unroll
                for (int mt = 0; mt < 4; mt++) {
                    mma16816(acc[mt][nt], ah[mt], bh);
                    mma16816(acc[mt][nt], ah[mt], bl);
                    mma16816(acc[mt][nt], al[mt], bh);
                }
            }
        }
    }
}

// QKV projection
__global__ __launch_bounds__(256) void qkv_gemm_tc(int)
{
    extern __shared__ bf16 gsm[];

    const int which = blockIdx.z;
    const bf16* Bhg = (which == 0) ? g_wqh : (which == 1) ? g_wkh : g_wvh;
    const bf16* Blg = (which == 0) ? g_wql : (which == 1) ? g_wkl : g_wvl;

    const int m0 = blockIdx.y * 128;
    const int n0 = blockIdx.x * 128;

    float acc[4][4][4];
    #pragma unroll
    for (int i = 0; i < 4; i++)
        #pragma unroll
        for (int j = 0; j < 4; j++)
            #pragma unroll
            for (int r = 0; r < 4; r++) acc[i][j][r] = 0.0f;

    gemm_mainloop_bf16(g_xh, g_xl, Bhg, Blg, m0, n0, gsm, acc);

    const int tid  = threadIdx.x;
    const int lane = tid & 31;
    const int warp = tid >> 5;
    const int wm = warp >> 2, wn = warp & 3;
    const int g = lane >> 2, t = lane & 3;
    const int bb = m0 >> 11;
    const int mloc = m0 & 2047;

    if (which == 2) {
        // Stage fp32 C-tile in smem, then write V^T hi/lo coalesced.
        float* Cs = (float*)gsm;     // 128 x 133 floats = 68096 B < 122880
        __syncthreads();             // all warps done with mainloop smem
        #pragma unroll
        for (int mt = 0; mt < 4; mt++) {
            #pragma unroll
            for (int nt = 0; nt < 4; nt++) {
                int row = wm*64 + mt*16 + g;
                int col = wn*32 + nt*8 + 2*t;
                Cs[row*133 + col]       = acc[mt][nt][0];
                Cs[row*133 + col + 1]   = acc[mt][nt][1];
                Cs[(row+8)*133 + col]   = acc[mt][nt][2];
                Cs[(row+8)*133 + col+1] = acc[mt][nt][3];
            }
        }
        __syncthreads();
        // 128 e-rows x 16 t-chunks of 8
        for (int idx = tid; idx < 2048; idx += 256) {
            int el  = idx >> 4;
            int tch = (idx & 15) * 8;
            bf16 hv8[8], lv8[8];
            #pragma unroll
            for (int q = 0; q < 8; q++) {
                float v = Cs[(tch + q)*133 + el];
                bf16 hv = __float2bfloat16(v);
                hv8[q] = hv;
                lv8[q] = __float2bfloat16(v - __bfloat162float(hv));
            }
            int col = n0 + el;
            int hh = col >> 6, e = col & 63;
            size_t rb = (((size_t)bb*HH + hh)*HDD + e)*TT + mloc + tch;
            *(uint4*)&g_vth[rb] = *(uint4*)hv8;
            *(uint4*)&g_vtl[rb] = *(uint4*)lv8;
        }
    } else {
        float sc = (which == 0) ? 0.125f : 1.0f;
        bf16* hp = (which == 0) ? g_qh : g_kh;
        bf16* lp = (which == 0) ? g_ql : g_kl;
        #pragma unroll
        for (int mt = 0; mt < 4; mt++) {
            #pragma unroll
            for (int nt = 0; nt < 4; nt++) {
                int row = mloc + wm*64 + mt*16 + g;
                int col = n0 + wn*32 + nt*8 + 2*t;
                int hh = col >> 6, e = col & 63;
                uint32_t hv, lv;
                size_t a0 = (((size_t)bb*HH + hh)*TT + row)*HDD + e;
                size_t a1 = (((size_t)bb*HH + hh)*TT + row + 8)*HDD + e;
                split_pack(acc[mt][nt][0]*sc, acc[mt][nt][1]*sc, hv, lv);
                *(uint32_t*)&hp[a0] = hv;
                *(uint32_t*)&lp[a0] = lv;
                split_pack(acc[mt][nt][2]*sc, acc[mt][nt][3]*sc, hv, lv);
                *(uint32_t*)&hp[a1] = hv;
                *(uint32_t*)&lp[a1] = lv;
            }
        }
    }
}

// Output projection
__global__ __launch_bounds__(256) void out_gemm_tc(
    const float* __restrict__ bo, float* __restrict__ outp)
{
    extern __shared__ bf16 gsm[];

    const int m0 = blockIdx.y * 128;
    const int n0 = blockIdx.x * 128;

    float acc[4][4][4];
    #pragma unroll
    for (int i = 0; i < 4; i++)
        #pragma unroll
        for (int j = 0; j < 4; j++)
            #pragma unroll
            for (int r = 0; r < 4; r++) acc[i][j][r] = 0.0f;

    gemm_mainloop_bf16(g_aoh, g_aol, g_woh, g_wol, m0, n0, gsm, acc);

    const int lane = threadIdx.x & 31;
    const int warp = threadIdx.x >> 5;
    const int wm = warp >> 2, wn = warp & 3;
    const int g = lane >> 2, t = lane & 3;

    #pragma unroll
    for (int mt = 0; mt < 4; mt++) {
        #pragma unroll
        for (int nt = 0; nt < 4; nt++) {
            int row = m0 + wm*64 + mt*16 + g;
            int col = n0 + wn*32 + nt*8 + 2*t;
            float bx = bo[col], by = bo[col+1];
            float2 v01 = make_float2(acc[mt][nt][0] + bx, acc[mt][nt][1] + by);
            float2 v23 = make_float2(acc[mt][nt][2] + bx, acc[mt][nt][3] + by);
            *(float2*)&outp[(size_t)row*DD + col]     = v01;
            *(float2*)&outp[(size_t)(row+8)*DD + col] = v23;
        }
    }
}

// ============================================================================
// Tensor-core flash attention: Q-tile 128 (8 warps), K/V tiles 64,
// cp.async double-buffered K/V. Warp w owns query rows [w*16, w*16+16).
// ============================================================================
#define AQS 72
#define KVARR (64*AQS)                      // bf16 per K/V array per stage
#define ATTN_Q_BYTES (2*128*AQS*2)          // Qh+Ql = 36864
#define ATTN_KV_BYTES (2*4*KVARR*2)         // 2 stages x (Kh,Kl,Vh,Vl) = 73728
#define ATTN_SMEM_BYTES (ATTN_Q_BYTES + ATTN_KV_BYTES)  // 110592

__device__ __forceinline__ void attn_load_kv(
    const bf16* khb, const bf16* klb, const bf16* vhb, const bf16* vlb,
    int j0, bf16* kvbase, int tid)
{
    bf16* Kh = kvbase;
    bf16* Kl = kvbase + KVARR;
    bf16* Vh = kvbase + 2*KVARR;
    bf16* Vl = kvbase + 3*KVARR;
    for (int idx = tid; idx < 512; idx += 256) {
        int r = idx >> 3;
        int c = (idx & 7) * 8;
        cp16(smem_u32(Kh + r*AQS + c), khb + (size_t)(j0 + r)*HDD + c);
        cp16(smem_u32(Kl + r*AQS + c), klb + (size_t)(j0 + r)*HDD + c);
        cp16(smem_u32(Vh + r*AQS + c), vhb + (size_t)r*TT + j0 + c);
        cp16(smem_u32(Vl + r*AQS + c), vlb + (size_t)r*TT + j0 + c);
    }
}

__global__ __launch_bounds__(256) void attn_tc()
{
    extern __shared__ bf16 asmem[];
    bf16* Qh = asmem;
    bf16* Ql = Qh + 128*AQS;
    bf16* KV = Ql + 128*AQS;    // 2 stages x 4 arrays

    const int bh = blockIdx.y;
    const int hh = bh & (HH-1);
    const int b  = bh >> 4;
    const int qt = gridDim.x - 1 - blockIdx.x;   // longest CTAs first
    const int q0 = qt * 128;
    const int njt = 2*qt + 2;

    const int tid  = threadIdx.x;
    const int lane = tid & 31;
    const int w    = tid >> 5;       // 0..7
    const int g    = lane >> 2;
    const int t    = lane & 3;

    const bf16* __restrict__ qhb = g_qh  + (size_t)bh * TT * HDD;
    const bf16* __restrict__ qlb = g_ql  + (size_t)bh * TT * HDD;
    const bf16* __restrict__ khb = g_kh  + (size_t)bh * TT * HDD;
    const bf16* __restrict__ klb = g_kl  + (size_t)bh * TT * HDD;
    const bf16* __restrict__ vhb = g_vth + (size_t)bh * HDD * TT;
    const bf16* __restrict__ vlb = g_vtl + (size_t)bh * HDD * TT;

    // Stage Q (128 rows)
    for (int idx = tid; idx < 1024; idx += 256) {
        int r = idx >> 3;
        int c = (idx & 7) * 8;
        *(uint4*)(Qh + r*AQS + c) = *(const uint4*)(qhb + (size_t)(q0 + r)*HDD + c);
        *(uint4*)(Ql + r*AQS + c) = *(const uint4*)(qlb + (size_t)(q0 + r)*HDD + c);
    }

    // Preload K/V tile 0
    attn_load_kv(khb, klb, vhb, vlb, 0, KV, tid); CP_COMMIT();

    float o[8][4];
    float m[2], l[2];
    #pragma unroll
    for (int et = 0; et < 8; et++)
        #pragma unroll
        for (int r = 0; r < 4; r++) o[et][r] = 0.0f;
    m[0] = m[1] = -1e30f;
    l[0] = l[1] = 0.0f;

    const int a_r = lane & 15;
    const int a_c = (lane >> 4) << 3;
    const int b_r = lane & 7;
    const int b_c = ((lane >> 3) & 1) << 3;

    const int r0w = q0 + w*16;       // warp's first query row

    for (int jt = 0; jt < njt; jt++) {
        const int j0 = jt * 64;

        __syncthreads();   // everyone done computing on buf (jt+1)%2 (from jt-1)
        if (jt + 1 < njt)
            attn_load_kv(khb, klb, vhb, vlb, (jt+1)*64, KV + ((jt+1)&1)*4*KVARR, tid);
        CP_COMMIT();
        cp_wait<1>();      // stage jt resident
        __syncthreads();

        // Fully-masked tile for this warp? (all kc >= j0 > warp's max row)
        if (j0 > r0w + 15) continue;   // no barrier inside: safe

        bf16* Kh = KV + (jt&1)*4*KVARR;
        bf16* Kl = Kh + KVARR;
        bf16* Vh = Kl + KVARR;
        bf16* Vl = Vh + KVARR;

        // S = Q K^T
        float s[8][4];
        #pragma unroll
        for (int nt = 0; nt < 8; nt++)
            #pragma unroll
            for (int r = 0; r < 4; r++) s[nt][r] = 0.0f;

        #pragma unroll
        for (int kk = 0; kk < 4; kk++) {
            uint32_t qah[4], qal[4];
            ldsm_x4(qah, smem_u32(Qh + (w*16 + a_r)*AQS + kk*16 + a_c));
            ldsm_x4(qal, smem_u32(Ql + (w*16 + a_r)*AQS + kk*16 + a_c));
            #pragma unroll
            for (int nt = 0; nt < 8; nt++) {
                uint32_t kbh[2], kbl[2];
                ldsm_x2(kbh, smem_u32(Kh + (nt*8 + b_r)*AQS + kk*16 + b_c));
                ldsm_x2(kbl, smem_u32(Kl + (nt*8 + b_r)*AQS + kk*16 + b_c));
                mma16816(s[nt], qah, kbh);
                mma16816(s[nt], qah, kbl);
                mma16816(s[nt], qal, kbh);
            }
        }

        const int r0 = r0w + g;
        const int r1 = r0 + 8;
        if (j0 + 63 > r0w) {           // tile touches the causal frontier
            #pragma unroll
            for (int nt = 0; nt < 8; nt++) {
                int c0 = j0 + nt*8 + 2*t;
                if (c0     > r0) s[nt][0] = -1e30f;
                if (c0 + 1 > r0) s[nt][1] = -1e30f;
                if (c0     > r1) s[nt][2] = -1e30f;
                if (c0 + 1 > r1) s[nt][3] = -1e30f;
            }
        }

        float mx0 = -1e30f, mx1 = -1e30f;
        #pragma unroll
        for (int nt = 0; nt < 8; nt++) {
            mx0 = fmaxf(mx0, fmaxf(s[nt][0], s[nt][1]));
            mx1 = fmaxf(mx1, fmaxf(s[nt][2], s[nt][3]));
        }
        #pragma unroll
        for (int off = 1; off <= 2; off <<= 1) {
            mx0 = fmaxf(mx0, __shfl_xor_sync(0xffffffffu, mx0, off));
            mx1 = fmaxf(mx1, __shfl_xor_sync(0xffffffffu, mx1, off));
        }
        float mn0 = fmaxf(m[0], mx0);
        float mn1 = fmaxf(m[1], mx1);
        float f0 = __expf(m[0] - mn0);
        float f1 = __expf(m[1] - mn1);
        float rs0 = 0.0f, rs1 = 0.0f;
        #pragma unroll
        for (int nt = 0; nt < 8; nt++) {
            s[nt][0] = __expf(s[nt][0] - mn0);
            s[nt][1] = __expf(s[nt][1] - mn0);
            s[nt][2] = __expf(s[nt][2] - mn1);
            s[nt][3] = __expf(s[nt][3] - mn1);
            rs0 += s[nt][0] + s[nt][1];
            rs1 += s[nt][2] + s[nt][3];
        }
        #pragma unroll
        for (int off = 1; off <= 2; off <<= 1) {
            rs0 += __shfl_xor_sync(0xffffffffu, rs0, off);
            rs1 += __shfl_xor_sync(0xffffffffu, rs1, off);
        }
        l[0] = l[0] * f0 + rs0;
        l[1] = l[1] * f1 + rs1;
        m[0] = mn0;
        m[1] = mn1;
        #pragma unroll
        for (int et = 0; et < 8; et++) {
            o[et][0] *= f0; o[et][1] *= f0;
            o[et][2] *= f1; o[et][3] *= f1;
        }

        // P*V
        #pragma unroll
        for (int kt = 0; kt < 4; kt++) {
            uint32_t pah[4], pal[4];
            split_pack(s[2*kt][0],   s[2*kt][1],   pah[0], pal[0]);
            split_pack(s[2*kt][2],   s[2*kt][3],   pah[1], pal[1]);
            split_pack(s[2*kt+1][0], s[2*kt+1][1], pah[2], pal[2]);
            split_pack(s[2*kt+1][2], s[2*kt+1][3], pah[3], pal[3]);
            #pragma unroll
            for (int et = 0; et < 8; et++) {
                uint32_t vbh[2], vbl[2];
                ldsm_x2(vbh, smem_u32(Vh + (et*8 + b_r)*AQS + kt*16 + b_c));
                ldsm_x2(vbl, smem_u32(Vl + (et*8 + b_r)*AQS + kt*16 + b_c));
                mma16816(o[et], pah, vbh);
                mma16816(o[et], pah, vbl);
                mma16816(o[et], pal, vbh);
            }
        }
    }

    // Epilogue: normalize, write bf16 hi/lo head-concat [B,T,D]
    float inv0 = 1.0f / l[0];
    float inv1 = 1.0f / l[1];
    int tq = q0 + w*16 + g;
    #pragma unroll
    for (int et = 0; et < 8; et++) {
        int col = hh*HDD + et*8 + 2*t;
        uint32_t hv, lv;
        size_t a0 = ((size_t)b*TT + tq)*DD + col;
        size_t a1 = ((size_t)b*TT + tq + 8)*DD + col;
        split_pack(o[et][0]*inv0, o[et][1]*inv0, hv, lv);
        *(uint32_t*)&g_aoh[a0] = hv;
        *(uint32_t*)&g_aol[a0] = lv;
        split_pack(o[et][2]*inv1, o[et][3]*inv1, hv, lv);
        *(uint32_t*)&g_aoh[a1] = hv;
        *(uint32_t*)&g_aol[a1] = lv;
    }
}

// ============================================================================
// Launch
// ============================================================================
extern "C" void kernel_launch(void* const* d_in, const int* in_sizes, int n_in,
                              void* d_out, int out_size)
{
    const float* x  = (const float*)d_in[0];
    const float* Wq = (const float*)d_in[1];
    const float* Wk = (const float*)d_in[2];
    const float* Wv = (const float*)d_in[3];
    const float* Wo = (const float*)d_in[4];
    const float* bo = (const float*)d_in[5];
    float* out = (float*)d_out;

    bf16 *xh, *xl, *wqh, *wql, *wkh, *wkl, *wvh, *wvl, *woh, *wol;
    cudaGetSymbolAddress((void**)&xh,  g_xh);
    cudaGetSymbolAddress((void**)&xl,  g_xl);
    cudaGetSymbolAddress((void**)&wqh, g_wqh);
    cudaGetSymbolAddress((void**)&wql, g_wql);
    cudaGetSymbolAddress((void**)&wkh, g_wkh);
    cudaGetSymbolAddress((void**)&wkl, g_wkl);
    cudaGetSymbolAddress((void**)&wvh, g_wvh);
    cudaGetSymbolAddress((void**)&wvl, g_wvl);
    cudaGetSymbolAddress((void**)&woh, g_woh);
    cudaGetSymbolAddress((void**)&wol, g_wol);

    cudaFuncSetAttribute(qkv_gemm_tc, cudaFuncAttributeMaxDynamicSharedMemorySize,
                         GEMM_SMEM_BYTES);
    cudaFuncSetAttribute(out_gemm_tc, cudaFuncAttributeMaxDynamicSharedMemorySize,
                         GEMM_SMEM_BYTES);
    cudaFuncSetAttribute(attn_tc, cudaFuncAttributeMaxDynamicSharedMemorySize,
                         ATTN_SMEM_BYTES);

    int nx = MTOT*DD/4, nw = DD*DD/4;
    convert_split_k<<<(nx+255)/256, 256>>>((const float4*)x,  xh,  xl,  nx);
    convert_split_k<<<(nw+255)/256, 256>>>((const float4*)Wq, wqh, wql, nw);
    convert_split_k<<<(nw+255)/256, 256>>>((const float4*)Wk, wkh, wkl, nw);
    convert_split_k<<<(nw+255)/256, 256>>>((const float4*)Wv, wvh, wvl, nw);
    convert_split_k<<<(nw+255)/256, 256>>>((const float4*)Wo, woh, wol, nw);

    qkv_gemm_tc<<<dim3(DD/128, MTOT/128, 3), 256, GEMM_SMEM_BYTES>>>(0);
    attn_tc<<<dim3(TT/128, BB*HH), 256, ATTN_SMEM_BYTES>>>();
    out_gemm_tc<<<dim3(DD/128, MTOT/128), 256, GEMM_SMEM_BYTES>>>(bo, out);
}

// round 8
// speedup vs baseline: 3.4710x; 1.1125x over previous
#include <cuda_runtime.h>
#include <cuda_bf16.h>
#include <cstdint>
#include <math.h>

#define BB   4
#define TT   2048
#define DD   1024
#define HH   16
#define HDD  64
#define MTOT (BB*TT)   // 8192

typedef __nv_bfloat16  bf16;
typedef __nv_bfloat162 bf162;

// ---- bf16 hi/lo split globals ----
__device__ bf16 g_xh [(size_t)MTOT*DD],  g_xl [(size_t)MTOT*DD];
__device__ bf16 g_wqh[(size_t)DD*DD],    g_wql[(size_t)DD*DD];
__device__ bf16 g_wkh[(size_t)DD*DD],    g_wkl[(size_t)DD*DD];
__device__ bf16 g_wvh[(size_t)DD*DD],    g_wvl[(size_t)DD*DD];
__device__ bf16 g_woh[(size_t)DD*DD],    g_wol[(size_t)DD*DD];
__device__ bf16 g_qh [(size_t)MTOT*DD],  g_ql [(size_t)MTOT*DD];   // [B,H,T,HD] (prescaled 1/8)
__device__ bf16 g_kh [(size_t)MTOT*DD],  g_kl [(size_t)MTOT*DD];   // [B,H,T,HD]
__device__ bf16 g_vth[(size_t)MTOT*DD],  g_vtl[(size_t)MTOT*DD];   // [B,H,HD,T]
__device__ bf16 g_aoh[(size_t)MTOT*DD],  g_aol[(size_t)MTOT*DD];   // [B,T,D]

// ============================================================================
// Helpers
// ============================================================================
__device__ __forceinline__ uint32_t smem_u32(const void* p) {
    return (uint32_t)__cvta_generic_to_shared(p);
}
__device__ __forceinline__ void ldsm_x4(uint32_t r[4], uint32_t addr) {
    asm volatile("ldmatrix.sync.aligned.m8n8.x4.shared.b16 {%0,%1,%2,%3}, [%4];"
                 : "=r"(r[0]), "=r"(r[1]), "=r"(r[2]), "=r"(r[3]) : "r"(addr));
}
__device__ __forceinline__ void mma16816(float d[4], const uint32_t a[4], const uint32_t b0, const uint32_t b1) {
    asm volatile(
        "mma.sync.aligned.m16n8k16.row.col.f32.bf16.bf16.f32 "
        "{%0,%1,%2,%3}, {%4,%5,%6,%7}, {%8,%9}, {%0,%1,%2,%3};"
        : "+f"(d[0]), "+f"(d[1]), "+f"(d[2]), "+f"(d[3])
        : "r"(a[0]), "r"(a[1]), "r"(a[2]), "r"(a[3]), "r"(b0), "r"(b1));
}
__device__ __forceinline__ void split2(float x, float y, bf162& h, bf162& l) {
    bf16 hx = __float2bfloat16(x);
    bf16 hy = __float2bfloat16(y);
    h = __halves2bfloat162(hx, hy);
    l = __halves2bfloat162(__float2bfloat16(x - __bfloat162float(hx)),
                           __float2bfloat16(y - __bfloat162float(hy)));
}
__device__ __forceinline__ void split_pack(float x, float y, uint32_t& h, uint32_t& l) {
    bf162 hv, lv;
    split2(x, y, hv, lv);
    h = *(uint32_t*)&hv;
    l = *(uint32_t*)&lv;
}
__device__ __forceinline__ void cp16(uint32_t s, const void* g) {
    asm volatile("cp.async.ca.shared.global [%0], [%1], 16;\n" :: "r"(s), "l"(g));
}
#define CP_COMMIT() asm volatile("cp.async.commit_group;\n" ::: "memory")
template<int N> __device__ __forceinline__ void cp_wait() {
    asm volatile("cp.async.wait_group %0;\n" :: "n"(N) : "memory");
}

// ============================================================================
// Convert kernels
// ============================================================================
__global__ __launch_bounds__(256) void convert_x_k(const float4* __restrict__ src)
{
    int i = blockIdx.x * 256 + threadIdx.x;
    float4 v = src[i];
    bf162 h0, l0, h1, l1;
    split2(v.x, v.y, h0, l0);
    split2(v.z, v.w, h1, l1);
    *(bf162*)(g_xh + (size_t)i*4)     = h0;
    *(bf162*)(g_xh + (size_t)i*4 + 2) = h1;
    *(bf162*)(g_xl + (size_t)i*4)     = l0;
    *(bf162*)(g_xl + (size_t)i*4 + 2) = l1;
}
__global__ __launch_bounds__(256) void convert_w_k(
    const float4* __restrict__ wq, const float4* __restrict__ wk,
    const float4* __restrict__ wv, const float4* __restrict__ wo)
{
    int which = blockIdx.y;
    const float4* src = (which == 0) ? wq : (which == 1) ? wk : (which == 2) ? wv : wo;
    bf16* ho = (which == 0) ? g_wqh : (which == 1) ? g_wkh : (which == 2) ? g_wvh : g_woh;
    bf16* lo = (which == 0) ? g_wql : (which == 1) ? g_wkl : (which == 2) ? g_wvl : g_wol;
    int i = blockIdx.x * 256 + threadIdx.x;
    float4 v = src[i];
    bf162 h0, l0, h1, l1;
    split2(v.x, v.y, h0, l0);
    split2(v.z, v.w, h1, l1);
    *(bf162*)(ho + (size_t)i*4)     = h0;
    *(bf162*)(ho + (size_t)i*4 + 2) = h1;
    *(bf162*)(lo + (size_t)i*4)     = l0;
    *(bf162*)(lo + (size_t)i*4 + 2) = l1;
}

// ============================================================================
// GEMM: CTA 128x128, 128 threads (4 warps, 2m x 2n), warp tile 64x64.
// 2-stage cp.async pipeline, B-fragments via ldsm_x4 n-tile pairs.
// ============================================================================
#define LDKB 40
#define STG_ARR (128*LDKB)          // bf16 per array per stage
#define STG4    (4*STG_ARR)         // Ah,Al,Bh,Bl
#define GEMM_SMEM_BYTES (2*STG4*2)  // 81920

__device__ __forceinline__ void gemm_load_stage(
    const bf16* __restrict__ Ahg, const bf16* __restrict__ Alg,
    const bf16* __restrict__ Bhg, const bf16* __restrict__ Blg,
    int m0, int n0, int k0, bf16* base, int tid)
{
    const bf16* gp[4] = {Ahg, Alg, Bhg, Blg};
    #pragma unroll
    for (int a = 0; a < 4; a++) {
        int row0 = (a < 2) ? m0 : n0;
        bf16* sb = base + a*STG_ARR;
        #pragma unroll
        for (int s = 0; s < 4; s++) {
            int idx = tid + s*128;
            int r = idx >> 2;
            int c = (idx & 3) * 8;
            cp16(smem_u32(sb + r*LDKB + c), gp[a] + (size_t)(row0 + r)*DD + k0 + c);
        }
    }
}

__device__ __forceinline__ void gemm_mainloop(
    const bf16* __restrict__ Ahg, const bf16* __restrict__ Alg,
    const bf16* __restrict__ Bhg, const bf16* __restrict__ Blg,
    int m0, int n0, bf16* smem, float acc[4][8][4])
{
    const int tid  = threadIdx.x;
    const int lane = tid & 31;
    const int warp = tid >> 5;
    const int wm = warp >> 1;            // 0..1
    const int wn = warp & 1;             // 0..1

    const int a_r  = lane & 15;
    const int a_c  = (lane >> 4) << 3;
    const int b4_r = ((lane >> 4) << 3) + (lane & 7);   // row within 16-row pair
    const int b4_c = ((lane >> 3) & 1) << 3;            // k-half

    const int NST = DD / 32;

    gemm_load_stage(Ahg, Alg, Bhg, Blg, m0, n0, 0, smem, tid); CP_COMMIT();

    for (int i = 0; i < NST; i++) {
        __syncthreads();                 // everyone done with buf (i+1)&1 (from i-1)
        if (i + 1 < NST)
            gemm_load_stage(Ahg, Alg, Bhg, Blg, m0, n0, (i+1)*32,
                            smem + ((i+1)&1)*STG4, tid);
        CP_COMMIT();
        cp_wait<1>();                    // stage i resident
        __syncthreads();

        bf16* Ahs = smem + (i&1)*STG4;
        bf16* Als = Ahs + STG_ARR;
        bf16* Bhs = Als + STG_ARR;
        bf16* Bls = Bhs + STG_ARR;

        #pragma unroll
        for (int kk = 0; kk < 32; kk += 16) {
            uint32_t ah[4][4], al[4][4];
            #pragma unroll
            for (int mt = 0; mt < 4; mt++) {
                ldsm_x4(ah[mt], smem_u32(Ahs + (wm*64 + mt*16 + a_r)*LDKB + kk + a_c));
                ldsm_x4(al[mt], smem_u32(Als + (wm*64 + mt*16 + a_r)*LDKB + kk + a_c));
            }
            #pragma unroll
            for (int p = 0; p < 4; p++) {          // n-tile pairs: nt = 2p, 2p+1
                uint32_t bh4[4], bl4[4];
                ldsm_x4(bh4, smem_u32(Bhs + (wn*64 + p*16 + b4_r)*LDKB + kk + b4_c));
                ldsm_x4(bl4, smem_u32(Bls + (wn*64 + p*16 + b4_r)*LDKB + kk + b4_c));
                #pragma unroll
                for (int mt = 0; mt < 4; mt++) {
                    mma16816(acc[mt][2*p],   ah[mt], bh4[0], bh4[1]);
                    mma16816(acc[mt][2*p],   ah[mt], bl4[0], bl4[1]);
                    mma16816(acc[mt][2*p],   al[mt], bh4[0], bh4[1]);
                    mma16816(acc[mt][2*p+1], ah[mt], bh4[2], bh4[3]);
                    mma16816(acc[mt][2*p+1], ah[mt], bl4[2], bl4[3]);
                    mma16816(acc[mt][2*p+1], al[mt], bh4[2], bh4[3]);
                }
            }
        }
    }
}

// QKV projection
__global__ __launch_bounds__(128) void qkv_gemm_tc(int)
{
    extern __shared__ bf16 gsm[];

    const int which = blockIdx.z;
    const bf16* Bhg = (which == 0) ? g_wqh : (which == 1) ? g_wkh : g_wvh;
    const bf16* Blg = (which == 0) ? g_wql : (which == 1) ? g_wkl : g_wvl;

    const int m0 = blockIdx.y * 128;
    const int n0 = blockIdx.x * 128;

    float acc[4][8][4];
    #pragma unroll
    for (int i = 0; i < 4; i++)
        #pragma unroll
        for (int j = 0; j < 8; j++)
            #pragma unroll
            for (int r = 0; r < 4; r++) acc[i][j][r] = 0.0f;

    gemm_mainloop(g_xh, g_xl, Bhg, Blg, m0, n0, gsm, acc);

    const int tid  = threadIdx.x;
    const int lane = tid & 31;
    const int warp = tid >> 5;
    const int wm = warp >> 1, wn = warp & 1;
    const int g = lane >> 2, t = lane & 3;
    const int bb = m0 >> 11;
    const int mloc = m0 & 2047;

    if (which == 2) {
        float* Cs = (float*)gsm;    // 128 x 133 fp32 = 68096 B < 81920
        __syncthreads();
        #pragma unroll
        for (int mt = 0; mt < 4; mt++) {
            #pragma unroll
            for (int nt = 0; nt < 8; nt++) {
                int row = wm*64 + mt*16 + g;
                int col = wn*64 + nt*8 + 2*t;
                Cs[row*133 + col]       = acc[mt][nt][0];
                Cs[row*133 + col + 1]   = acc[mt][nt][1];
                Cs[(row+8)*133 + col]   = acc[mt][nt][2];
                Cs[(row+8)*133 + col+1] = acc[mt][nt][3];
            }
        }
        __syncthreads();
        for (int idx = tid; idx < 2048; idx += 128) {
            int el  = idx >> 4;
            int tch = (idx & 15) * 8;
            bf16 hv8[8], lv8[8];
            #pragma unroll
            for (int q = 0; q < 8; q++) {
                float v = Cs[(tch + q)*133 + el];
                bf16 hv = __float2bfloat16(v);
                hv8[q] = hv;
                lv8[q] = __float2bfloat16(v - __bfloat162float(hv));
            }
            int col = n0 + el;
            int hh = col >> 6, e = col & 63;
            size_t rb = (((size_t)bb*HH + hh)*HDD + e)*TT + mloc + tch;
            *(uint4*)&g_vth[rb] = *(uint4*)hv8;
            *(uint4*)&g_vtl[rb] = *(uint4*)lv8;
        }
    } else {
        float sc = (which == 0) ? 0.125f : 1.0f;
        bf16* hp = (which == 0) ? g_qh : g_kh;
        bf16* lp = (which == 0) ? g_ql : g_kl;
        #pragma unroll
        for (int mt = 0; mt < 4; mt++) {
            #pragma unroll
            for (int nt = 0; nt < 8; nt++) {
                int row = mloc + wm*64 + mt*16 + g;
                int col = n0 + wn*64 + nt*8 + 2*t;
                int hh = col >> 6, e = col & 63;
                uint32_t hv, lv;
                size_t a0 = (((size_t)bb*HH + hh)*TT + row)*HDD + e;
                size_t a1 = (((size_t)bb*HH + hh)*TT + row + 8)*HDD + e;
                split_pack(acc[mt][nt][0]*sc, acc[mt][nt][1]*sc, hv, lv);
                *(uint32_t*)&hp[a0] = hv;
                *(uint32_t*)&lp[a0] = lv;
                split_pack(acc[mt][nt][2]*sc, acc[mt][nt][3]*sc, hv, lv);
                *(uint32_t*)&hp[a1] = hv;
                *(uint32_t*)&lp[a1] = lv;
            }
        }
    }
}

// Output projection
__global__ __launch_bounds__(128) void out_gemm_tc(
    const float* __restrict__ bo, float* __restrict__ outp)
{
    extern __shared__ bf16 gsm[];

    const int m0 = blockIdx.y * 128;
    const int n0 = blockIdx.x * 128;

    float acc[4][8][4];
    #pragma unroll
    for (int i = 0; i < 4; i++)
        #pragma unroll
        for (int j = 0; j < 8; j++)
            #pragma unroll
            for (int r = 0; r < 4; r++) acc[i][j][r] = 0.0f;

    gemm_mainloop(g_aoh, g_aol, g_woh, g_wol, m0, n0, gsm, acc);

    const int lane = threadIdx.x & 31;
    const int warp = threadIdx.x >> 5;
    const int wm = warp >> 1, wn = warp & 1;
    const int g = lane >> 2, t = lane & 3;

    #pragma unroll
    for (int mt = 0; mt < 4; mt++) {
        #pragma unroll
        for (int nt = 0; nt < 8; nt++) {
            int row = m0 + wm*64 + mt*16 + g;
            int col = n0 + wn*64 + nt*8 + 2*t;
            float bx = bo[col], by = bo[col+1];
            float2 v01 = make_float2(acc[mt][nt][0] + bx, acc[mt][nt][1] + by);
            float2 v23 = make_float2(acc[mt][nt][2] + bx, acc[mt][nt][3] + by);
            *(float2*)&outp[(size_t)row*DD + col]     = v01;
            *(float2*)&outp[(size_t)(row+8)*DD + col] = v23;
        }
    }
}

// ============================================================================
// Flash attention: 128 threads (4 warps), q-tile 128, warp owns 32 rows
// (2 m-frags). K/V double-buffered cp.async; ldsm_x4 pairs for K and V.
// ============================================================================
#define AQS 72
#define KVARR (64*AQS)
#define ATTN_Q_BYTES (2*128*AQS*2)                      // 36864
#define ATTN_KV_BYTES (2*4*KVARR*2)                     // 73728
#define ATTN_SMEM_BYTES (ATTN_Q_BYTES + ATTN_KV_BYTES)  // 110592

__device__ __forceinline__ void attn_load_kv(
    const bf16* khb, const bf16* klb, const bf16* vhb, const bf16* vlb,
    int j0, bf16* kvbase, int tid)
{
    bf16* Kh = kvbase;
    bf16* Kl = kvbase + KVARR;
    bf16* Vh = kvbase + 2*KVARR;
    bf16* Vl = kvbase + 3*KVARR;
    #pragma unroll
    for (int s = 0; s < 4; s++) {
        int idx = tid + s*128;
        int r = idx >> 3;
        int c = (idx & 7) * 8;
        cp16(smem_u32(Kh + r*AQS + c), khb + (size_t)(j0 + r)*HDD + c);
        cp16(smem_u32(Kl + r*AQS + c), klb + (size_t)(j0 + r)*HDD + c);
        cp16(smem_u32(Vh + r*AQS + c), vhb + (size_t)r*TT + j0 + c);
        cp16(smem_u32(Vl + r*AQS + c), vlb + (size_t)r*TT + j0 + c);
    }
}

__global__ __launch_bounds__(128) void attn_tc()
{
    extern __shared__ bf16 asmem[];
    bf16* Qh = asmem;
    bf16* Ql = Qh + 128*AQS;
    bf16* KV = Ql + 128*AQS;

    const int bh = blockIdx.y;
    const int hh = bh & (HH-1);
    const int b  = bh >> 4;
    const int qt = gridDim.x - 1 - blockIdx.x;
    const int q0 = qt * 128;
    const int njt = 2*qt + 2;

    const int tid  = threadIdx.x;
    const int lane = tid & 31;
    const int w    = tid >> 5;      // 0..3; warp rows q0 + w*32 .. +31
    const int g    = lane >> 2;
    const int t    = lane & 3;

    const bf16* __restrict__ qhb = g_qh  + (size_t)bh * TT * HDD;
    const bf16* __restrict__ qlb = g_ql  + (size_t)bh * TT * HDD;
    const bf16* __restrict__ khb = g_kh  + (size_t)bh * TT * HDD;
    const bf16* __restrict__ klb = g_kl  + (size_t)bh * TT * HDD;
    const bf16* __restrict__ vhb = g_vth + (size_t)bh * HDD * TT;
    const bf16* __restrict__ vlb = g_vtl + (size_t)bh * HDD * TT;

    for (int idx = tid; idx < 1024; idx += 128) {
        int r = idx >> 3;
        int c = (idx & 7) * 8;
        *(uint4*)(Qh + r*AQS + c) = *(const uint4*)(qhb + (size_t)(q0 + r)*HDD + c);
        *(uint4*)(Ql + r*AQS + c) = *(const uint4*)(qlb + (size_t)(q0 + r)*HDD + c);
    }

    attn_load_kv(khb, klb, vhb, vlb, 0, KV, tid); CP_COMMIT();

    float o[2][8][4];
    float m[4], l[4];   // [mf*2 + half]
    #pragma unroll
    for (int mf = 0; mf < 2; mf++)
        #pragma unroll
        for (int et = 0; et < 8; et++)
            #pragma unroll
            for (int r = 0; r < 4; r++) o[mf][et][r] = 0.0f;
    #pragma unroll
    for (int i = 0; i < 4; i++) { m[i] = -1e30f; l[i] = 0.0f; }

    const int a_r  = lane & 15;
    const int a_c  = (lane >> 4) << 3;
    const int b4_r = ((lane >> 4) << 3) + (lane & 7);
    const int b4_c = ((lane >> 3) & 1) << 3;

    const int r0w = q0 + w*32;

    for (int jt = 0; jt < njt; jt++) {
        const int j0 = jt * 64;

        __syncthreads();
        if (jt + 1 < njt)
            attn_load_kv(khb, klb, vhb, vlb, (jt+1)*64, KV + ((jt+1)&1)*4*KVARR, tid);
        CP_COMMIT();
        cp_wait<1>();
        __syncthreads();

        if (j0 > r0w + 31) continue;   // fully masked for this warp

        bf16* Kh = KV + (jt&1)*4*KVARR;
        bf16* Kl = Kh + KVARR;
        bf16* Vh = Kl + KVARR;
        bf16* Vl = Vh + KVARR;

        // S = Q K^T : s[mf][nt][4]
        float s[2][8][4];
        #pragma unroll
        for (int mf = 0; mf < 2; mf++)
            #pragma unroll
            for (int nt = 0; nt < 8; nt++)
                #pragma unroll
                for (int r = 0; r < 4; r++) s[mf][nt][r] = 0.0f;

        #pragma unroll
        for (int kk = 0; kk < 4; kk++) {
            uint32_t qah[2][4], qal[2][4];
            #pragma unroll
            for (int mf = 0; mf < 2; mf++) {
                ldsm_x4(qah[mf], smem_u32(Qh + (w*32 + mf*16 + a_r)*AQS + kk*16 + a_c));
                ldsm_x4(qal[mf], smem_u32(Ql + (w*32 + mf*16 + a_r)*AQS + kk*16 + a_c));
            }
            #pragma unroll
            for (int p = 0; p < 4; p++) {
                uint32_t kh4[4], kl4[4];
                ldsm_x4(kh4, smem_u32(Kh + (p*16 + b4_r)*AQS + kk*16 + b4_c));
                ldsm_x4(kl4, smem_u32(Kl + (p*16 + b4_r)*AQS + kk*16 + b4_c));
                #pragma unroll
                for (int mf = 0; mf < 2; mf++) {
                    mma16816(s[mf][2*p],   qah[mf], kh4[0], kh4[1]);
                    mma16816(s[mf][2*p],   qah[mf], kl4[0], kl4[1]);
                    mma16816(s[mf][2*p],   qal[mf], kh4[0], kh4[1]);
                    mma16816(s[mf][2*p+1], qah[mf], kh4[2], kh4[3]);
                    mma16816(s[mf][2*p+1], qah[mf], kl4[2], kl4[3]);
                    mma16816(s[mf][2*p+1], qal[mf], kh4[2], kh4[3]);
                }
            }
        }

        // Causal mask
        if (j0 + 63 > r0w) {
            #pragma unroll
            for (int mf = 0; mf < 2; mf++) {
                int r0 = r0w + mf*16 + g;
                int r1 = r0 + 8;
                #pragma unroll
                for (int nt = 0; nt < 8; nt++) {
                    int c0 = j0 + nt*8 + 2*t;
                    if (c0     > r0) s[mf][nt][0] = -1e30f;
                    if (c0 + 1 > r0) s[mf][nt][1] = -1e30f;
                    if (c0     > r1) s[mf][nt][2] = -1e30f;
                    if (c0 + 1 > r1) s[mf][nt][3] = -1e30f;
                }
            }
        }

        // Online softmax per mf
        #pragma unroll
        for (int mf = 0; mf < 2; mf++) {
            float mx0 = -1e30f, mx1 = -1e30f;
            #pragma unroll
            for (int nt = 0; nt < 8; nt++) {
                mx0 = fmaxf(mx0, fmaxf(s[mf][nt][0], s[mf][nt][1]));
                mx1 = fmaxf(mx1, fmaxf(s[mf][nt][2], s[mf][nt][3]));
            }
            #pragma unroll
            for (int off = 1; off <= 2; off <<= 1) {
                mx0 = fmaxf(mx0, __shfl_xor_sync(0xffffffffu, mx0, off));
                mx1 = fmaxf(mx1, __shfl_xor_sync(0xffffffffu, mx1, off));
            }
            float mn0 = fmaxf(m[mf*2],   mx0);
            float mn1 = fmaxf(m[mf*2+1], mx1);
            float f0 = __expf(m[mf*2]   - mn0);
            float f1 = __expf(m[mf*2+1] - mn1);
            float rs0 = 0.0f, rs1 = 0.0f;
            #pragma unroll
            for (int nt = 0; nt < 8; nt++) {
                s[mf][nt][0] = __expf(s[mf][nt][0] - mn0);
                s[mf][nt][1] = __expf(s[mf][nt][1] - mn0);
                s[mf][nt][2] = __expf(s[mf][nt][2] - mn1);
                s[mf][nt][3] = __expf(s[mf][nt][3] - mn1);
                rs0 += s[mf][nt][0] + s[mf][nt][1];
                rs1 += s[mf][nt][2] + s[mf][nt][3];
            }
            #pragma unroll
            for (int off = 1; off <= 2; off <<= 1) {
                rs0 += __shfl_xor_sync(0xffffffffu, rs0, off);
                rs1 += __shfl_xor_sync(0xffffffffu, rs1, off);
            }
            l[mf*2]   = l[mf*2]   * f0 + rs0;
            l[mf*2+1] = l[mf*2+1] * f1 + rs1;
            m[mf*2]   = mn0;
            m[mf*2+1] = mn1;
            #pragma unroll
            for (int et = 0; et < 8; et++) {
                o[mf][et][0] *= f0; o[mf][et][1] *= f0;
                o[mf][et][2] *= f1; o[mf][et][3] *= f1;
            }
        }

        // P*V — V pairs loaded once per kt, shared across both mf
        #pragma unroll
        for (int kt = 0; kt < 4; kt++) {
            uint32_t pah[2][4], pal[2][4];
            #pragma unroll
            for (int mf = 0; mf < 2; mf++) {
                split_pack(s[mf][2*kt][0],   s[mf][2*kt][1],   pah[mf][0], pal[mf][0]);
                split_pack(s[mf][2*kt][2],   s[mf][2*kt][3],   pah[mf][1], pal[mf][1]);
                split_pack(s[mf][2*kt+1][0], s[mf][2*kt+1][1], pah[mf][2], pal[mf][2]);
                split_pack(s[mf][2*kt+1][2], s[mf][2*kt+1][3], pah[mf][3], pal[mf][3]);
            }
            #pragma unroll
            for (int pe = 0; pe < 4; pe++) {
                uint32_t vh4[4], vl4[4];
                ldsm_x4(vh4, smem_u32(Vh + (pe*16 + b4_r)*AQS + kt*16 + b4_c));
                ldsm_x4(vl4, smem_u32(Vl + (pe*16 + b4_r)*AQS + kt*16 + b4_c));
                #pragma unroll
                for (int mf = 0; mf < 2; mf++) {
                    mma16816(o[mf][2*pe],   pah[mf], vh4[0], vh4[1]);
                    mma16816(o[mf][2*pe],   pah[mf], vl4[0], vl4[1]);
                    mma16816(o[mf][2*pe],   pal[mf], vh4[0], vh4[1]);
                    mma16816(o[mf][2*pe+1], pah[mf], vh4[2], vh4[3]);
                    mma16816(o[mf][2*pe+1], pah[mf], vl4[2], vl4[3]);
                    mma16816(o[mf][2*pe+1], pal[mf], vh4[2], vh4[3]);
                }
            }
        }
    }

    // Epilogue
    #pragma unroll
    for (int mf = 0; mf < 2; mf++) {
        float inv0 = 1.0f / l[mf*2];
        float inv1 = 1.0f / l[mf*2+1];
        int tq = q0 + w*32 + mf*16 + g;
        #pragma unroll
        for (int et = 0; et < 8; et++) {
            int col = hh*HDD + et*8 + 2*t;
            uint32_t hv, lv;
            size_t a0 = ((size_t)b*TT + tq)*DD + col;
            size_t a1 = ((size_t)b*TT + tq + 8)*DD + col;
            split_pack(o[mf][et][0]*inv0, o[mf][et][1]*inv0, hv, lv);
            *(uint32_t*)&g_aoh[a0] = hv;
            *(uint32_t*)&g_aol[a0] = lv;
            split_pack(o[mf][et][2]*inv1, o[mf][et][3]*inv1, hv, lv);
            *(uint32_t*)&g_aoh[a1] = hv;
            *(uint32_t*)&g_aol[a1] = lv;
        }
    }
}

// ============================================================================
// Launch
// ============================================================================
extern "C" void kernel_launch(void* const* d_in, const int* in_sizes, int n_in,
                              void* d_out, int out_size)
{
    const float* x  = (const float*)d_in[0];
    const float* Wq = (const float*)d_in[1];
    const float* Wk = (const float*)d_in[2];
    const float* Wv = (const float*)d_in[3];
    const float* Wo = (const float*)d_in[4];
    const float* bo = (const float*)d_in[5];
    float* out = (float*)d_out;

    cudaFuncSetAttribute(qkv_gemm_tc, cudaFuncAttributeMaxDynamicSharedMemorySize,
                         GEMM_SMEM_BYTES);
    cudaFuncSetAttribute(out_gemm_tc, cudaFuncAttributeMaxDynamicSharedMemorySize,
                         GEMM_SMEM_BYTES);
    cudaFuncSetAttribute(attn_tc, cudaFuncAttributeMaxDynamicSharedMemorySize,
                         ATTN_SMEM_BYTES);

    int nx = MTOT*DD/4, nw = DD*DD/4;
    convert_x_k<<<nx/256, 256>>>((const float4*)x);
    convert_w_k<<<dim3(nw/256, 4), 256>>>((const float4*)Wq, (const float4*)Wk,
                                          (const float4*)Wv, (const float4*)Wo);

    qkv_gemm_tc<<<dim3(DD/128, MTOT/128, 3), 128, GEMM_SMEM_BYTES>>>(0);
    attn_tc<<<dim3(TT/128, BB*HH), 128, ATTN_SMEM_BYTES>>>();
    out_gemm_tc<<<dim3(DD/128, MTOT/128), 128, GEMM_SMEM_BYTES>>>(bo, out);
}

// round 10
// speedup vs baseline: 3.6602x; 1.0545x over previous
#include <cuda_runtime.h>
#include <cuda_bf16.h>
#include <cuda_fp16.h>
#include <cstdint>
#include <math.h>

#define BB   4
#define TT   2048
#define DD   1024
#define HH   16
#define HDD  64
#define MTOT (BB*TT)   // 8192

typedef __nv_bfloat16  bf16;
typedef __nv_bfloat162 bf162;

// ---- split globals ----
__device__ bf16 g_xh [(size_t)MTOT*DD],  g_xl [(size_t)MTOT*DD];
__device__ bf16 g_wqh[(size_t)DD*DD],    g_wql[(size_t)DD*DD];
__device__ bf16 g_wkh[(size_t)DD*DD],    g_wkl[(size_t)DD*DD];
__device__ bf16 g_wvh[(size_t)DD*DD],    g_wvl[(size_t)DD*DD];
__device__ bf16 g_woh[(size_t)DD*DD],    g_wol[(size_t)DD*DD];
__device__ bf16 g_qh [(size_t)MTOT*DD],  g_ql [(size_t)MTOT*DD];   // [B,H,T,HD] (prescaled log2e/8)
__device__ bf16 g_kh [(size_t)MTOT*DD],  g_kl [(size_t)MTOT*DD];   // [B,H,T,HD]
__device__ __half g_vth[(size_t)MTOT*DD], g_vtl[(size_t)MTOT*DD];  // [B,H,HD,T] fp16 hi/lo
__device__ bf16 g_aoh[(size_t)MTOT*DD],  g_aol[(size_t)MTOT*DD];   // [B,T,D]

// ============================================================================
// Helpers
// ============================================================================
__device__ __forceinline__ uint32_t smem_u32(const void* p) {
    return (uint32_t)__cvta_generic_to_shared(p);
}
__device__ __forceinline__ void ldsm_x4(uint32_t r[4], uint32_t addr) {
    asm volatile("ldmatrix.sync.aligned.m8n8.x4.shared.b16 {%0,%1,%2,%3}, [%4];"
                 : "=r"(r[0]), "=r"(r[1]), "=r"(r[2]), "=r"(r[3]) : "r"(addr));
}
__device__ __forceinline__ void mma16816(float d[4], const uint32_t a[4], const uint32_t b0, const uint32_t b1) {
    asm volatile(
        "mma.sync.aligned.m16n8k16.row.col.f32.bf16.bf16.f32 "
        "{%0,%1,%2,%3}, {%4,%5,%6,%7}, {%8,%9}, {%0,%1,%2,%3};"
        : "+f"(d[0]), "+f"(d[1]), "+f"(d[2]), "+f"(d[3])
        : "r"(a[0]), "r"(a[1]), "r"(a[2]), "r"(a[3]), "r"(b0), "r"(b1));
}
__device__ __forceinline__ void mma16816h(float d[4], const uint32_t a[4], const uint32_t b0, const uint32_t b1) {
    asm volatile(
        "mma.sync.aligned.m16n8k16.row.col.f32.f16.f16.f32 "
        "{%0,%1,%2,%3}, {%4,%5,%6,%7}, {%8,%9}, {%0,%1,%2,%3};"
        : "+f"(d[0]), "+f"(d[1]), "+f"(d[2]), "+f"(d[3])
        : "r"(a[0]), "r"(a[1]), "r"(a[2]), "r"(a[3]), "r"(b0), "r"(b1));
}
__device__ __forceinline__ void split2(float x, float y, bf162& h, bf162& l) {
    bf16 hx = __float2bfloat16(x);
    bf16 hy = __float2bfloat16(y);
    h = __halves2bfloat162(hx, hy);
    l = __halves2bfloat162(__float2bfloat16(x - __bfloat162float(hx)),
                           __float2bfloat16(y - __bfloat162float(hy)));
}
// packed split: bf16(x) in lo16, bf16(y) in hi16; residuals via exact shifts
__device__ __forceinline__ void split_pack(float x, float y, uint32_t& h, uint32_t& l) {
    uint32_t hp;
    asm("cvt.rn.bf16x2.f32 %0, %1, %2;" : "=r"(hp) : "f"(y), "f"(x));
    float xh = __uint_as_float(hp << 16);
    float yh = __uint_as_float(hp & 0xFFFF0000u);
    uint32_t lp;
    asm("cvt.rn.bf16x2.f32 %0, %1, %2;" : "=r"(lp) : "f"(y - yh), "f"(x - xh));
    h = hp; l = lp;
}
__device__ __forceinline__ uint32_t f16pack(float x, float y) {
    uint32_t r;
    asm("cvt.rn.f16x2.f32 %0, %1, %2;" : "=r"(r) : "f"(y), "f"(x));
    return r;
}
__device__ __forceinline__ float ex2f(float x) {
    float r;
    asm("ex2.approx.f32 %0, %1;" : "=f"(r) : "f"(x));
    return r;
}
__device__ __forceinline__ void cp16(uint32_t s, const void* g) {
    asm volatile("cp.async.ca.shared.global [%0], [%1], 16;\n" :: "r"(s), "l"(g));
}
#define CP_COMMIT() asm volatile("cp.async.commit_group;\n" ::: "memory")
template<int N> __device__ __forceinline__ void cp_wait() {
    asm volatile("cp.async.wait_group %0;\n" :: "n"(N) : "memory");
}

// ============================================================================
// Convert kernels
// ============================================================================
__global__ __launch_bounds__(256) void convert_x_k(const float4* __restrict__ src)
{
    int i = blockIdx.x * 256 + threadIdx.x;
    float4 v = src[i];
    bf162 h0, l0, h1, l1;
    split2(v.x, v.y, h0, l0);
    split2(v.z, v.w, h1, l1);
    *(bf162*)(g_xh + (size_t)i*4)     = h0;
    *(bf162*)(g_xh + (size_t)i*4 + 2) = h1;
    *(bf162*)(g_xl + (size_t)i*4)     = l0;
    *(bf162*)(g_xl + (size_t)i*4 + 2) = l1;
}
__global__ __launch_bounds__(256) void convert_w_k(
    const float4* __restrict__ wq, const float4* __restrict__ wk,
    const float4* __restrict__ wv, const float4* __restrict__ wo)
{
    int which = blockIdx.y;
    const float4* src = (which == 0) ? wq : (which == 1) ? wk : (which == 2) ? wv : wo;
    bf16* ho = (which == 0) ? g_wqh : (which == 1) ? g_wkh : (which == 2) ? g_wvh : g_woh;
    bf16* lo = (which == 0) ? g_wql : (which == 1) ? g_wkl : (which == 2) ? g_wvl : g_wol;
    int i = blockIdx.x * 256 + threadIdx.x;
    float4 v = src[i];
    bf162 h0, l0, h1, l1;
    split2(v.x, v.y, h0, l0);
    split2(v.z, v.w, h1, l1);
    *(bf162*)(ho + (size_t)i*4)     = h0;
    *(bf162*)(ho + (size_t)i*4 + 2) = h1;
    *(bf162*)(lo + (size_t)i*4)     = l0;
    *(bf162*)(lo + (size_t)i*4 + 2) = l1;
}

// ============================================================================
// GEMM: CTA 128x128, 128 threads (4 warps, 2m x 2n), warp tile 64x64.
// 2-stage cp.async pipeline. (R8 structure, unchanged numerics)
// ============================================================================
#define LDKB 40
#define STG_ARR (128*LDKB)
#define STG4    (4*STG_ARR)
#define GEMM_SMEM_BYTES (2*STG4*2)  // 81920

__device__ __forceinline__ void gemm_load_stage(
    const bf16* __restrict__ Ahg, const bf16* __restrict__ Alg,
    const bf16* __restrict__ Bhg, const bf16* __restrict__ Blg,
    int m0, int n0, int k0, bf16* base, int tid)
{
    const bf16* gp[4] = {Ahg, Alg, Bhg, Blg};
    #pragma unroll
    for (int a = 0; a < 4; a++) {
        int row0 = (a < 2) ? m0 : n0;
        bf16* sb = base + a*STG_ARR;
        #pragma unroll
        for (int s = 0; s < 4; s++) {
            int idx = tid + s*128;
            int r = idx >> 2;
            int c = (idx & 3) * 8;
            cp16(smem_u32(sb + r*LDKB + c), gp[a] + (size_t)(row0 + r)*DD + k0 + c);
        }
    }
}

__device__ __forceinline__ void gemm_mainloop(
    const bf16* __restrict__ Ahg, const bf16* __restrict__ Alg,
    const bf16* __restrict__ Bhg, const bf16* __restrict__ Blg,
    int m0, int n0, bf16* smem, float acc[4][8][4])
{
    const int tid  = threadIdx.x;
    const int lane = tid & 31;
    const int warp = tid >> 5;
    const int wm = warp >> 1;
    const int wn = warp & 1;

    const int a_r  = lane & 15;
    const int a_c  = (lane >> 4) << 3;
    const int b4_r = ((lane >> 4) << 3) + (lane & 7);
    const int b4_c = ((lane >> 3) & 1) << 3;

    const int NST = DD / 32;

    gemm_load_stage(Ahg, Alg, Bhg, Blg, m0, n0, 0, smem, tid); CP_COMMIT();

    for (int i = 0; i < NST; i++) {
        __syncthreads();
        if (i + 1 < NST)
            gemm_load_stage(Ahg, Alg, Bhg, Blg, m0, n0, (i+1)*32,
                            smem + ((i+1)&1)*STG4, tid);
        CP_COMMIT();
        cp_wait<1>();
        __syncthreads();

        bf16* Ahs = smem + (i&1)*STG4;
        bf16* Als = Ahs + STG_ARR;
        bf16* Bhs = Als + STG_ARR;
        bf16* Bls = Bhs + STG_ARR;

        #pragma unroll
        for (int kk = 0; kk < 32; kk += 16) {
            uint32_t ah[4][4], al[4][4];
            #pragma unroll
            for (int mt = 0; mt < 4; mt++) {
                ldsm_x4(ah[mt], smem_u32(Ahs + (wm*64 + mt*16 + a_r)*LDKB + kk + a_c));
                ldsm_x4(al[mt], smem_u32(Als + (wm*64 + mt*16 + a_r)*LDKB + kk + a_c));
            }
            #pragma unroll
            for (int p = 0; p < 4; p++) {
                uint32_t bh4[4], bl4[4];
                ldsm_x4(bh4, smem_u32(Bhs + (wn*64 + p*16 + b4_r)*LDKB + kk + b4_c));
                ldsm_x4(bl4, smem_u32(Bls + (wn*64 + p*16 + b4_r)*LDKB + kk + b4_c));
                #pragma unroll
                for (int mt = 0; mt < 4; mt++) {
                    mma16816(acc[mt][2*p],   ah[mt], bh4[0], bh4[1]);
                    mma16816(acc[mt][2*p],   ah[mt], bl4[0], bl4[1]);
                    mma16816(acc[mt][2*p],   al[mt], bh4[0], bh4[1]);
                    mma16816(acc[mt][2*p+1], ah[mt], bh4[2], bh4[3]);
                    mma16816(acc[mt][2*p+1], ah[mt], bl4[2], bl4[3]);
                    mma16816(acc[mt][2*p+1], al[mt], bh4[2], bh4[3]);
                }
            }
        }
    }
}

// QKV projection
__global__ __launch_bounds__(128) void qkv_gemm_tc(int)
{
    extern __shared__ bf16 gsm[];

    const int which = blockIdx.z;
    const bf16* Bhg = (which == 0) ? g_wqh : (which == 1) ? g_wkh : g_wvh;
    const bf16* Blg = (which == 0) ? g_wql : (which == 1) ? g_wkl : g_wvl;

    const int m0 = blockIdx.y * 128;
    const int n0 = blockIdx.x * 128;

    float acc[4][8][4];
    #pragma unroll
    for (int i = 0; i < 4; i++)
        #pragma unroll
        for (int j = 0; j < 8; j++)
            #pragma unroll
            for (int r = 0; r < 4; r++) acc[i][j][r] = 0.0f;

    gemm_mainloop(g_xh, g_xl, Bhg, Blg, m0, n0, gsm, acc);

    const int tid  = threadIdx.x;
    const int lane = tid & 31;
    const int warp = tid >> 5;
    const int wm = warp >> 1, wn = warp & 1;
    const int g = lane >> 2, t = lane & 3;
    const int bb = m0 >> 11;
    const int mloc = m0 & 2047;

    if (which == 2) {
        // V: stage fp32 tile, write V^T as fp16 hi/lo coalesced
        float* Cs = (float*)gsm;
        __syncthreads();
        #pragma unroll
        for (int mt = 0; mt < 4; mt++) {
            #pragma unroll
            for (int nt = 0; nt < 8; nt++) {
                int row = wm*64 + mt*16 + g;
                int col = wn*64 + nt*8 + 2*t;
                Cs[row*133 + col]       = acc[mt][nt][0];
                Cs[row*133 + col + 1]   = acc[mt][nt][1];
                Cs[(row+8)*133 + col]   = acc[mt][nt][2];
                Cs[(row+8)*133 + col+1] = acc[mt][nt][3];
            }
        }
        __syncthreads();
        for (int idx = tid; idx < 2048; idx += 128) {
            int el  = idx >> 4;
            int tch = (idx & 15) * 8;
            __half hv8[8], lv8[8];
            #pragma unroll
            for (int q = 0; q < 8; q++) {
                float v = Cs[(tch + q)*133 + el];
                __half hv = __float2half_rn(v);
                hv8[q] = hv;
                lv8[q] = __float2half_rn(v - __half2float(hv));
            }
            int col = n0 + el;
            int hh = col >> 6, e = col & 63;
            size_t rb = (((size_t)bb*HH + hh)*HDD + e)*TT + mloc + tch;
            *(uint4*)&g_vth[rb] = *(uint4*)hv8;
            *(uint4*)&g_vtl[rb] = *(uint4*)lv8;
        }
    } else {
        // Q prescale folds 1/8 AND log2e (softmax done in log2 domain)
        float sc = (which == 0) ? (0.125f * 1.4426950408889634f) : 1.0f;
        bf16* hp = (which == 0) ? g_qh : g_kh;
        bf16* lp = (which == 0) ? g_ql : g_kl;
        #pragma unroll
        for (int mt = 0; mt < 4; mt++) {
            #pragma unroll
            for (int nt = 0; nt < 8; nt++) {
                int row = mloc + wm*64 + mt*16 + g;
                int col = n0 + wn*64 + nt*8 + 2*t;
                int hh = col >> 6, e = col & 63;
                uint32_t hv, lv;
                size_t a0 = (((size_t)bb*HH + hh)*TT + row)*HDD + e;
                size_t a1 = (((size_t)bb*HH + hh)*TT + row + 8)*HDD + e;
                split_pack(acc[mt][nt][0]*sc, acc[mt][nt][1]*sc, hv, lv);
                *(uint32_t*)&hp[a0] = hv;
                *(uint32_t*)&lp[a0] = lv;
                split_pack(acc[mt][nt][2]*sc, acc[mt][nt][3]*sc, hv, lv);
                *(uint32_t*)&hp[a1] = hv;
                *(uint32_t*)&lp[a1] = lv;
            }
        }
    }
}

// Output projection
__global__ __launch_bounds__(128) void out_gemm_tc(
    const float* __restrict__ bo, float* __restrict__ outp)
{
    extern __shared__ bf16 gsm[];

    const int m0 = blockIdx.y * 128;
    const int n0 = blockIdx.x * 128;

    float acc[4][8][4];
    #pragma unroll
    for (int i = 0; i < 4; i++)
        #pragma unroll
        for (int j = 0; j < 8; j++)
            #pragma unroll
            for (int r = 0; r < 4; r++) acc[i][j][r] = 0.0f;

    gemm_mainloop(g_aoh, g_aol, g_woh, g_wol, m0, n0, gsm, acc);

    const int lane = threadIdx.x & 31;
    const int warp = threadIdx.x >> 5;
    const int wm = warp >> 1, wn = warp & 1;
    const int g = lane >> 2, t = lane & 3;

    #pragma unroll
    for (int mt = 0; mt < 4; mt++) {
        #pragma unroll
        for (int nt = 0; nt < 8; nt++) {
            int row = m0 + wm*64 + mt*16 + g;
            int col = n0 + wn*64 + nt*8 + 2*t;
            float bx = bo[col], by = bo[col+1];
            float2 v01 = make_float2(acc[mt][nt][0] + bx, acc[mt][nt][1] + by);
            float2 v23 = make_float2(acc[mt][nt][2] + bx, acc[mt][nt][3] + by);
            *(float2*)&outp[(size_t)row*DD + col]     = v01;
            *(float2*)&outp[(size_t)(row+8)*DD + col] = v23;
        }
    }
}

// ============================================================================
// Flash attention: 128 threads (4 warps x 32 rows), q-tile 128, K/V tiles 64,
// double-buffered cp.async. QK: bf16 3-term. PV: fp16 2-term (P single-fp16).
// Softmax in log2 domain (Q prescaled by log2e/8).
// ============================================================================
#define AQS 72
#define KVARR (64*AQS)
#define ATTN_Q_BYTES (2*128*AQS*2)
#define ATTN_KV_BYTES (2*4*KVARR*2)
#define ATTN_SMEM_BYTES (ATTN_Q_BYTES + ATTN_KV_BYTES)  // 110592

__device__ __forceinline__ void attn_load_kv(
    const bf16* khb, const bf16* klb, const __half* vhb, const __half* vlb,
    int j0, bf16* kvbase, int tid)
{
    bf16* Kh = kvbase;
    bf16* Kl = kvbase + KVARR;
    bf16* Vh = kvbase + 2*KVARR;
    bf16* Vl = kvbase + 3*KVARR;
    #pragma unroll
    for (int s = 0; s < 4; s++) {
        int idx = tid + s*128;
        int r = idx >> 3;
        int c = (idx & 7) * 8;
        cp16(smem_u32(Kh + r*AQS + c), khb + (size_t)(j0 + r)*HDD + c);
        cp16(smem_u32(Kl + r*AQS + c), klb + (size_t)(j0 + r)*HDD + c);
        cp16(smem_u32(Vh + r*AQS + c), vhb + (size_t)r*TT + j0 + c);
        cp16(smem_u32(Vl + r*AQS + c), vlb + (size_t)r*TT + j0 + c);
    }
}

__global__ __launch_bounds__(128) void attn_tc()
{
    extern __shared__ bf16 asmem[];
    bf16* Qh = asmem;
    bf16* Ql = Qh + 128*AQS;
    bf16* KV = Ql + 128*AQS;

    const int bh = blockIdx.y;
    const int hh = bh & (HH-1);
    const int b  = bh >> 4;
    const int qt = gridDim.x - 1 - blockIdx.x;
    const int q0 = qt * 128;
    const int njt = 2*qt + 2;

    const int tid  = threadIdx.x;
    const int lane = tid & 31;
    const int w    = tid >> 5;
    const int g    = lane >> 2;
    const int t    = lane & 3;

    const bf16* __restrict__ qhb = g_qh  + (size_t)bh * TT * HDD;
    const bf16* __restrict__ qlb = g_ql  + (size_t)bh * TT * HDD;
    const bf16* __restrict__ khb = g_kh  + (size_t)bh * TT * HDD;
    const bf16* __restrict__ klb = g_kl  + (size_t)bh * TT * HDD;
    const __half* __restrict__ vhb = g_vth + (size_t)bh * HDD * TT;
    const __half* __restrict__ vlb = g_vtl + (size_t)bh * HDD * TT;

    for (int idx = tid; idx < 1024; idx += 128) {
        int r = idx >> 3;
        int c = (idx & 7) * 8;
        *(uint4*)(Qh + r*AQS + c) = *(const uint4*)(qhb + (size_t)(q0 + r)*HDD + c);
        *(uint4*)(Ql + r*AQS + c) = *(const uint4*)(qlb + (size_t)(q0 + r)*HDD + c);
    }

    attn_load_kv(khb, klb, vhb, vlb, 0, KV, tid); CP_COMMIT();

    float o[2][8][4];
    float m[4], l[4];
    #pragma unroll
    for (int mf = 0; mf < 2; mf++)
        #pragma unroll
        for (int et = 0; et < 8; et++)
            #pragma unroll
            for (int r = 0; r < 4; r++) o[mf][et][r] = 0.0f;
    #pragma unroll
    for (int i = 0; i < 4; i++) { m[i] = -1e30f; l[i] = 0.0f; }

    const int a_r  = lane & 15;
    const int a_c  = (lane >> 4) << 3;
    const int b4_r = ((lane >> 4) << 3) + (lane & 7);
    const int b4_c = ((lane >> 3) & 1) << 3;

    const int r0w = q0 + w*32;

    for (int jt = 0; jt < njt; jt++) {
        const int j0 = jt * 64;

        __syncthreads();
        if (jt + 1 < njt)
            attn_load_kv(khb, klb, vhb, vlb, (jt+1)*64, KV + ((jt+1)&1)*4*KVARR, tid);
        CP_COMMIT();
        cp_wait<1>();
        __syncthreads();

        if (j0 > r0w + 31) continue;

        bf16* Kh = KV + (jt&1)*4*KVARR;
        bf16* Kl = Kh + KVARR;
        bf16* Vh = Kl + KVARR;   // fp16 payload
        bf16* Vl = Vh + KVARR;   // fp16 payload

        // S = Q K^T  (bf16 3-term; scores in log2 domain)
        float s[2][8][4];
        #pragma unroll
        for (int mf = 0; mf < 2; mf++)
            #pragma unroll
            for (int nt = 0; nt < 8; nt++)
                #pragma unroll
                for (int r = 0; r < 4; r++) s[mf][nt][r] = 0.0f;

        #pragma unroll
        for (int kk = 0; kk < 4; kk++) {
            uint32_t qah[2][4], qal[2][4];
            #pragma unroll
            for (int mf = 0; mf < 2; mf++) {
                ldsm_x4(qah[mf], smem_u32(Qh + (w*32 + mf*16 + a_r)*AQS + kk*16 + a_c));
                ldsm_x4(qal[mf], smem_u32(Ql + (w*32 + mf*16 + a_r)*AQS + kk*16 + a_c));
            }
            #pragma unroll
            for (int p = 0; p < 4; p++) {
                uint32_t kh4[4], kl4[4];
                ldsm_x4(kh4, smem_u32(Kh + (p*16 + b4_r)*AQS + kk*16 + b4_c));
                ldsm_x4(kl4, smem_u32(Kl + (p*16 + b4_r)*AQS + kk*16 + b4_c));
                #pragma unroll
                for (int mf = 0; mf < 2; mf++) {
                    mma16816(s[mf][2*p],   qah[mf], kh4[0], kh4[1]);
                    mma16816(s[mf][2*p],   qah[mf], kl4[0], kl4[1]);
                    mma16816(s[mf][2*p],   qal[mf], kh4[0], kh4[1]);
                    mma16816(s[mf][2*p+1], qah[mf], kh4[2], kh4[3]);
                    mma16816(s[mf][2*p+1], qah[mf], kl4[2], kl4[3]);
                    mma16816(s[mf][2*p+1], qal[mf], kh4[2], kh4[3]);
                }
            }
        }

        if (j0 + 63 > r0w) {
            #pragma unroll
            for (int mf = 0; mf < 2; mf++) {
                int r0 = r0w + mf*16 + g;
                int r1 = r0 + 8;
                #pragma unroll
                for (int nt = 0; nt < 8; nt++) {
                    int c0 = j0 + nt*8 + 2*t;
                    if (c0     > r0) s[mf][nt][0] = -1e30f;
                    if (c0 + 1 > r0) s[mf][nt][1] = -1e30f;
                    if (c0     > r1) s[mf][nt][2] = -1e30f;
                    if (c0 + 1 > r1) s[mf][nt][3] = -1e30f;
                }
            }
        }

        // Online softmax (log2 domain: p = 2^(s - m))
        #pragma unroll
        for (int mf = 0; mf < 2; mf++) {
            float mx0 = -1e30f, mx1 = -1e30f;
            #pragma unroll
            for (int nt = 0; nt < 8; nt++) {
                mx0 = fmaxf(mx0, fmaxf(s[mf][nt][0], s[mf][nt][1]));
                mx1 = fmaxf(mx1, fmaxf(s[mf][nt][2], s[mf][nt][3]));
            }
            #pragma unroll
            for (int off = 1; off <= 2; off <<= 1) {
                mx0 = fmaxf(mx0, __shfl_xor_sync(0xffffffffu, mx0, off));
                mx1 = fmaxf(mx1, __shfl_xor_sync(0xffffffffu, mx1, off));
            }
            float mn0 = fmaxf(m[mf*2],   mx0);
            float mn1 = fmaxf(m[mf*2+1], mx1);
            float f0 = ex2f(m[mf*2]   - mn0);
            float f1 = ex2f(m[mf*2+1] - mn1);
            float rs0 = 0.0f, rs1 = 0.0f;
            #pragma unroll
            for (int nt = 0; nt < 8; nt++) {
                s[mf][nt][0] = ex2f(s[mf][nt][0] - mn0);
                s[mf][nt][1] = ex2f(s[mf][nt][1] - mn0);
                s[mf][nt][2] = ex2f(s[mf][nt][2] - mn1);
                s[mf][nt][3] = ex2f(s[mf][nt][3] - mn1);
                rs0 += s[mf][nt][0] + s[mf][nt][1];
                rs1 += s[mf][nt][2] + s[mf][nt][3];
            }
            #pragma unroll
            for (int off = 1; off <= 2; off <<= 1) {
                rs0 += __shfl_xor_sync(0xffffffffu, rs0, off);
                rs1 += __shfl_xor_sync(0xffffffffu, rs1, off);
            }
            l[mf*2]   = l[mf*2]   * f0 + rs0;
            l[mf*2+1] = l[mf*2+1] * f1 + rs1;
            m[mf*2]   = mn0;
            m[mf*2+1] = mn1;
            #pragma unroll
            for (int et = 0; et < 8; et++) {
                o[mf][et][0] *= f0; o[mf][et][1] *= f0;
                o[mf][et][2] *= f1; o[mf][et][3] *= f1;
            }
        }

        // P*V: P as single fp16, V fp16 hi/lo -> 4 MMAs per fragment pair
        #pragma unroll
        for (int kt = 0; kt < 4; kt++) {
            uint32_t pa[2][4];
            #pragma unroll
            for (int mf = 0; mf < 2; mf++) {
                pa[mf][0] = f16pack(s[mf][2*kt][0],   s[mf][2*kt][1]);
                pa[mf][1] = f16pack(s[mf][2*kt][2],   s[mf][2*kt][3]);
                pa[mf][2] = f16pack(s[mf][2*kt+1][0], s[mf][2*kt+1][1]);
                pa[mf][3] = f16pack(s[mf][2*kt+1][2], s[mf][2*kt+1][3]);
            }
            #pragma unroll
            for (int pe = 0; pe < 4; pe++) {
                uint32_t vh4[4], vl4[4];
                ldsm_x4(vh4, smem_u32(Vh + (pe*16 + b4_r)*AQS + kt*16 + b4_c));
                ldsm_x4(vl4, smem_u32(Vl + (pe*16 + b4_r)*AQS + kt*16 + b4_c));
                #pragma unroll
                for (int mf = 0; mf < 2; mf++) {
                    mma16816h(o[mf][2*pe],   pa[mf], vh4[0], vh4[1]);
                    mma16816h(o[mf][2*pe],   pa[mf], vl4[0], vl4[1]);
                    mma16816h(o[mf][2*pe+1], pa[mf], vh4[2], vh4[3]);
                    mma16816h(o[mf][2*pe+1], pa[mf], vl4[2], vl4[3]);
                }
            }
        }
    }

    // Epilogue
    #pragma unroll
    for (int mf = 0; mf < 2; mf++) {
        float inv0 = 1.0f / l[mf*2];
        float inv1 = 1.0f / l[mf*2+1];
        int tq = q0 + w*32 + mf*16 + g;
        #pragma unroll
        for (int et = 0; et < 8; et++) {
            int col = hh*HDD + et*8 + 2*t;
            uint32_t hv, lv;
            size_t a0 = ((size_t)b*TT + tq)*DD + col;
            size_t a1 = ((size_t)b*TT + tq + 8)*DD + col;
            split_pack(o[mf][et][0]*inv0, o[mf][et][1]*inv0, hv, lv);
            *(uint32_t*)&g_aoh[a0] = hv;
            *(uint32_t*)&g_aol[a0] = lv;
            split_pack(o[mf][et][2]*inv1, o[mf][et][3]*inv1, hv, lv);
            *(uint32_t*)&g_aoh[a1] = hv;
            *(uint32_t*)&g_aol[a1] = lv;
        }
    }
}

// ============================================================================
// Launch
// ============================================================================
extern "C" void kernel_launch(void* const* d_in, const int* in_sizes, int n_in,
                              void* d_out, int out_size)
{
    const float* x  = (const float*)d_in[0];
    const float* Wq = (const float*)d_in[1];
    const float* Wk = (const float*)d_in[2];
    const float* Wv = (const float*)d_in[3];
    const float* Wo = (const float*)d_in[4];
    const float* bo = (const float*)d_in[5];
    float* out = (float*)d_out;

    cudaFuncSetAttribute(qkv_gemm_tc, cudaFuncAttributeMaxDynamicSharedMemorySize,
                         GEMM_SMEM_BYTES);
    cudaFuncSetAttribute(out_gemm_tc, cudaFuncAttributeMaxDynamicSharedMemorySize,
                         GEMM_SMEM_BYTES);
    cudaFuncSetAttribute(attn_tc, cudaFuncAttributeMaxDynamicSharedMemorySize,
                         ATTN_SMEM_BYTES);

    int nx = MTOT*DD/4, nw = DD*DD/4;
    convert_x_k<<<nx/256, 256>>>((const float4*)x);
    convert_w_k<<<dim3(nw/256, 4), 256>>>((const float4*)Wq, (const float4*)Wk,
                                          (const float4*)Wv, (const float4*)Wo);

    qkv_gemm_tc<<<dim3(DD/128, MTOT/128, 3), 128, GEMM_SMEM_BYTES>>>(0);
    attn_tc<<<dim3(TT/128, BB*HH), 128, ATTN_SMEM_BYTES>>>();
    out_gemm_tc<<<dim3(DD/128, MTOT/128), 128, GEMM_SMEM_BYTES>>>(bo, out);
}

// round 11
// speedup vs baseline: 4.8917x; 1.3365x over previous
#include <cuda_runtime.h>
#include <cuda_bf16.h>
#include <cuda_fp16.h>
#include <cstdint>
#include <math.h>

#define BB   4
#define TT   2048
#define DD   1024
#define HH   16
#define HDD  64
#define MTOT (BB*TT)   // 8192

typedef __nv_bfloat16  bf16;
typedef __nv_bfloat162 bf162;

// ---- precision-split globals ----
__device__ bf16   g_xh [(size_t)MTOT*DD], g_xl [(size_t)MTOT*DD];  // x bf16 hi/lo (QK proj)
__device__ __half g_xf [(size_t)MTOT*DD];                          // x fp16 (V proj)
__device__ bf16   g_wqh[(size_t)DD*DD],   g_wql[(size_t)DD*DD];
__device__ bf16   g_wkh[(size_t)DD*DD],   g_wkl[(size_t)DD*DD];
__device__ __half g_wvf[(size_t)DD*DD];                            // Wv fp16
__device__ __half g_wof[(size_t)DD*DD];                            // Wo fp16
__device__ bf16   g_qh [(size_t)MTOT*DD], g_ql [(size_t)MTOT*DD];  // [B,H,T,HD] prescaled log2e/8
__device__ bf16   g_kh [(size_t)MTOT*DD], g_kl [(size_t)MTOT*DD];  // [B,H,T,HD]
__device__ __half g_vtf[(size_t)MTOT*DD];                          // V^T [B,H,HD,T] fp16
__device__ __half g_aof[(size_t)MTOT*DD];                          // attn out [B,T,D] fp16

// ============================================================================
// Helpers
// ============================================================================
__device__ __forceinline__ uint32_t smem_u32(const void* p) {
    return (uint32_t)__cvta_generic_to_shared(p);
}
__device__ __forceinline__ void ldsm_x4(uint32_t r[4], uint32_t addr) {
    asm volatile("ldmatrix.sync.aligned.m8n8.x4.shared.b16 {%0,%1,%2,%3}, [%4];"
                 : "=r"(r[0]), "=r"(r[1]), "=r"(r[2]), "=r"(r[3]) : "r"(addr));
}
__device__ __forceinline__ void mma16816(float d[4], const uint32_t a[4], const uint32_t b0, const uint32_t b1) {
    asm volatile(
        "mma.sync.aligned.m16n8k16.row.col.f32.bf16.bf16.f32 "
        "{%0,%1,%2,%3}, {%4,%5,%6,%7}, {%8,%9}, {%0,%1,%2,%3};"
        : "+f"(d[0]), "+f"(d[1]), "+f"(d[2]), "+f"(d[3])
        : "r"(a[0]), "r"(a[1]), "r"(a[2]), "r"(a[3]), "r"(b0), "r"(b1));
}
__device__ __forceinline__ void mma16816h(float d[4], const uint32_t a[4], const uint32_t b0, const uint32_t b1) {
    asm volatile(
        "mma.sync.aligned.m16n8k16.row.col.f32.f16.f16.f32 "
        "{%0,%1,%2,%3}, {%4,%5,%6,%7}, {%8,%9}, {%0,%1,%2,%3};"
        : "+f"(d[0]), "+f"(d[1]), "+f"(d[2]), "+f"(d[3])
        : "r"(a[0]), "r"(a[1]), "r"(a[2]), "r"(a[3]), "r"(b0), "r"(b1));
}
__device__ __forceinline__ void split2(float x, float y, bf162& h, bf162& l) {
    bf16 hx = __float2bfloat16(x);
    bf16 hy = __float2bfloat16(y);
    h = __halves2bfloat162(hx, hy);
    l = __halves2bfloat162(__float2bfloat16(x - __bfloat162float(hx)),
                           __float2bfloat16(y - __bfloat162float(hy)));
}
__device__ __forceinline__ void split_pack(float x, float y, uint32_t& h, uint32_t& l) {
    uint32_t hp;
    asm("cvt.rn.bf16x2.f32 %0, %1, %2;" : "=r"(hp) : "f"(y), "f"(x));
    float xh = __uint_as_float(hp << 16);
    float yh = __uint_as_float(hp & 0xFFFF0000u);
    uint32_t lp;
    asm("cvt.rn.bf16x2.f32 %0, %1, %2;" : "=r"(lp) : "f"(y - yh), "f"(x - xh));
    h = hp; l = lp;
}
__device__ __forceinline__ uint32_t f16pack(float x, float y) {
    uint32_t r;
    asm("cvt.rn.f16x2.f32 %0, %1, %2;" : "=r"(r) : "f"(y), "f"(x));
    return r;
}
__device__ __forceinline__ uint32_t h2ex2(uint32_t x) {
    uint32_t r;
    asm("ex2.approx.f16x2 %0, %1;" : "=r"(r) : "r"(x));
    return r;
}
__device__ __forceinline__ float ex2f(float x) {
    float r;
    asm("ex2.approx.f32 %0, %1;" : "=f"(r) : "f"(x));
    return r;
}
__device__ __forceinline__ void cp16(uint32_t s, const void* g) {
    asm volatile("cp.async.ca.shared.global [%0], [%1], 16;\n" :: "r"(s), "l"(g));
}
#define CP_COMMIT() asm volatile("cp.async.commit_group;\n" ::: "memory")
template<int N> __device__ __forceinline__ void cp_wait() {
    asm volatile("cp.async.wait_group %0;\n" :: "n"(N) : "memory");
}

// ============================================================================
// Convert kernels
// ============================================================================
__global__ __launch_bounds__(256) void convert_x_k(const float4* __restrict__ src)
{
    int i = blockIdx.x * 256 + threadIdx.x;
    float4 v = src[i];
    bf162 h0, l0, h1, l1;
    split2(v.x, v.y, h0, l0);
    split2(v.z, v.w, h1, l1);
    *(bf162*)(g_xh + (size_t)i*4)     = h0;
    *(bf162*)(g_xh + (size_t)i*4 + 2) = h1;
    *(bf162*)(g_xl + (size_t)i*4)     = l0;
    *(bf162*)(g_xl + (size_t)i*4 + 2) = l1;
    *(__half2*)(g_xf + (size_t)i*4)     = __floats2half2_rn(v.x, v.y);
    *(__half2*)(g_xf + (size_t)i*4 + 2) = __floats2half2_rn(v.z, v.w);
}
__global__ __launch_bounds__(256) void convert_w_k(
    const float4* __restrict__ wq, const float4* __restrict__ wk,
    const float4* __restrict__ wv, const float4* __restrict__ wo)
{
    int which = blockIdx.y;
    int i = blockIdx.x * 256 + threadIdx.x;
    if (which < 2) {
        const float4* src = (which == 0) ? wq : wk;
        bf16* ho = (which == 0) ? g_wqh : g_wkh;
        bf16* lo = (which == 0) ? g_wql : g_wkl;
        float4 v = src[i];
        bf162 h0, l0, h1, l1;
        split2(v.x, v.y, h0, l0);
        split2(v.z, v.w, h1, l1);
        *(bf162*)(ho + (size_t)i*4)     = h0;
        *(bf162*)(ho + (size_t)i*4 + 2) = h1;
        *(bf162*)(lo + (size_t)i*4)     = l0;
        *(bf162*)(lo + (size_t)i*4 + 2) = l1;
    } else {
        const float4* src = (which == 2) ? wv : wo;
        __half* ho = (which == 2) ? g_wvf : g_wof;
        float4 v = src[i];
        *(__half2*)(ho + (size_t)i*4)     = __floats2half2_rn(v.x, v.y);
        *(__half2*)(ho + (size_t)i*4 + 2) = __floats2half2_rn(v.z, v.w);
    }
}

// ============================================================================
// bf16 3-term GEMM (Q/K projections): CTA 128x128, 4 warps, warp tile 64x64.
// ============================================================================
#define LDKB 40
#define STG_ARR (128*LDKB)
#define STG4    (4*STG_ARR)
#define GEMM_SMEM_BYTES (2*STG4*2)  // 81920

__device__ __forceinline__ void gemm_load_stage(
    const bf16* __restrict__ Ahg, const bf16* __restrict__ Alg,
    const bf16* __restrict__ Bhg, const bf16* __restrict__ Blg,
    int m0, int n0, int k0, bf16* base, int tid)
{
    const bf16* gp[4] = {Ahg, Alg, Bhg, Blg};
    #pragma unroll
    for (int a = 0; a < 4; a++) {
        int row0 = (a < 2) ? m0 : n0;
        bf16* sb = base + a*STG_ARR;
        #pragma unroll
        for (int s = 0; s < 4; s++) {
            int idx = tid + s*128;
            int r = idx >> 2;
            int c = (idx & 3) * 8;
            cp16(smem_u32(sb + r*LDKB + c), gp[a] + (size_t)(row0 + r)*DD + k0 + c);
        }
    }
}

__device__ __forceinline__ void gemm_mainloop(
    const bf16* __restrict__ Ahg, const bf16* __restrict__ Alg,
    const bf16* __restrict__ Bhg, const bf16* __restrict__ Blg,
    int m0, int n0, bf16* smem, float acc[4][8][4])
{
    const int tid  = threadIdx.x;
    const int lane = tid & 31;
    const int warp = tid >> 5;
    const int wm = warp >> 1;
    const int wn = warp & 1;

    const int a_r  = lane & 15;
    const int a_c  = (lane >> 4) << 3;
    const int b4_r = ((lane >> 4) << 3) + (lane & 7);
    const int b4_c = ((lane >> 3) & 1) << 3;

    const int NST = DD / 32;

    gemm_load_stage(Ahg, Alg, Bhg, Blg, m0, n0, 0, smem, tid); CP_COMMIT();

    for (int i = 0; i < NST; i++) {
        __syncthreads();
        if (i + 1 < NST)
            gemm_load_stage(Ahg, Alg, Bhg, Blg, m0, n0, (i+1)*32,
                            smem + ((i+1)&1)*STG4, tid);
        CP_COMMIT();
        cp_wait<1>();
        __syncthreads();

        bf16* Ahs = smem + (i&1)*STG4;
        bf16* Als = Ahs + STG_ARR;
        bf16* Bhs = Als + STG_ARR;
        bf16* Bls = Bhs + STG_ARR;

        #pragma unroll
        for (int kk = 0; kk < 32; kk += 16) {
            uint32_t ah[4][4], al[4][4];
            #pragma unroll
            for (int mt = 0; mt < 4; mt++) {
                ldsm_x4(ah[mt], smem_u32(Ahs + (wm*64 + mt*16 + a_r)*LDKB + kk + a_c));
                ldsm_x4(al[mt], smem_u32(Als + (wm*64 + mt*16 + a_r)*LDKB + kk + a_c));
            }
            #pragma unroll
            for (int p = 0; p < 4; p++) {
                uint32_t bh4[4], bl4[4];
                ldsm_x4(bh4, smem_u32(Bhs + (wn*64 + p*16 + b4_r)*LDKB + kk + b4_c));
                ldsm_x4(bl4, smem_u32(Bls + (wn*64 + p*16 + b4_r)*LDKB + kk + b4_c));
                #pragma unroll
                for (int mt = 0; mt < 4; mt++) {
                    mma16816(acc[mt][2*p],   ah[mt], bh4[0], bh4[1]);
                    mma16816(acc[mt][2*p],   ah[mt], bl4[0], bl4[1]);
                    mma16816(acc[mt][2*p],   al[mt], bh4[0], bh4[1]);
                    mma16816(acc[mt][2*p+1], ah[mt], bh4[2], bh4[3]);
                    mma16816(acc[mt][2*p+1], ah[mt], bl4[2], bl4[3]);
                    mma16816(acc[mt][2*p+1], al[mt], bh4[2], bh4[3]);
                }
            }
        }
    }
}

// Q/K projection (z: 0=Q, 1=K)
__global__ __launch_bounds__(128) void qk_gemm_tc(int)
{
    extern __shared__ bf16 gsm[];

    const int which = blockIdx.z;
    const bf16* Bhg = (which == 0) ? g_wqh : g_wkh;
    const bf16* Blg = (which == 0) ? g_wql : g_wkl;

    const int m0 = blockIdx.y * 128;
    const int n0 = blockIdx.x * 128;

    float acc[4][8][4];
    #pragma unroll
    for (int i = 0; i < 4; i++)
        #pragma unroll
        for (int j = 0; j < 8; j++)
            #pragma unroll
            for (int r = 0; r < 4; r++) acc[i][j][r] = 0.0f;

    gemm_mainloop(g_xh, g_xl, Bhg, Blg, m0, n0, gsm, acc);

    const int lane = threadIdx.x & 31;
    const int warp = threadIdx.x >> 5;
    const int wm = warp >> 1, wn = warp & 1;
    const int g = lane >> 2, t = lane & 3;
    const int bb = m0 >> 11;
    const int mloc = m0 & 2047;

    // Q prescale folds 1/8 AND log2e (softmax in log2 domain)
    float sc = (which == 0) ? (0.125f * 1.4426950408889634f) : 1.0f;
    bf16* hp = (which == 0) ? g_qh : g_kh;
    bf16* lp = (which == 0) ? g_ql : g_kl;
    #pragma unroll
    for (int mt = 0; mt < 4; mt++) {
        #pragma unroll
        for (int nt = 0; nt < 8; nt++) {
            int row = mloc + wm*64 + mt*16 + g;
            int col = n0 + wn*64 + nt*8 + 2*t;
            int hh = col >> 6, e = col & 63;
            uint32_t hv, lv;
            size_t a0 = (((size_t)bb*HH + hh)*TT + row)*HDD + e;
            size_t a1 = (((size_t)bb*HH + hh)*TT + row + 8)*HDD + e;
            split_pack(acc[mt][nt][0]*sc, acc[mt][nt][1]*sc, hv, lv);
            *(uint32_t*)&hp[a0] = hv;
            *(uint32_t*)&lp[a0] = lv;
            split_pack(acc[mt][nt][2]*sc, acc[mt][nt][3]*sc, hv, lv);
            *(uint32_t*)&hp[a1] = hv;
            *(uint32_t*)&lp[a1] = lv;
        }
    }
}

// ============================================================================
// fp16 1-term GEMM (V projection, out projection)
// ============================================================================
#define F16_STG   (128*LDKB)           // halfs per array per stage
#define F16_STG2  (2*F16_STG)          // A + B
#define F16_PIPE_BYTES (2*F16_STG2*2)  // 40960
#define V_SMEM_BYTES 69632             // max(pipeline, Cs 128x133 fp32)

__device__ __forceinline__ void f16_load_stage(
    const __half* __restrict__ Ag, const __half* __restrict__ Bg,
    int m0, int n0, int k0, __half* base, int tid)
{
    #pragma unroll
    for (int s = 0; s < 4; s++) {
        int idx = tid + s*128;
        int r = idx >> 2;
        int c = (idx & 3) * 8;
        cp16(smem_u32(base + r*LDKB + c), Ag + (size_t)(m0 + r)*DD + k0 + c);
        cp16(smem_u32(base + F16_STG + r*LDKB + c), Bg + (size_t)(n0 + r)*DD + k0 + c);
    }
}

__device__ __forceinline__ void f16_gemm_mainloop(
    const __half* __restrict__ Ag, const __half* __restrict__ Bg,
    int m0, int n0, __half* smem, float acc[4][8][4])
{
    const int tid  = threadIdx.x;
    const int lane = tid & 31;
    const int warp = tid >> 5;
    const int wm = warp >> 1;
    const int wn = warp & 1;

    const int a_r  = lane & 15;
    const int a_c  = (lane >> 4) << 3;
    const int b4_r = ((lane >> 4) << 3) + (lane & 7);
    const int b4_c = ((lane >> 3) & 1) << 3;

    const int NST = DD / 32;

    f16_load_stage(Ag, Bg, m0, n0, 0, smem, tid); CP_COMMIT();

    for (int i = 0; i < NST; i++) {
        __syncthreads();
        if (i + 1 < NST)
            f16_load_stage(Ag, Bg, m0, n0, (i+1)*32, smem + ((i+1)&1)*F16_STG2, tid);
        CP_COMMIT();
        cp_wait<1>();
        __syncthreads();

        __half* As = smem + (i&1)*F16_STG2;
        __half* Bs = As + F16_STG;

        #pragma unroll
        for (int kk = 0; kk < 32; kk += 16) {
            uint32_t a4[4][4];
            #pragma unroll
            for (int mt = 0; mt < 4; mt++)
                ldsm_x4(a4[mt], smem_u32(As + (wm*64 + mt*16 + a_r)*LDKB + kk + a_c));
            #pragma unroll
            for (int p = 0; p < 4; p++) {
                uint32_t b4[4];
                ldsm_x4(b4, smem_u32(Bs + (wn*64 + p*16 + b4_r)*LDKB + kk + b4_c));
                #pragma unroll
                for (int mt = 0; mt < 4; mt++) {
                    mma16816h(acc[mt][2*p],   a4[mt], b4[0], b4[1]);
                    mma16816h(acc[mt][2*p+1], a4[mt], b4[2], b4[3]);
                }
            }
        }
    }
}

// V projection: writes V^T [B,H,HD,T] fp16
__global__ __launch_bounds__(128) void v_gemm_f16()
{
    extern __shared__ __half fsm[];

    const int m0 = blockIdx.y * 128;
    const int n0 = blockIdx.x * 128;
    const int tid = threadIdx.x;
    const int bb = m0 >> 11;
    const int mloc = m0 & 2047;

    float acc[4][8][4];
    #pragma unroll
    for (int i = 0; i < 4; i++)
        #pragma unroll
        for (int j = 0; j < 8; j++)
            #pragma unroll
            for (int r = 0; r < 4; r++) acc[i][j][r] = 0.0f;

    f16_gemm_mainloop(g_xf, g_wvf, m0, n0, fsm, acc);

    const int lane = tid & 31;
    const int warp = tid >> 5;
    const int wm = warp >> 1, wn = warp & 1;
    const int g = lane >> 2, t = lane & 3;

    // Stage fp32 tile, then write V^T fp16 coalesced
    float* Cs = (float*)fsm;
    __syncthreads();
    #pragma unroll
    for (int mt = 0; mt < 4; mt++) {
        #pragma unroll
        for (int nt = 0; nt < 8; nt++) {
            int row = wm*64 + mt*16 + g;
            int col = wn*64 + nt*8 + 2*t;
            Cs[row*133 + col]       = acc[mt][nt][0];
            Cs[row*133 + col + 1]   = acc[mt][nt][1];
            Cs[(row+8)*133 + col]   = acc[mt][nt][2];
            Cs[(row+8)*133 + col+1] = acc[mt][nt][3];
        }
    }
    __syncthreads();
    for (int idx = tid; idx < 2048; idx += 128) {
        int el  = idx >> 4;
        int tch = (idx & 15) * 8;
        __half hv8[8];
        #pragma unroll
        for (int q = 0; q < 8; q++)
            hv8[q] = __float2half_rn(Cs[(tch + q)*133 + el]);
        int col = n0 + el;
        int hh = col >> 6, e = col & 63;
        size_t rb = (((size_t)bb*HH + hh)*HDD + e)*TT + mloc + tch;
        *(uint4*)&g_vtf[rb] = *(uint4*)hv8;
    }
}

// Output projection: out = aof @ Wo^T + bo (fp32 out)
__global__ __launch_bounds__(128) void out_gemm_f16(
    const float* __restrict__ bo, float* __restrict__ outp)
{
    extern __shared__ __half fsm[];

    const int m0 = blockIdx.y * 128;
    const int n0 = blockIdx.x * 128;

    float acc[4][8][4];
    #pragma unroll
    for (int i = 0; i < 4; i++)
        #pragma unroll
        for (int j = 0; j < 8; j++)
            #pragma unroll
            for (int r = 0; r < 4; r++) acc[i][j][r] = 0.0f;

    f16_gemm_mainloop(g_aof, g_wof, m0, n0, fsm, acc);

    const int lane = threadIdx.x & 31;
    const int warp = threadIdx.x >> 5;
    const int wm = warp >> 1, wn = warp & 1;
    const int g = lane >> 2, t = lane & 3;

    #pragma unroll
    for (int mt = 0; mt < 4; mt++) {
        #pragma unroll
        for (int nt = 0; nt < 8; nt++) {
            int row = m0 + wm*64 + mt*16 + g;
            int col = n0 + wn*64 + nt*8 + 2*t;
            float bx = bo[col], by = bo[col+1];
            float2 v01 = make_float2(acc[mt][nt][0] + bx, acc[mt][nt][1] + by);
            float2 v23 = make_float2(acc[mt][nt][2] + bx, acc[mt][nt][3] + by);
            *(float2*)&outp[(size_t)row*DD + col]     = v01;
            *(float2*)&outp[(size_t)(row+8)*DD + col] = v23;
        }
    }
}

// ============================================================================
// Flash attention: q-tile 128, 4 warps x 32 rows. QK bf16 3-term;
// softmax via ex2.approx.f16x2 (output IS the fp16 P fragment);
// PV fp16 1-term (V single fp16). K/V double-buffered cp.async.
// ============================================================================
#define AQS 72
#define KVARR (64*AQS)
#define ATTN_Q_BYTES (2*128*AQS*2)                      // 36864
#define ATTN_KV_BYTES (2*3*KVARR*2)                     // 55296
#define ATTN_SMEM_BYTES (ATTN_Q_BYTES + ATTN_KV_BYTES)  // 92160

__device__ __forceinline__ void attn_load_kv(
    const bf16* khb, const bf16* klb, const __half* vhb,
    int j0, bf16* kvbase, int tid)
{
    bf16* Kh = kvbase;
    bf16* Kl = kvbase + KVARR;
    bf16* Vh = kvbase + 2*KVARR;   // fp16 payload
    #pragma unroll
    for (int s = 0; s < 4; s++) {
        int idx = tid + s*128;
        int r = idx >> 3;
        int c = (idx & 7) * 8;
        cp16(smem_u32(Kh + r*AQS + c), khb + (size_t)(j0 + r)*HDD + c);
        cp16(smem_u32(Kl + r*AQS + c), klb + (size_t)(j0 + r)*HDD + c);
        cp16(smem_u32(Vh + r*AQS + c), vhb + (size_t)r*TT + j0 + c);
    }
}

__global__ __launch_bounds__(128) void attn_tc()
{
    extern __shared__ bf16 asmem[];
    bf16* Qh = asmem;
    bf16* Ql = Qh + 128*AQS;
    bf16* KV = Ql + 128*AQS;

    const int bh = blockIdx.y;
    const int hh = bh & (HH-1);
    const int b  = bh >> 4;
    const int qt = gridDim.x - 1 - blockIdx.x;
    const int q0 = qt * 128;
    const int njt = 2*qt + 2;

    const int tid  = threadIdx.x;
    const int lane = tid & 31;
    const int w    = tid >> 5;
    const int g    = lane >> 2;
    const int t    = lane & 3;

    const bf16* __restrict__ qhb = g_qh  + (size_t)bh * TT * HDD;
    const bf16* __restrict__ qlb = g_ql  + (size_t)bh * TT * HDD;
    const bf16* __restrict__ khb = g_kh  + (size_t)bh * TT * HDD;
    const bf16* __restrict__ klb = g_kl  + (size_t)bh * TT * HDD;
    const __half* __restrict__ vhb = g_vtf + (size_t)bh * HDD * TT;

    for (int idx = tid; idx < 1024; idx += 128) {
        int r = idx >> 3;
        int c = (idx & 7) * 8;
        *(uint4*)(Qh + r*AQS + c) = *(const uint4*)(qhb + (size_t)(q0 + r)*HDD + c);
        *(uint4*)(Ql + r*AQS + c) = *(const uint4*)(qlb + (size_t)(q0 + r)*HDD + c);
    }

    attn_load_kv(khb, klb, vhb, 0, KV, tid); CP_COMMIT();

    float o[2][8][4];
    float m[4], l[4];
    #pragma unroll
    for (int mf = 0; mf < 2; mf++)
        #pragma unroll
        for (int et = 0; et < 8; et++)
            #pragma unroll
            for (int r = 0; r < 4; r++) o[mf][et][r] = 0.0f;
    #pragma unroll
    for (int i = 0; i < 4; i++) { m[i] = -1e30f; l[i] = 0.0f; }

    const int a_r  = lane & 15;
    const int a_c  = (lane >> 4) << 3;
    const int b4_r = ((lane >> 4) << 3) + (lane & 7);
    const int b4_c = ((lane >> 3) & 1) << 3;

    const int r0w = q0 + w*32;

    for (int jt = 0; jt < njt; jt++) {
        const int j0 = jt * 64;

        __syncthreads();
        if (jt + 1 < njt)
            attn_load_kv(khb, klb, vhb, (jt+1)*64, KV + ((jt+1)&1)*3*KVARR, tid);
        CP_COMMIT();
        cp_wait<1>();
        __syncthreads();

        if (j0 > r0w + 31) continue;

        bf16* Kh = KV + (jt&1)*3*KVARR;
        bf16* Kl = Kh + KVARR;
        bf16* Vh = Kl + KVARR;   // fp16 payload

        // S = Q K^T (bf16 3-term; scores in log2 domain)
        float s[2][8][4];
        #pragma unroll
        for (int mf = 0; mf < 2; mf++)
            #pragma unroll
            for (int nt = 0; nt < 8; nt++)
                #pragma unroll
                for (int r = 0; r < 4; r++) s[mf][nt][r] = 0.0f;

        #pragma unroll
        for (int kk = 0; kk < 4; kk++) {
            uint32_t qah[2][4], qal[2][4];
            #pragma unroll
            for (int mf = 0; mf < 2; mf++) {
                ldsm_x4(qah[mf], smem_u32(Qh + (w*32 + mf*16 + a_r)*AQS + kk*16 + a_c));
                ldsm_x4(qal[mf], smem_u32(Ql + (w*32 + mf*16 + a_r)*AQS + kk*16 + a_c));
            }
            #pragma unroll
            for (int p = 0; p < 4; p++) {
                uint32_t kh4[4], kl4[4];
                ldsm_x4(kh4, smem_u32(Kh + (p*16 + b4_r)*AQS + kk*16 + b4_c));
                ldsm_x4(kl4, smem_u32(Kl + (p*16 + b4_r)*AQS + kk*16 + b4_c));
                #pragma unroll
                for (int mf = 0; mf < 2; mf++) {
                    mma16816(s[mf][2*p],   qah[mf], kh4[0], kh4[1]);
                    mma16816(s[mf][2*p],   qah[mf], kl4[0], kl4[1]);
                    mma16816(s[mf][2*p],   qal[mf], kh4[0], kh4[1]);
                    mma16816(s[mf][2*p+1], qah[mf], kh4[2], kh4[3]);
                    mma16816(s[mf][2*p+1], qah[mf], kl4[2], kl4[3]);
                    mma16816(s[mf][2*p+1], qal[mf], kh4[2], kh4[3]);
                }
            }
        }

        if (j0 + 63 > r0w) {
            #pragma unroll
            for (int mf = 0; mf < 2; mf++) {
                int r0 = r0w + mf*16 + g;
                int r1 = r0 + 8;
                #pragma unroll
                for (int nt = 0; nt < 8; nt++) {
                    int c0 = j0 + nt*8 + 2*t;
                    if (c0     > r0) s[mf][nt][0] = -1e30f;
                    if (c0 + 1 > r0) s[mf][nt][1] = -1e30f;
                    if (c0     > r1) s[mf][nt][2] = -1e30f;
                    if (c0 + 1 > r1) s[mf][nt][3] = -1e30f;
                }
            }
        }

        // Online softmax in log2 domain; ex2.f16x2 output = fp16 P fragments
        uint32_t ph[2][8][2];
        #pragma unroll
        for (int mf = 0; mf < 2; mf++) {
            float mx0 = -1e30f, mx1 = -1e30f;
            #pragma unroll
            for (int nt = 0; nt < 8; nt++) {
                mx0 = fmaxf(mx0, fmaxf(s[mf][nt][0], s[mf][nt][1]));
                mx1 = fmaxf(mx1, fmaxf(s[mf][nt][2], s[mf][nt][3]));
            }
            #pragma unroll
            for (int off = 1; off <= 2; off <<= 1) {
                mx0 = fmaxf(mx0, __shfl_xor_sync(0xffffffffu, mx0, off));
                mx1 = fmaxf(mx1, __shfl_xor_sync(0xffffffffu, mx1, off));
            }
            float mn0 = fmaxf(m[mf*2],   mx0);
            float mn1 = fmaxf(m[mf*2+1], mx1);
            float f0 = ex2f(m[mf*2]   - mn0);
            float f1 = ex2f(m[mf*2+1] - mn1);
            float rs0 = 0.0f, rs1 = 0.0f;
            #pragma unroll
            for (int nt = 0; nt < 8; nt++) {
                uint32_t w0 = h2ex2(f16pack(s[mf][nt][0] - mn0, s[mf][nt][1] - mn0));
                uint32_t w1 = h2ex2(f16pack(s[mf][nt][2] - mn1, s[mf][nt][3] - mn1));
                ph[mf][nt][0] = w0;
                ph[mf][nt][1] = w1;
                float2 fa = __half22float2(*(__half2*)&w0);
                float2 fb = __half22float2(*(__half2*)&w1);
                rs0 += fa.x + fa.y;
                rs1 += fb.x + fb.y;
            }
            #pragma unroll
            for (int off = 1; off <= 2; off <<= 1) {
                rs0 += __shfl_xor_sync(0xffffffffu, rs0, off);
                rs1 += __shfl_xor_sync(0xffffffffu, rs1, off);
            }
            l[mf*2]   = l[mf*2]   * f0 + rs0;
            l[mf*2+1] = l[mf*2+1] * f1 + rs1;
            m[mf*2]   = mn0;
            m[mf*2+1] = mn1;
            #pragma unroll
            for (int et = 0; et < 8; et++) {
                o[mf][et][0] *= f0; o[mf][et][1] *= f0;
                o[mf][et][2] *= f1; o[mf][et][3] *= f1;
            }
        }

        // P*V: fp16 1-term (V single fp16)
        #pragma unroll
        for (int kt = 0; kt < 4; kt++) {
            uint32_t pa[2][4];
            #pragma unroll
            for (int mf = 0; mf < 2; mf++) {
                pa[mf][0] = ph[mf][2*kt][0];
                pa[mf][1] = ph[mf][2*kt][1];
                pa[mf][2] = ph[mf][2*kt+1][0];
                pa[mf][3] = ph[mf][2*kt+1][1];
            }
            #pragma unroll
            for (int pe = 0; pe < 4; pe++) {
                uint32_t vh4[4];
                ldsm_x4(vh4, smem_u32(Vh + (pe*16 + b4_r)*AQS + kt*16 + b4_c));
                #pragma unroll
                for (int mf = 0; mf < 2; mf++) {
                    mma16816h(o[mf][2*pe],   pa[mf], vh4[0], vh4[1]);
                    mma16816h(o[mf][2*pe+1], pa[mf], vh4[2], vh4[3]);
                }
            }
        }
    }

    // Epilogue: normalize, write fp16 attn output [B,T,D]
    #pragma unroll
    for (int mf = 0; mf < 2; mf++) {
        float inv0 = 1.0f / l[mf*2];
        float inv1 = 1.0f / l[mf*2+1];
        int tq = q0 + w*32 + mf*16 + g;
        #pragma unroll
        for (int et = 0; et < 8; et++) {
            int col = hh*HDD + et*8 + 2*t;
            size_t a0 = ((size_t)b*TT + tq)*DD + col;
            size_t a1 = ((size_t)b*TT + tq + 8)*DD + col;
            *(uint32_t*)&g_aof[a0] = f16pack(o[mf][et][0]*inv0, o[mf][et][1]*inv0);
            *(uint32_t*)&g_aof[a1] = f16pack(o[mf][et][2]*inv1, o[mf][et][3]*inv1);
        }
    }
}

// ============================================================================
// Launch
// ============================================================================
extern "C" void kernel_launch(void* const* d_in, const int* in_sizes, int n_in,
                              void* d_out, int out_size)
{
    const float* x  = (const float*)d_in[0];
    const float* Wq = (const float*)d_in[1];
    const float* Wk = (const float*)d_in[2];
    const float* Wv = (const float*)d_in[3];
    const float* Wo = (const float*)d_in[4];
    const float* bo = (const float*)d_in[5];
    float* out = (float*)d_out;

    cudaFuncSetAttribute(qk_gemm_tc, cudaFuncAttributeMaxDynamicSharedMemorySize,
                         GEMM_SMEM_BYTES);
    cudaFuncSetAttribute(v_gemm_f16, cudaFuncAttributeMaxDynamicSharedMemorySize,
                         V_SMEM_BYTES);
    cudaFuncSetAttribute(out_gemm_f16, cudaFuncAttributeMaxDynamicSharedMemorySize,
                         F16_PIPE_BYTES);
    cudaFuncSetAttribute(attn_tc, cudaFuncAttributeMaxDynamicSharedMemorySize,
                         ATTN_SMEM_BYTES);

    int nx = MTOT*DD/4, nw = DD*DD/4;
    convert_x_k<<<nx/256, 256>>>((const float4*)x);
    convert_w_k<<<dim3(nw/256, 4), 256>>>((const float4*)Wq, (const float4*)Wk,
                                          (const float4*)Wv, (const float4*)Wo);

    qk_gemm_tc<<<dim3(DD/128, MTOT/128, 2), 128, GEMM_SMEM_BYTES>>>(0);
    v_gemm_f16<<<dim3(DD/128, MTOT/128), 128, V_SMEM_BYTES>>>();
    attn_tc<<<dim3(TT/128, BB*HH), 128, ATTN_SMEM_BYTES>>>();
    out_gemm_f16<<<dim3(DD/128, MTOT/128), 128, F16_PIPE_BYTES>>>(bo, out);
}

// round 12
// speedup vs baseline: 5.3322x; 1.0901x over previous
#include <cuda_runtime.h>
#include <cuda_bf16.h>
#include <cuda_fp16.h>
#include <cstdint>
#include <math.h>

#define BB   4
#define TT   2048
#define DD   1024
#define HH   16
#define HDD  64
#define MTOT (BB*TT)   // 8192

typedef __nv_bfloat16  bf16;
typedef __nv_bfloat162 bf162;

// ---- precision-split globals ----
__device__ bf16   g_xh [(size_t)MTOT*DD], g_xl [(size_t)MTOT*DD];  // x bf16 hi/lo (QK proj)
__device__ __half g_xf [(size_t)MTOT*DD];                          // x fp16 (V proj)
__device__ bf16   g_wqh[(size_t)DD*DD],   g_wql[(size_t)DD*DD];
__device__ bf16   g_wkh[(size_t)DD*DD],   g_wkl[(size_t)DD*DD];
__device__ __half g_wvf[(size_t)DD*DD];                            // Wv fp16
__device__ __half g_wof[(size_t)DD*DD];                            // Wo fp16
__device__ bf16   g_qh [(size_t)MTOT*DD], g_ql [(size_t)MTOT*DD];  // [B,H,T,HD] prescaled log2e/8
__device__ bf16   g_kh [(size_t)MTOT*DD];                          // [B,H,T,HD] K single bf16
__device__ __half g_vtf[(size_t)MTOT*DD];                          // V^T [B,H,HD,T] fp16
__device__ __half g_aof[(size_t)MTOT*DD];                          // attn out [B,T,D] fp16

// ============================================================================
// Helpers
// ============================================================================
__device__ __forceinline__ uint32_t smem_u32(const void* p) {
    return (uint32_t)__cvta_generic_to_shared(p);
}
__device__ __forceinline__ void ldsm_x4(uint32_t r[4], uint32_t addr) {
    asm volatile("ldmatrix.sync.aligned.m8n8.x4.shared.b16 {%0,%1,%2,%3}, [%4];"
                 : "=r"(r[0]), "=r"(r[1]), "=r"(r[2]), "=r"(r[3]) : "r"(addr));
}
__device__ __forceinline__ void mma16816(float d[4], const uint32_t a[4], const uint32_t b0, const uint32_t b1) {
    asm volatile(
        "mma.sync.aligned.m16n8k16.row.col.f32.bf16.bf16.f32 "
        "{%0,%1,%2,%3}, {%4,%5,%6,%7}, {%8,%9}, {%0,%1,%2,%3};"
        : "+f"(d[0]), "+f"(d[1]), "+f"(d[2]), "+f"(d[3])
        : "r"(a[0]), "r"(a[1]), "r"(a[2]), "r"(a[3]), "r"(b0), "r"(b1));
}
__device__ __forceinline__ void mma16816h(float d[4], const uint32_t a[4], const uint32_t b0, const uint32_t b1) {
    asm volatile(
        "mma.sync.aligned.m16n8k16.row.col.f32.f16.f16.f32 "
        "{%0,%1,%2,%3}, {%4,%5,%6,%7}, {%8,%9}, {%0,%1,%2,%3};"
        : "+f"(d[0]), "+f"(d[1]), "+f"(d[2]), "+f"(d[3])
        : "r"(a[0]), "r"(a[1]), "r"(a[2]), "r"(a[3]), "r"(b0), "r"(b1));
}
__device__ __forceinline__ void split2(float x, float y, bf162& h, bf162& l) {
    bf16 hx = __float2bfloat16(x);
    bf16 hy = __float2bfloat16(y);
    h = __halves2bfloat162(hx, hy);
    l = __halves2bfloat162(__float2bfloat16(x - __bfloat162float(hx)),
                           __float2bfloat16(y - __bfloat162float(hy)));
}
__device__ __forceinline__ void split_pack(float x, float y, uint32_t& h, uint32_t& l) {
    uint32_t hp;
    asm("cvt.rn.bf16x2.f32 %0, %1, %2;" : "=r"(hp) : "f"(y), "f"(x));
    float xh = __uint_as_float(hp << 16);
    float yh = __uint_as_float(hp & 0xFFFF0000u);
    uint32_t lp;
    asm("cvt.rn.bf16x2.f32 %0, %1, %2;" : "=r"(lp) : "f"(y - yh), "f"(x - xh));
    h = hp; l = lp;
}
__device__ __forceinline__ uint32_t bf16pack(float x, float y) {
    uint32_t r;
    asm("cvt.rn.bf16x2.f32 %0, %1, %2;" : "=r"(r) : "f"(y), "f"(x));
    return r;
}
__device__ __forceinline__ uint32_t f16pack(float x, float y) {
    uint32_t r;
    asm("cvt.rn.f16x2.f32 %0, %1, %2;" : "=r"(r) : "f"(y), "f"(x));
    return r;
}
__device__ __forceinline__ uint32_t h2ex2(uint32_t x) {
    uint32_t r;
    asm("ex2.approx.f16x2 %0, %1;" : "=r"(r) : "r"(x));
    return r;
}
__device__ __forceinline__ float ex2f(float x) {
    float r;
    asm("ex2.approx.f32 %0, %1;" : "=f"(r) : "f"(x));
    return r;
}
__device__ __forceinline__ void cp16(uint32_t s, const void* g) {
    asm volatile("cp.async.ca.shared.global [%0], [%1], 16;\n" :: "r"(s), "l"(g));
}
#define CP_COMMIT() asm volatile("cp.async.commit_group;\n" ::: "memory")
template<int N> __device__ __forceinline__ void cp_wait() {
    asm volatile("cp.async.wait_group %0;\n" :: "n"(N) : "memory");
}

// ============================================================================
// Convert kernels
// ============================================================================
__global__ __launch_bounds__(256) void convert_x_k(const float4* __restrict__ src)
{
    int i = blockIdx.x * 256 + threadIdx.x;
    float4 v = src[i];
    bf162 h0, l0, h1, l1;
    split2(v.x, v.y, h0, l0);
    split2(v.z, v.w, h1, l1);
    *(bf162*)(g_xh + (size_t)i*4)     = h0;
    *(bf162*)(g_xh + (size_t)i*4 + 2) = h1;
    *(bf162*)(g_xl + (size_t)i*4)     = l0;
    *(bf162*)(g_xl + (size_t)i*4 + 2) = l1;
    *(__half2*)(g_xf + (size_t)i*4)     = __floats2half2_rn(v.x, v.y);
    *(__half2*)(g_xf + (size_t)i*4 + 2) = __floats2half2_rn(v.z, v.w);
}
__global__ __launch_bounds__(256) void convert_w_k(
    const float4* __restrict__ wq, const float4* __restrict__ wk,
    const float4* __restrict__ wv, const float4* __restrict__ wo)
{
    int which = blockIdx.y;
    int i = blockIdx.x * 256 + threadIdx.x;
    if (which < 2) {
        const float4* src = (which == 0) ? wq : wk;
        bf16* ho = (which == 0) ? g_wqh : g_wkh;
        bf16* lo = (which == 0) ? g_wql : g_wkl;
        float4 v = src[i];
        bf162 h0, l0, h1, l1;
        split2(v.x, v.y, h0, l0);
        split2(v.z, v.w, h1, l1);
        *(bf162*)(ho + (size_t)i*4)     = h0;
        *(bf162*)(ho + (size_t)i*4 + 2) = h1;
        *(bf162*)(lo + (size_t)i*4)     = l0;
        *(bf162*)(lo + (size_t)i*4 + 2) = l1;
    } else {
        const float4* src = (which == 2) ? wv : wo;
        __half* ho = (which == 2) ? g_wvf : g_wof;
        float4 v = src[i];
        *(__half2*)(ho + (size_t)i*4)     = __floats2half2_rn(v.x, v.y);
        *(__half2*)(ho + (size_t)i*4 + 2) = __floats2half2_rn(v.z, v.w);
    }
}

// ============================================================================
// bf16 3-term GEMM (Q/K projections): CTA 128x128, 4 warps, warp tile 64x64.
// ============================================================================
#define LDKB 40
#define STG_ARR (128*LDKB)
#define STG4    (4*STG_ARR)
#define GEMM_SMEM_BYTES (2*STG4*2)  // 81920

__device__ __forceinline__ void gemm_load_stage(
    const bf16* __restrict__ Ahg, const bf16* __restrict__ Alg,
    const bf16* __restrict__ Bhg, const bf16* __restrict__ Blg,
    int m0, int n0, int k0, bf16* base, int tid)
{
    const bf16* gp[4] = {Ahg, Alg, Bhg, Blg};
    #pragma unroll
    for (int a = 0; a < 4; a++) {
        int row0 = (a < 2) ? m0 : n0;
        bf16* sb = base + a*STG_ARR;
        #pragma unroll
        for (int s = 0; s < 4; s++) {
            int idx = tid + s*128;
            int r = idx >> 2;
            int c = (idx & 3) * 8;
            cp16(smem_u32(sb + r*LDKB + c), gp[a] + (size_t)(row0 + r)*DD + k0 + c);
        }
    }
}

__device__ __forceinline__ void gemm_mainloop(
    const bf16* __restrict__ Ahg, const bf16* __restrict__ Alg,
    const bf16* __restrict__ Bhg, const bf16* __restrict__ Blg,
    int m0, int n0, bf16* smem, float acc[4][8][4])
{
    const int tid  = threadIdx.x;
    const int lane = tid & 31;
    const int warp = tid >> 5;
    const int wm = warp >> 1;
    const int wn = warp & 1;

    const int a_r  = lane & 15;
    const int a_c  = (lane >> 4) << 3;
    const int b4_r = ((lane >> 4) << 3) + (lane & 7);
    const int b4_c = ((lane >> 3) & 1) << 3;

    const int NST = DD / 32;

    gemm_load_stage(Ahg, Alg, Bhg, Blg, m0, n0, 0, smem, tid); CP_COMMIT();

    for (int i = 0; i < NST; i++) {
        __syncthreads();
        if (i + 1 < NST)
            gemm_load_stage(Ahg, Alg, Bhg, Blg, m0, n0, (i+1)*32,
                            smem + ((i+1)&1)*STG4, tid);
        CP_COMMIT();
        cp_wait<1>();
        __syncthreads();

        bf16* Ahs = smem + (i&1)*STG4;
        bf16* Als = Ahs + STG_ARR;
        bf16* Bhs = Als + STG_ARR;
        bf16* Bls = Bhs + STG_ARR;

        #pragma unroll
        for (int kk = 0; kk < 32; kk += 16) {
            uint32_t ah[4][4], al[4][4];
            #pragma unroll
            for (int mt = 0; mt < 4; mt++) {
                ldsm_x4(ah[mt], smem_u32(Ahs + (wm*64 + mt*16 + a_r)*LDKB + kk + a_c));
                ldsm_x4(al[mt], smem_u32(Als + (wm*64 + mt*16 + a_r)*LDKB + kk + a_c));
            }
            #pragma unroll
            for (int p = 0; p < 4; p++) {
                uint32_t bh4[4], bl4[4];
                ldsm_x4(bh4, smem_u32(Bhs + (wn*64 + p*16 + b4_r)*LDKB + kk + b4_c));
                ldsm_x4(bl4, smem_u32(Bls + (wn*64 + p*16 + b4_r)*LDKB + kk + b4_c));
                #pragma unroll
                for (int mt = 0; mt < 4; mt++) {
                    mma16816(acc[mt][2*p],   ah[mt], bh4[0], bh4[1]);
                    mma16816(acc[mt][2*p],   ah[mt], bl4[0], bl4[1]);
                    mma16816(acc[mt][2*p],   al[mt], bh4[0], bh4[1]);
                    mma16816(acc[mt][2*p+1], ah[mt], bh4[2], bh4[3]);
                    mma16816(acc[mt][2*p+1], ah[mt], bl4[2], bl4[3]);
                    mma16816(acc[mt][2*p+1], al[mt], bh4[2], bh4[3]);
                }
            }
        }
    }
}

// Q/K projection (z: 0=Q, 1=K). Q: bf16 hi/lo out; K: single bf16 out.
__global__ __launch_bounds__(128) void qk_gemm_tc(int)
{
    extern __shared__ bf16 gsm[];

    const int which = blockIdx.z;
    const bf16* Bhg = (which == 0) ? g_wqh : g_wkh;
    const bf16* Blg = (which == 0) ? g_wql : g_wkl;

    const int m0 = blockIdx.y * 128;
    const int n0 = blockIdx.x * 128;

    float acc[4][8][4];
    #pragma unroll
    for (int i = 0; i < 4; i++)
        #pragma unroll
        for (int j = 0; j < 8; j++)
            #pragma unroll
            for (int r = 0; r < 4; r++) acc[i][j][r] = 0.0f;

    gemm_mainloop(g_xh, g_xl, Bhg, Blg, m0, n0, gsm, acc);

    const int lane = threadIdx.x & 31;
    const int warp = threadIdx.x >> 5;
    const int wm = warp >> 1, wn = warp & 1;
    const int g = lane >> 2, t = lane & 3;
    const int bb = m0 >> 11;
    const int mloc = m0 & 2047;

    if (which == 0) {
        // Q prescale folds 1/8 AND log2e (softmax in log2 domain)
        const float sc = 0.125f * 1.4426950408889634f;
        #pragma unroll
        for (int mt = 0; mt < 4; mt++) {
            #pragma unroll
            for (int nt = 0; nt < 8; nt++) {
                int row = mloc + wm*64 + mt*16 + g;
                int col = n0 + wn*64 + nt*8 + 2*t;
                int hh = col >> 6, e = col & 63;
                uint32_t hv, lv;
                size_t a0 = (((size_t)bb*HH + hh)*TT + row)*HDD + e;
                size_t a1 = (((size_t)bb*HH + hh)*TT + row + 8)*HDD + e;
                split_pack(acc[mt][nt][0]*sc, acc[mt][nt][1]*sc, hv, lv);
                *(uint32_t*)&g_qh[a0] = hv;
                *(uint32_t*)&g_ql[a0] = lv;
                split_pack(acc[mt][nt][2]*sc, acc[mt][nt][3]*sc, hv, lv);
                *(uint32_t*)&g_qh[a1] = hv;
                *(uint32_t*)&g_ql[a1] = lv;
            }
        }
    } else {
        // K: single bf16 (2-term QK^T absorbs the rounding; see error model)
        #pragma unroll
        for (int mt = 0; mt < 4; mt++) {
            #pragma unroll
            for (int nt = 0; nt < 8; nt++) {
                int row = mloc + wm*64 + mt*16 + g;
                int col = n0 + wn*64 + nt*8 + 2*t;
                int hh = col >> 6, e = col & 63;
                size_t a0 = (((size_t)bb*HH + hh)*TT + row)*HDD + e;
                size_t a1 = (((size_t)bb*HH + hh)*TT + row + 8)*HDD + e;
                *(uint32_t*)&g_kh[a0] = bf16pack(acc[mt][nt][0], acc[mt][nt][1]);
                *(uint32_t*)&g_kh[a1] = bf16pack(acc[mt][nt][2], acc[mt][nt][3]);
            }
        }
    }
}

// ============================================================================
// fp16 1-term GEMM (V projection, out projection)
// ============================================================================
#define F16_STG   (128*LDKB)
#define F16_STG2  (2*F16_STG)
#define F16_PIPE_BYTES (2*F16_STG2*2)  // 40960
#define V_SMEM_BYTES 69632

__device__ __forceinline__ void f16_load_stage(
    const __half* __restrict__ Ag, const __half* __restrict__ Bg,
    int m0, int n0, int k0, __half* base, int tid)
{
    #pragma unroll
    for (int s = 0; s < 4; s++) {
        int idx = tid + s*128;
        int r = idx >> 2;
        int c = (idx & 3) * 8;
        cp16(smem_u32(base + r*LDKB + c), Ag + (size_t)(m0 + r)*DD + k0 + c);
        cp16(smem_u32(base + F16_STG + r*LDKB + c), Bg + (size_t)(n0 + r)*DD + k0 + c);
    }
}

__device__ __forceinline__ void f16_gemm_mainloop(
    const __half* __restrict__ Ag, const __half* __restrict__ Bg,
    int m0, int n0, __half* smem, float acc[4][8][4])
{
    const int tid  = threadIdx.x;
    const int lane = tid & 31;
    const int warp = tid >> 5;
    const int wm = warp >> 1;
    const int wn = warp & 1;

    const int a_r  = lane & 15;
    const int a_c  = (lane >> 4) << 3;
    const int b4_r = ((lane >> 4) << 3) + (lane & 7);
    const int b4_c = ((lane >> 3) & 1) << 3;

    const int NST = DD / 32;

    f16_load_stage(Ag, Bg, m0, n0, 0, smem, tid); CP_COMMIT();

    for (int i = 0; i < NST; i++) {
        __syncthreads();
        if (i + 1 < NST)
            f16_load_stage(Ag, Bg, m0, n0, (i+1)*32, smem + ((i+1)&1)*F16_STG2, tid);
        CP_COMMIT();
        cp_wait<1>();
        __syncthreads();

        __half* As = smem + (i&1)*F16_STG2;
        __half* Bs = As + F16_STG;

        #pragma unroll
        for (int kk = 0; kk < 32; kk += 16) {
            uint32_t a4[4][4];
            #pragma unroll
            for (int mt = 0; mt < 4; mt++)
                ldsm_x4(a4[mt], smem_u32(As + (wm*64 + mt*16 + a_r)*LDKB + kk + a_c));
            #pragma unroll
            for (int p = 0; p < 4; p++) {
                uint32_t b4[4];
                ldsm_x4(b4, smem_u32(Bs + (wn*64 + p*16 + b4_r)*LDKB + kk + b4_c));
                #pragma unroll
                for (int mt = 0; mt < 4; mt++) {
                    mma16816h(acc[mt][2*p],   a4[mt], b4[0], b4[1]);
                    mma16816h(acc[mt][2*p+1], a4[mt], b4[2], b4[3]);
                }
            }
        }
    }
}

// V projection: writes V^T [B,H,HD,T] fp16
__global__ __launch_bounds__(128) void v_gemm_f16()
{
    extern __shared__ __half fsm[];

    const int m0 = blockIdx.y * 128;
    const int n0 = blockIdx.x * 128;
    const int tid = threadIdx.x;
    const int bb = m0 >> 11;
    const int mloc = m0 & 2047;

    float acc[4][8][4];
    #pragma unroll
    for (int i = 0; i < 4; i++)
        #pragma unroll
        for (int j = 0; j < 8; j++)
            #pragma unroll
            for (int r = 0; r < 4; r++) acc[i][j][r] = 0.0f;

    f16_gemm_mainloop(g_xf, g_wvf, m0, n0, fsm, acc);

    const int lane = tid & 31;
    const int warp = tid >> 5;
    const int wm = warp >> 1, wn = warp & 1;
    const int g = lane >> 2, t = lane & 3;

    float* Cs = (float*)fsm;
    __syncthreads();
    #pragma unroll
    for (int mt = 0; mt < 4; mt++) {
        #pragma unroll
        for (int nt = 0; nt < 8; nt++) {
            int row = wm*64 + mt*16 + g;
            int col = wn*64 + nt*8 + 2*t;
            Cs[row*133 + col]       = acc[mt][nt][0];
            Cs[row*133 + col + 1]   = acc[mt][nt][1];
            Cs[(row+8)*133 + col]   = acc[mt][nt][2];
            Cs[(row+8)*133 + col+1] = acc[mt][nt][3];
        }
    }
    __syncthreads();
    for (int idx = tid; idx < 2048; idx += 128) {
        int el  = idx >> 4;
        int tch = (idx & 15) * 8;
        __half hv8[8];
        #pragma unroll
        for (int q = 0; q < 8; q++)
            hv8[q] = __float2half_rn(Cs[(tch + q)*133 + el]);
        int col = n0 + el;
        int hh = col >> 6, e = col & 63;
        size_t rb = (((size_t)bb*HH + hh)*HDD + e)*TT + mloc + tch;
        *(uint4*)&g_vtf[rb] = *(uint4*)hv8;
    }
}

// Output projection: out = aof @ Wo^T + bo (fp32 out)
__global__ __launch_bounds__(128) void out_gemm_f16(
    const float* __restrict__ bo, float* __restrict__ outp)
{
    extern __shared__ __half fsm[];

    const int m0 = blockIdx.y * 128;
    const int n0 = blockIdx.x * 128;

    float acc[4][8][4];
    #pragma unroll
    for (int i = 0; i < 4; i++)
        #pragma unroll
        for (int j = 0; j < 8; j++)
            #pragma unroll
            for (int r = 0; r < 4; r++) acc[i][j][r] = 0.0f;

    f16_gemm_mainloop(g_aof, g_wof, m0, n0, fsm, acc);

    const int lane = threadIdx.x & 31;
    const int warp = threadIdx.x >> 5;
    const int wm = warp >> 1, wn = warp & 1;
    const int g = lane >> 2, t = lane & 3;

    #pragma unroll
    for (int mt = 0; mt < 4; mt++) {
        #pragma unroll
        for (int nt = 0; nt < 8; nt++) {
            int row = m0 + wm*64 + mt*16 + g;
            int col = n0 + wn*64 + nt*8 + 2*t;
            float bx = bo[col], by = bo[col+1];
            float2 v01 = make_float2(acc[mt][nt][0] + bx, acc[mt][nt][1] + by);
            float2 v23 = make_float2(acc[mt][nt][2] + bx, acc[mt][nt][3] + by);
            *(float2*)&outp[(size_t)row*DD + col]     = v01;
            *(float2*)&outp[(size_t)(row+8)*DD + col] = v23;
        }
    }
}

// ============================================================================
// Flash attention: q-tile 128, 4 warps x 32 rows. QK 2-term (Qh+Ql)·Kh;
// softmax via ex2.approx.f16x2 (output IS the fp16 P fragment);
// PV fp16 1-term. K/V double-buffered cp.async (2 arrays/stage).
// ============================================================================
#define AQS 72
#define KVARR (64*AQS)
#define ATTN_Q_BYTES (2*128*AQS*2)                      // 36864
#define ATTN_KV_BYTES (2*2*KVARR*2)                     // 36864
#define ATTN_SMEM_BYTES (ATTN_Q_BYTES + ATTN_KV_BYTES)  // 73728

__device__ __forceinline__ void attn_load_kv(
    const bf16* khb, const __half* vhb,
    int j0, bf16* kvbase, int tid)
{
    bf16* Kh = kvbase;
    bf16* Vh = kvbase + KVARR;   // fp16 payload
    #pragma unroll
    for (int s = 0; s < 4; s++) {
        int idx = tid + s*128;
        int r = idx >> 3;
        int c = (idx & 7) * 8;
        cp16(smem_u32(Kh + r*AQS + c), khb + (size_t)(j0 + r)*HDD + c);
        cp16(smem_u32(Vh + r*AQS + c), vhb + (size_t)r*TT + j0 + c);
    }
}

__global__ __launch_bounds__(128) void attn_tc()
{
    extern __shared__ bf16 asmem[];
    bf16* Qh = asmem;
    bf16* Ql = Qh + 128*AQS;
    bf16* KV = Ql + 128*AQS;

    const int bh = blockIdx.y;
    const int hh = bh & (HH-1);
    const int b  = bh >> 4;
    const int qt = gridDim.x - 1 - blockIdx.x;
    const int q0 = qt * 128;
    const int njt = 2*qt + 2;

    const int tid  = threadIdx.x;
    const int lane = tid & 31;
    const int w    = tid >> 5;
    const int g    = lane >> 2;
    const int t    = lane & 3;

    const bf16* __restrict__ qhb = g_qh  + (size_t)bh * TT * HDD;
    const bf16* __restrict__ qlb = g_ql  + (size_t)bh * TT * HDD;
    const bf16* __restrict__ khb = g_kh  + (size_t)bh * TT * HDD;
    const __half* __restrict__ vhb = g_vtf + (size_t)bh * HDD * TT;

    for (int idx = tid; idx < 1024; idx += 128) {
        int r = idx >> 3;
        int c = (idx & 7) * 8;
        *(uint4*)(Qh + r*AQS + c) = *(const uint4*)(qhb + (size_t)(q0 + r)*HDD + c);
        *(uint4*)(Ql + r*AQS + c) = *(const uint4*)(qlb + (size_t)(q0 + r)*HDD + c);
    }

    attn_load_kv(khb, vhb, 0, KV, tid); CP_COMMIT();

    float o[2][8][4];
    float m[4], l[4];
    #pragma unroll
    for (int mf = 0; mf < 2; mf++)
        #pragma unroll
        for (int et = 0; et < 8; et++)
            #pragma unroll
            for (int r = 0; r < 4; r++) o[mf][et][r] = 0.0f;
    #pragma unroll
    for (int i = 0; i < 4; i++) { m[i] = -1e30f; l[i] = 0.0f; }

    const int a_r  = lane & 15;
    const int a_c  = (lane >> 4) << 3;
    const int b4_r = ((lane >> 4) << 3) + (lane & 7);
    const int b4_c = ((lane >> 3) & 1) << 3;

    const int r0w = q0 + w*32;

    for (int jt = 0; jt < njt; jt++) {
        const int j0 = jt * 64;

        __syncthreads();
        if (jt + 1 < njt)
            attn_load_kv(khb, vhb, (jt+1)*64, KV + ((jt+1)&1)*2*KVARR, tid);
        CP_COMMIT();
        cp_wait<1>();
        __syncthreads();

        if (j0 > r0w + 31) continue;

        bf16* Kh = KV + (jt&1)*2*KVARR;
        bf16* Vh = Kh + KVARR;   // fp16 payload

        // S = Q K^T : 2-term (Qh + Ql) x Kh
        float s[2][8][4];
        #pragma unroll
        for (int mf = 0; mf < 2; mf++)
            #pragma unroll
            for (int nt = 0; nt < 8; nt++)
                #pragma unroll
                for (int r = 0; r < 4; r++) s[mf][nt][r] = 0.0f;

        #pragma unroll
        for (int kk = 0; kk < 4; kk++) {
            uint32_t qah[2][4], qal[2][4];
            #pragma unroll
            for (int mf = 0; mf < 2; mf++) {
                ldsm_x4(qah[mf], smem_u32(Qh + (w*32 + mf*16 + a_r)*AQS + kk*16 + a_c));
                ldsm_x4(qal[mf], smem_u32(Ql + (w*32 + mf*16 + a_r)*AQS + kk*16 + a_c));
            }
            #pragma unroll
            for (int p = 0; p < 4; p++) {
                uint32_t kh4[4];
                ldsm_x4(kh4, smem_u32(Kh + (p*16 + b4_r)*AQS + kk*16 + b4_c));
                #pragma unroll
                for (int mf = 0; mf < 2; mf++) {
                    mma16816(s[mf][2*p],   qah[mf], kh4[0], kh4[1]);
                    mma16816(s[mf][2*p],   qal[mf], kh4[0], kh4[1]);
                    mma16816(s[mf][2*p+1], qah[mf], kh4[2], kh4[3]);
                    mma16816(s[mf][2*p+1], qal[mf], kh4[2], kh4[3]);
                }
            }
        }

        if (j0 + 63 > r0w) {
            #pragma unroll
            for (int mf = 0; mf < 2; mf++) {
                int r0 = r0w + mf*16 + g;
                int r1 = r0 + 8;
                #pragma unroll
                for (int nt = 0; nt < 8; nt++) {
                    int c0 = j0 + nt*8 + 2*t;
                    if (c0     > r0) s[mf][nt][0] = -1e30f;
                    if (c0 + 1 > r0) s[mf][nt][1] = -1e30f;
                    if (c0     > r1) s[mf][nt][2] = -1e30f;
                    if (c0 + 1 > r1) s[mf][nt][3] = -1e30f;
                }
            }
        }

        // Online softmax in log2 domain; ex2.f16x2 output = fp16 P fragments
        uint32_t ph[2][8][2];
        #pragma unroll
        for (int mf = 0; mf < 2; mf++) {
            float mx0 = -1e30f, mx1 = -1e30f;
            #pragma unroll
            for (int nt = 0; nt < 8; nt++) {
                mx0 = fmaxf(mx0, fmaxf(s[mf][nt][0], s[mf][nt][1]));
                mx1 = fmaxf(mx1, fmaxf(s[mf][nt][2], s[mf][nt][3]));
            }
            #pragma unroll
            for (int off = 1; off <= 2; off <<= 1) {
                mx0 = fmaxf(mx0, __shfl_xor_sync(0xffffffffu, mx0, off));
                mx1 = fmaxf(mx1, __shfl_xor_sync(0xffffffffu, mx1, off));
            }
            float mn0 = fmaxf(m[mf*2],   mx0);
            float mn1 = fmaxf(m[mf*2+1], mx1);
            float f0 = ex2f(m[mf*2]   - mn0);
            float f1 = ex2f(m[mf*2+1] - mn1);
            float rs0 = 0.0f, rs1 = 0.0f;
            #pragma unroll
            for (int nt = 0; nt < 8; nt++) {
                uint32_t w0 = h2ex2(f16pack(s[mf][nt][0] - mn0, s[mf][nt][1] - mn0));
                uint32_t w1 = h2ex2(f16pack(s[mf][nt][2] - mn1, s[mf][nt][3] - mn1));
                ph[mf][nt][0] = w0;
                ph[mf][nt][1] = w1;
                float2 fa = __half22float2(*(__half2*)&w0);
                float2 fb = __half22float2(*(__half2*)&w1);
                rs0 += fa.x + fa.y;
                rs1 += fb.x + fb.y;
            }
            #pragma unroll
            for (int off = 1; off <= 2; off <<= 1) {
                rs0 += __shfl_xor_sync(0xffffffffu, rs0, off);
                rs1 += __shfl_xor_sync(0xffffffffu, rs1, off);
            }
            l[mf*2]   = l[mf*2]   * f0 + rs0;
            l[mf*2+1] = l[mf*2+1] * f1 + rs1;
            m[mf*2]   = mn0;
            m[mf*2+1] = mn1;
            #pragma unroll
            for (int et = 0; et < 8; et++) {
                o[mf][et][0] *= f0; o[mf][et][1] *= f0;
                o[mf][et][2] *= f1; o[mf][et][3] *= f1;
            }
        }

        // P*V: fp16 1-term
        #pragma unroll
        for (int kt = 0; kt < 4; kt++) {
            uint32_t pa[2][4];
            #pragma unroll
            for (int mf = 0; mf < 2; mf++) {
                pa[mf][0] = ph[mf][2*kt][0];
                pa[mf][1] = ph[mf][2*kt][1];
                pa[mf][2] = ph[mf][2*kt+1][0];
                pa[mf][3] = ph[mf][2*kt+1][1];
            }
            #pragma unroll
            for (int pe = 0; pe < 4; pe++) {
                uint32_t vh4[4];
                ldsm_x4(vh4, smem_u32(Vh + (pe*16 + b4_r)*AQS + kt*16 + b4_c));
                #pragma unroll
                for (int mf = 0; mf < 2; mf++) {
                    mma16816h(o[mf][2*pe],   pa[mf], vh4[0], vh4[1]);
                    mma16816h(o[mf][2*pe+1], pa[mf], vh4[2], vh4[3]);
                }
            }
        }
    }

    // Epilogue: normalize, write fp16 attn output [B,T,D]
    #pragma unroll
    for (int mf = 0; mf < 2; mf++) {
        float inv0 = 1.0f / l[mf*2];
        float inv1 = 1.0f / l[mf*2+1];
        int tq = q0 + w*32 + mf*16 + g;
        #pragma unroll
        for (int et = 0; et < 8; et++) {
            int col = hh*HDD + et*8 + 2*t;
            size_t a0 = ((size_t)b*TT + tq)*DD + col;
            size_t a1 = ((size_t)b*TT + tq + 8)*DD + col;
            *(uint32_t*)&g_aof[a0] = f16pack(o[mf][et][0]*inv0, o[mf][et][1]*inv0);
            *(uint32_t*)&g_aof[a1] = f16pack(o[mf][et][2]*inv1, o[mf][et][3]*inv1);
        }
    }
}

// ============================================================================
// Launch
// ============================================================================
extern "C" void kernel_launch(void* const* d_in, const int* in_sizes, int n_in,
                              void* d_out, int out_size)
{
    const float* x  = (const float*)d_in[0];
    const float* Wq = (const float*)d_in[1];
    const float* Wk = (const float*)d_in[2];
    const float* Wv = (const float*)d_in[3];
    const float* Wo = (const float*)d_in[4];
    const float* bo = (const float*)d_in[5];
    float* out = (float*)d_out;

    cudaFuncSetAttribute(qk_gemm_tc, cudaFuncAttributeMaxDynamicSharedMemorySize,
                         GEMM_SMEM_BYTES);
    cudaFuncSetAttribute(v_gemm_f16, cudaFuncAttributeMaxDynamicSharedMemorySize,
                         V_SMEM_BYTES);
    cudaFuncSetAttribute(out_gemm_f16, cudaFuncAttributeMaxDynamicSharedMemorySize,
                         F16_PIPE_BYTES);
    cudaFuncSetAttribute(attn_tc, cudaFuncAttributeMaxDynamicSharedMemorySize,
                         ATTN_SMEM_BYTES);

    int nx = MTOT*DD/4, nw = DD*DD/4;
    convert_x_k<<<nx/256, 256>>>((const float4*)x);
    convert_w_k<<<dim3(nw/256, 4), 256>>>((const float4*)Wq, (const float4*)Wk,
                                          (const float4*)Wv, (const float4*)Wo);

    qk_gemm_tc<<<dim3(DD/128, MTOT/128, 2), 128, GEMM_SMEM_BYTES>>>(0);
    v_gemm_f16<<<dim3(DD/128, MTOT/128), 128, V_SMEM_BYTES>>>();
    attn_tc<<<dim3(TT/128, BB*HH), 128, ATTN_SMEM_BYTES>>>();
    out_gemm_f16<<<dim3(DD/128, MTOT/128), 128, F16_PIPE_BYTES>>>(bo, out);
}

// round 13
// speedup vs baseline: 5.7153x; 1.0719x over previous
#include <cuda_runtime.h>
#include <cuda_bf16.h>
#include <cuda_fp16.h>
#include <cstdint>
#include <math.h>

#define BB   4
#define TT   2048
#define DD   1024
#define HH   16
#define HDD  64
#define MTOT (BB*TT)   // 8192

typedef __nv_bfloat16  bf16;
typedef __nv_bfloat162 bf162;

// ---- precision-split globals ----
__device__ bf16   g_xh [(size_t)MTOT*DD], g_xl [(size_t)MTOT*DD];  // x bf16 hi/lo (QK proj)
__device__ __half g_xf [(size_t)MTOT*DD];                          // x fp16 (V proj)
__device__ bf16   g_wqh[(size_t)DD*DD],   g_wql[(size_t)DD*DD];
__device__ bf16   g_wkh[(size_t)DD*DD],   g_wkl[(size_t)DD*DD];
__device__ __half g_wvf[(size_t)DD*DD];                            // Wv fp16
__device__ __half g_wof[(size_t)DD*DD];                            // Wo fp16
__device__ bf16   g_qh [(size_t)MTOT*DD], g_ql [(size_t)MTOT*DD];  // [B,H,T,HD] prescaled log2e/8
__device__ bf16   g_kh [(size_t)MTOT*DD];                          // [B,H,T,HD] K single bf16
__device__ __half g_vtf[(size_t)MTOT*DD];                          // V^T [B,H,HD,T] fp16
__device__ __half g_aof[(size_t)MTOT*DD];                          // attn out [B,T,D] fp16

// ============================================================================
// Helpers
// ============================================================================
__device__ __forceinline__ uint32_t smem_u32(const void* p) {
    return (uint32_t)__cvta_generic_to_shared(p);
}
__device__ __forceinline__ void ldsm_x4(uint32_t r[4], uint32_t addr) {
    asm volatile("ldmatrix.sync.aligned.m8n8.x4.shared.b16 {%0,%1,%2,%3}, [%4];"
                 : "=r"(r[0]), "=r"(r[1]), "=r"(r[2]), "=r"(r[3]) : "r"(addr));
}
__device__ __forceinline__ void mma16816(float d[4], const uint32_t a[4], const uint32_t b0, const uint32_t b1) {
    asm volatile(
        "mma.sync.aligned.m16n8k16.row.col.f32.bf16.bf16.f32 "
        "{%0,%1,%2,%3}, {%4,%5,%6,%7}, {%8,%9}, {%0,%1,%2,%3};"
        : "+f"(d[0]), "+f"(d[1]), "+f"(d[2]), "+f"(d[3])
        : "r"(a[0]), "r"(a[1]), "r"(a[2]), "r"(a[3]), "r"(b0), "r"(b1));
}
__device__ __forceinline__ void mma16816h(float d[4], const uint32_t a[4], const uint32_t b0, const uint32_t b1) {
    asm volatile(
        "mma.sync.aligned.m16n8k16.row.col.f32.f16.f16.f32 "
        "{%0,%1,%2,%3}, {%4,%5,%6,%7}, {%8,%9}, {%0,%1,%2,%3};"
        : "+f"(d[0]), "+f"(d[1]), "+f"(d[2]), "+f"(d[3])
        : "r"(a[0]), "r"(a[1]), "r"(a[2]), "r"(a[3]), "r"(b0), "r"(b1));
}
__device__ __forceinline__ void split2(float x, float y, bf162& h, bf162& l) {
    bf16 hx = __float2bfloat16(x);
    bf16 hy = __float2bfloat16(y);
    h = __halves2bfloat162(hx, hy);
    l = __halves2bfloat162(__float2bfloat16(x - __bfloat162float(hx)),
                           __float2bfloat16(y - __bfloat162float(hy)));
}
__device__ __forceinline__ void split_pack(float x, float y, uint32_t& h, uint32_t& l) {
    uint32_t hp;
    asm("cvt.rn.bf16x2.f32 %0, %1, %2;" : "=r"(hp) : "f"(y), "f"(x));
    float xh = __uint_as_float(hp << 16);
    float yh = __uint_as_float(hp & 0xFFFF0000u);
    uint32_t lp;
    asm("cvt.rn.bf16x2.f32 %0, %1, %2;" : "=r"(lp) : "f"(y - yh), "f"(x - xh));
    h = hp; l = lp;
}
__device__ __forceinline__ uint32_t bf16pack(float x, float y) {
    uint32_t r;
    asm("cvt.rn.bf16x2.f32 %0, %1, %2;" : "=r"(r) : "f"(y), "f"(x));
    return r;
}
__device__ __forceinline__ uint32_t f16pack(float x, float y) {
    uint32_t r;
    asm("cvt.rn.f16x2.f32 %0, %1, %2;" : "=r"(r) : "f"(y), "f"(x));
    return r;
}
__device__ __forceinline__ uint32_t h2ex2(uint32_t x) {
    uint32_t r;
    asm("ex2.approx.f16x2 %0, %1;" : "=r"(r) : "r"(x));
    return r;
}
__device__ __forceinline__ float ex2f(float x) {
    float r;
    asm("ex2.approx.f32 %0, %1;" : "=f"(r) : "f"(x));
    return r;
}
__device__ __forceinline__ void cp16(uint32_t s, const void* g) {
    asm volatile("cp.async.ca.shared.global [%0], [%1], 16;\n" :: "r"(s), "l"(g));
}
#define CP_COMMIT() asm volatile("cp.async.commit_group;\n" ::: "memory")
template<int N> __device__ __forceinline__ void cp_wait() {
    asm volatile("cp.async.wait_group %0;\n" :: "n"(N) : "memory");
}

// ============================================================================
// Convert kernels
// ============================================================================
__global__ __launch_bounds__(256) void convert_x_k(const float4* __restrict__ src)
{
    int i = blockIdx.x * 256 + threadIdx.x;
    float4 v = src[i];
    bf162 h0, l0, h1, l1;
    split2(v.x, v.y, h0, l0);
    split2(v.z, v.w, h1, l1);
    *(bf162*)(g_xh + (size_t)i*4)     = h0;
    *(bf162*)(g_xh + (size_t)i*4 + 2) = h1;
    *(bf162*)(g_xl + (size_t)i*4)     = l0;
    *(bf162*)(g_xl + (size_t)i*4 + 2) = l1;
    *(__half2*)(g_xf + (size_t)i*4)     = __floats2half2_rn(v.x, v.y);
    *(__half2*)(g_xf + (size_t)i*4 + 2) = __floats2half2_rn(v.z, v.w);
}
__global__ __launch_bounds__(256) void convert_w_k(
    const float4* __restrict__ wq, const float4* __restrict__ wk,
    const float4* __restrict__ wv, const float4* __restrict__ wo)
{
    int which = blockIdx.y;
    int i = blockIdx.x * 256 + threadIdx.x;
    if (which < 2) {
        const float4* src = (which == 0) ? wq : wk;
        bf16* ho = (which == 0) ? g_wqh : g_wkh;
        bf16* lo = (which == 0) ? g_wql : g_wkl;
        float4 v = src[i];
        bf162 h0, l0, h1, l1;
        split2(v.x, v.y, h0, l0);
        split2(v.z, v.w, h1, l1);
        *(bf162*)(ho + (size_t)i*4)     = h0;
        *(bf162*)(ho + (size_t)i*4 + 2) = h1;
        *(bf162*)(lo + (size_t)i*4)     = l0;
        *(bf162*)(lo + (size_t)i*4 + 2) = l1;
    } else {
        const float4* src = (which == 2) ? wv : wo;
        __half* ho = (which == 2) ? g_wvf : g_wof;
        float4 v = src[i];
        *(__half2*)(ho + (size_t)i*4)     = __floats2half2_rn(v.x, v.y);
        *(__half2*)(ho + (size_t)i*4 + 2) = __floats2half2_rn(v.z, v.w);
    }
}

// ============================================================================
// GEMM mainloops (bf16 3-term; fp16 1-term). CTA 128x128, 4 warps, 64x64.
// ============================================================================
#define LDKB 40
#define STG_ARR (128*LDKB)
#define STG4    (4*STG_ARR)
#define GEMM_SMEM_BYTES (2*STG4*2)  // 81920

__device__ __forceinline__ void gemm_load_stage(
    const bf16* __restrict__ Ahg, const bf16* __restrict__ Alg,
    const bf16* __restrict__ Bhg, const bf16* __restrict__ Blg,
    int m0, int n0, int k0, bf16* base, int tid)
{
    const bf16* gp[4] = {Ahg, Alg, Bhg, Blg};
    #pragma unroll
    for (int a = 0; a < 4; a++) {
        int row0 = (a < 2) ? m0 : n0;
        bf16* sb = base + a*STG_ARR;
        #pragma unroll
        for (int s = 0; s < 4; s++) {
            int idx = tid + s*128;
            int r = idx >> 2;
            int c = (idx & 3) * 8;
            cp16(smem_u32(sb + r*LDKB + c), gp[a] + (size_t)(row0 + r)*DD + k0 + c);
        }
    }
}

__device__ __forceinline__ void gemm_mainloop(
    const bf16* __restrict__ Ahg, const bf16* __restrict__ Alg,
    const bf16* __restrict__ Bhg, const bf16* __restrict__ Blg,
    int m0, int n0, bf16* smem, float acc[4][8][4])
{
    const int tid  = threadIdx.x;
    const int lane = tid & 31;
    const int warp = tid >> 5;
    const int wm = warp >> 1;
    const int wn = warp & 1;

    const int a_r  = lane & 15;
    const int a_c  = (lane >> 4) << 3;
    const int b4_r = ((lane >> 4) << 3) + (lane & 7);
    const int b4_c = ((lane >> 3) & 1) << 3;

    const int NST = DD / 32;

    gemm_load_stage(Ahg, Alg, Bhg, Blg, m0, n0, 0, smem, tid); CP_COMMIT();

    for (int i = 0; i < NST; i++) {
        __syncthreads();
        if (i + 1 < NST)
            gemm_load_stage(Ahg, Alg, Bhg, Blg, m0, n0, (i+1)*32,
                            smem + ((i+1)&1)*STG4, tid);
        CP_COMMIT();
        cp_wait<1>();
        __syncthreads();

        bf16* Ahs = smem + (i&1)*STG4;
        bf16* Als = Ahs + STG_ARR;
        bf16* Bhs = Als + STG_ARR;
        bf16* Bls = Bhs + STG_ARR;

        #pragma unroll
        for (int kk = 0; kk < 32; kk += 16) {
            uint32_t ah[4][4], al[4][4];
            #pragma unroll
            for (int mt = 0; mt < 4; mt++) {
                ldsm_x4(ah[mt], smem_u32(Ahs + (wm*64 + mt*16 + a_r)*LDKB + kk + a_c));
                ldsm_x4(al[mt], smem_u32(Als + (wm*64 + mt*16 + a_r)*LDKB + kk + a_c));
            }
            #pragma unroll
            for (int p = 0; p < 4; p++) {
                uint32_t bh4[4], bl4[4];
                ldsm_x4(bh4, smem_u32(Bhs + (wn*64 + p*16 + b4_r)*LDKB + kk + b4_c));
                ldsm_x4(bl4, smem_u32(Bls + (wn*64 + p*16 + b4_r)*LDKB + kk + b4_c));
                #pragma unroll
                for (int mt = 0; mt < 4; mt++) {
                    mma16816(acc[mt][2*p],   ah[mt], bh4[0], bh4[1]);
                    mma16816(acc[mt][2*p],   ah[mt], bl4[0], bl4[1]);
                    mma16816(acc[mt][2*p],   al[mt], bh4[0], bh4[1]);
                    mma16816(acc[mt][2*p+1], ah[mt], bh4[2], bh4[3]);
                    mma16816(acc[mt][2*p+1], ah[mt], bl4[2], bl4[3]);
                    mma16816(acc[mt][2*p+1], al[mt], bh4[2], bh4[3]);
                }
            }
        }
    }
}

#define F16_STG   (128*LDKB)
#define F16_STG2  (2*F16_STG)

__device__ __forceinline__ void f16_load_stage(
    const __half* __restrict__ Ag, const __half* __restrict__ Bg,
    int m0, int n0, int k0, __half* base, int tid)
{
    #pragma unroll
    for (int s = 0; s < 4; s++) {
        int idx = tid + s*128;
        int r = idx >> 2;
        int c = (idx & 3) * 8;
        cp16(smem_u32(base + r*LDKB + c), Ag + (size_t)(m0 + r)*DD + k0 + c);
        cp16(smem_u32(base + F16_STG + r*LDKB + c), Bg + (size_t)(n0 + r)*DD + k0 + c);
    }
}

__device__ __forceinline__ void f16_gemm_mainloop(
    const __half* __restrict__ Ag, const __half* __restrict__ Bg,
    int m0, int n0, __half* smem, float acc[4][8][4])
{
    const int tid  = threadIdx.x;
    const int lane = tid & 31;
    const int warp = tid >> 5;
    const int wm = warp >> 1;
    const int wn = warp & 1;

    const int a_r  = lane & 15;
    const int a_c  = (lane >> 4) << 3;
    const int b4_r = ((lane >> 4) << 3) + (lane & 7);
    const int b4_c = ((lane >> 3) & 1) << 3;

    const int NST = DD / 32;

    f16_load_stage(Ag, Bg, m0, n0, 0, smem, tid); CP_COMMIT();

    for (int i = 0; i < NST; i++) {
        __syncthreads();
        if (i + 1 < NST)
            f16_load_stage(Ag, Bg, m0, n0, (i+1)*32, smem + ((i+1)&1)*F16_STG2, tid);
        CP_COMMIT();
        cp_wait<1>();
        __syncthreads();

        __half* As = smem + (i&1)*F16_STG2;
        __half* Bs = As + F16_STG;

        #pragma unroll
        for (int kk = 0; kk < 32; kk += 16) {
            uint32_t a4[4][4];
            #pragma unroll
            for (int mt = 0; mt < 4; mt++)
                ldsm_x4(a4[mt], smem_u32(As + (wm*64 + mt*16 + a_r)*LDKB + kk + a_c));
            #pragma unroll
            for (int p = 0; p < 4; p++) {
                uint32_t b4[4];
                ldsm_x4(b4, smem_u32(Bs + (wn*64 + p*16 + b4_r)*LDKB + kk + b4_c));
                #pragma unroll
                for (int mt = 0; mt < 4; mt++) {
                    mma16816h(acc[mt][2*p],   a4[mt], b4[0], b4[1]);
                    mma16816h(acc[mt][2*p+1], a4[mt], b4[2], b4[3]);
                }
            }
        }
    }
}

// ============================================================================
// Merged QKV projection: grid (8, 64, 3). z=0 Q (bf16 3-term), z=1 K, z=2 V (fp16).
// One launch packs all 1536 CTAs -> fewer partial-wave tails.
// ============================================================================
__global__ __launch_bounds__(128) void qkv_proj_tc()
{
    extern __shared__ char dsm[];

    const int which = blockIdx.z;
    const int m0 = blockIdx.y * 128;
    const int n0 = blockIdx.x * 128;
    const int tid = threadIdx.x;
    const int bb = m0 >> 11;
    const int mloc = m0 & 2047;

    float acc[4][8][4];
    #pragma unroll
    for (int i = 0; i < 4; i++)
        #pragma unroll
        for (int j = 0; j < 8; j++)
            #pragma unroll
            for (int r = 0; r < 4; r++) acc[i][j][r] = 0.0f;

    const int lane = tid & 31;
    const int warp = tid >> 5;
    const int wm = warp >> 1, wn = warp & 1;
    const int g = lane >> 2, t = lane & 3;

    if (which == 2) {
        // V: fp16 1-term, write V^T [B,H,HD,T]
        __half* fsm = (__half*)dsm;
        f16_gemm_mainloop(g_xf, g_wvf, m0, n0, fsm, acc);

        float* Cs = (float*)dsm;
        __syncthreads();
        #pragma unroll
        for (int mt = 0; mt < 4; mt++) {
            #pragma unroll
            for (int nt = 0; nt < 8; nt++) {
                int row = wm*64 + mt*16 + g;
                int col = wn*64 + nt*8 + 2*t;
                Cs[row*133 + col]       = acc[mt][nt][0];
                Cs[row*133 + col + 1]   = acc[mt][nt][1];
                Cs[(row+8)*133 + col]   = acc[mt][nt][2];
                Cs[(row+8)*133 + col+1] = acc[mt][nt][3];
            }
        }
        __syncthreads();
        for (int idx = tid; idx < 2048; idx += 128) {
            int el  = idx >> 4;
            int tch = (idx & 15) * 8;
            __half hv8[8];
            #pragma unroll
            for (int q = 0; q < 8; q++)
                hv8[q] = __float2half_rn(Cs[(tch + q)*133 + el]);
            int col = n0 + el;
            int hh = col >> 6, e = col & 63;
            size_t rb = (((size_t)bb*HH + hh)*HDD + e)*TT + mloc + tch;
            *(uint4*)&g_vtf[rb] = *(uint4*)hv8;
        }
        return;
    }

    bf16* gsm = (bf16*)dsm;
    const bf16* Bhg = (which == 0) ? g_wqh : g_wkh;
    const bf16* Blg = (which == 0) ? g_wql : g_wkl;
    gemm_mainloop(g_xh, g_xl, Bhg, Blg, m0, n0, gsm, acc);

    if (which == 0) {
        const float sc = 0.125f * 1.4426950408889634f;
        #pragma unroll
        for (int mt = 0; mt < 4; mt++) {
            #pragma unroll
            for (int nt = 0; nt < 8; nt++) {
                int row = mloc + wm*64 + mt*16 + g;
                int col = n0 + wn*64 + nt*8 + 2*t;
                int hh = col >> 6, e = col & 63;
                uint32_t hv, lv;
                size_t a0 = (((size_t)bb*HH + hh)*TT + row)*HDD + e;
                size_t a1 = (((size_t)bb*HH + hh)*TT + row + 8)*HDD + e;
                split_pack(acc[mt][nt][0]*sc, acc[mt][nt][1]*sc, hv, lv);
                *(uint32_t*)&g_qh[a0] = hv;
                *(uint32_t*)&g_ql[a0] = lv;
                split_pack(acc[mt][nt][2]*sc, acc[mt][nt][3]*sc, hv, lv);
                *(uint32_t*)&g_qh[a1] = hv;
                *(uint32_t*)&g_ql[a1] = lv;
            }
        }
    } else {
        #pragma unroll
        for (int mt = 0; mt < 4; mt++) {
            #pragma unroll
            for (int nt = 0; nt < 8; nt++) {
                int row = mloc + wm*64 + mt*16 + g;
                int col = n0 + wn*64 + nt*8 + 2*t;
                int hh = col >> 6, e = col & 63;
                size_t a0 = (((size_t)bb*HH + hh)*TT + row)*HDD + e;
                size_t a1 = (((size_t)bb*HH + hh)*TT + row + 8)*HDD + e;
                *(uint32_t*)&g_kh[a0] = bf16pack(acc[mt][nt][0], acc[mt][nt][1]);
                *(uint32_t*)&g_kh[a1] = bf16pack(acc[mt][nt][2], acc[mt][nt][3]);
            }
        }
    }
}

// Output projection: out = aof @ Wo^T + bo (fp32 out)
#define F16_PIPE_BYTES (2*F16_STG2*2)  // 40960
__global__ __launch_bounds__(128) void out_gemm_f16(
    const float* __restrict__ bo, float* __restrict__ outp)
{
    extern __shared__ __half fsm[];

    const int m0 = blockIdx.y * 128;
    const int n0 = blockIdx.x * 128;

    float acc[4][8][4];
    #pragma unroll
    for (int i = 0; i < 4; i++)
        #pragma unroll
        for (int j = 0; j < 8; j++)
            #pragma unroll
            for (int r = 0; r < 4; r++) acc[i][j][r] = 0.0f;

    f16_gemm_mainloop(g_aof, g_wof, m0, n0, fsm, acc);

    const int lane = threadIdx.x & 31;
    const int warp = threadIdx.x >> 5;
    const int wm = warp >> 1, wn = warp & 1;
    const int g = lane >> 2, t = lane & 3;

    #pragma unroll
    for (int mt = 0; mt < 4; mt++) {
        #pragma unroll
        for (int nt = 0; nt < 8; nt++) {
            int row = m0 + wm*64 + mt*16 + g;
            int col = n0 + wn*64 + nt*8 + 2*t;
            float bx = bo[col], by = bo[col+1];
            float2 v01 = make_float2(acc[mt][nt][0] + bx, acc[mt][nt][1] + by);
            float2 v23 = make_float2(acc[mt][nt][2] + bx, acc[mt][nt][3] + by);
            *(float2*)&outp[(size_t)row*DD + col]     = v01;
            *(float2*)&outp[(size_t)(row+8)*DD + col] = v23;
        }
    }
}

// ============================================================================
// Flash attention: q-tile 128, 4 warps x 32 rows. QK 2-term (Qh+Ql)·Kh;
// softmax ex2.f16x2 -> P fragments; PV fp16 1-term.
// __launch_bounds__(128, 3): 3 CTAs/SM (smem 73.7KB x3 = 221KB fits).
// ============================================================================
#define AQS 72
#define KVARR (64*AQS)
#define ATTN_Q_BYTES (2*128*AQS*2)                      // 36864
#define ATTN_KV_BYTES (2*2*KVARR*2)                     // 36864
#define ATTN_SMEM_BYTES (ATTN_Q_BYTES + ATTN_KV_BYTES)  // 73728

__device__ __forceinline__ void attn_load_kv(
    const bf16* khb, const __half* vhb,
    int j0, bf16* kvbase, int tid)
{
    bf16* Kh = kvbase;
    bf16* Vh = kvbase + KVARR;   // fp16 payload
    #pragma unroll
    for (int s = 0; s < 4; s++) {
        int idx = tid + s*128;
        int r = idx >> 3;
        int c = (idx & 7) * 8;
        cp16(smem_u32(Kh + r*AQS + c), khb + (size_t)(j0 + r)*HDD + c);
        cp16(smem_u32(Vh + r*AQS + c), vhb + (size_t)r*TT + j0 + c);
    }
}

__global__ __launch_bounds__(128, 3) void attn_tc()
{
    extern __shared__ bf16 asmem[];
    bf16* Qh = asmem;
    bf16* Ql = Qh + 128*AQS;
    bf16* KV = Ql + 128*AQS;

    const int bh = blockIdx.y;
    const int hh = bh & (HH-1);
    const int b  = bh >> 4;
    const int qt = gridDim.x - 1 - blockIdx.x;
    const int q0 = qt * 128;
    const int njt = 2*qt + 2;

    const int tid  = threadIdx.x;
    const int lane = tid & 31;
    const int w    = tid >> 5;
    const int g    = lane >> 2;
    const int t    = lane & 3;

    const bf16* __restrict__ qhb = g_qh  + (size_t)bh * TT * HDD;
    const bf16* __restrict__ qlb = g_ql  + (size_t)bh * TT * HDD;
    const bf16* __restrict__ khb = g_kh  + (size_t)bh * TT * HDD;
    const __half* __restrict__ vhb = g_vtf + (size_t)bh * HDD * TT;

    for (int idx = tid; idx < 1024; idx += 128) {
        int r = idx >> 3;
        int c = (idx & 7) * 8;
        *(uint4*)(Qh + r*AQS + c) = *(const uint4*)(qhb + (size_t)(q0 + r)*HDD + c);
        *(uint4*)(Ql + r*AQS + c) = *(const uint4*)(qlb + (size_t)(q0 + r)*HDD + c);
    }

    attn_load_kv(khb, vhb, 0, KV, tid); CP_COMMIT();

    float o[2][8][4];
    float m[4], l[4];
    #pragma unroll
    for (int mf = 0; mf < 2; mf++)
        #pragma unroll
        for (int et = 0; et < 8; et++)
            #pragma unroll
            for (int r = 0; r < 4; r++) o[mf][et][r] = 0.0f;
    #pragma unroll
    for (int i = 0; i < 4; i++) { m[i] = -1e30f; l[i] = 0.0f; }

    const int a_r  = lane & 15;
    const int a_c  = (lane >> 4) << 3;
    const int b4_r = ((lane >> 4) << 3) + (lane & 7);
    const int b4_c = ((lane >> 3) & 1) << 3;

    const int r0w = q0 + w*32;

    for (int jt = 0; jt < njt; jt++) {
        const int j0 = jt * 64;

        __syncthreads();
        if (jt + 1 < njt)
            attn_load_kv(khb, vhb, (jt+1)*64, KV + ((jt+1)&1)*2*KVARR, tid);
        CP_COMMIT();
        cp_wait<1>();
        __syncthreads();

        if (j0 > r0w + 31) continue;

        bf16* Kh = KV + (jt&1)*2*KVARR;
        bf16* Vh = Kh + KVARR;   // fp16 payload

        // S = Q K^T : 2-term (Qh + Ql) x Kh
        float s[2][8][4];
        #pragma unroll
        for (int mf = 0; mf < 2; mf++)
            #pragma unroll
            for (int nt = 0; nt < 8; nt++)
                #pragma unroll
                for (int r = 0; r < 4; r++) s[mf][nt][r] = 0.0f;

        #pragma unroll
        for (int kk = 0; kk < 4; kk++) {
            uint32_t qah[2][4], qal[2][4];
            #pragma unroll
            for (int mf = 0; mf < 2; mf++) {
                ldsm_x4(qah[mf], smem_u32(Qh + (w*32 + mf*16 + a_r)*AQS + kk*16 + a_c));
                ldsm_x4(qal[mf], smem_u32(Ql + (w*32 + mf*16 + a_r)*AQS + kk*16 + a_c));
            }
            #pragma unroll
            for (int p = 0; p < 4; p++) {
                uint32_t kh4[4];
                ldsm_x4(kh4, smem_u32(Kh + (p*16 + b4_r)*AQS + kk*16 + b4_c));
                #pragma unroll
                for (int mf = 0; mf < 2; mf++) {
                    mma16816(s[mf][2*p],   qah[mf], kh4[0], kh4[1]);
                    mma16816(s[mf][2*p],   qal[mf], kh4[0], kh4[1]);
                    mma16816(s[mf][2*p+1], qah[mf], kh4[2], kh4[3]);
                    mma16816(s[mf][2*p+1], qal[mf], kh4[2], kh4[3]);
                }
            }
        }

        if (j0 + 63 > r0w) {
            #pragma unroll
            for (int mf = 0; mf < 2; mf++) {
                int r0 = r0w + mf*16 + g;
                int r1 = r0 + 8;
                #pragma unroll
                for (int nt = 0; nt < 8; nt++) {
                    int c0 = j0 + nt*8 + 2*t;
                    if (c0     > r0) s[mf][nt][0] = -1e30f;
                    if (c0 + 1 > r0) s[mf][nt][1] = -1e30f;
                    if (c0     > r1) s[mf][nt][2] = -1e30f;
                    if (c0 + 1 > r1) s[mf][nt][3] = -1e30f;
                }
            }
        }

        // Online softmax in log2 domain; ex2.f16x2 output = fp16 P fragments
        uint32_t ph[2][8][2];
        #pragma unroll
        for (int mf = 0; mf < 2; mf++) {
            float mx0 = -1e30f, mx1 = -1e30f;
            #pragma unroll
            for (int nt = 0; nt < 8; nt++) {
                mx0 = fmaxf(mx0, fmaxf(s[mf][nt][0], s[mf][nt][1]));
                mx1 = fmaxf(mx1, fmaxf(s[mf][nt][2], s[mf][nt][3]));
            }
            #pragma unroll
            for (int off = 1; off <= 2; off <<= 1) {
                mx0 = fmaxf(mx0, __shfl_xor_sync(0xffffffffu, mx0, off));
                mx1 = fmaxf(mx1, __shfl_xor_sync(0xffffffffu, mx1, off));
            }
            float mn0 = fmaxf(m[mf*2],   mx0);
            float mn1 = fmaxf(m[mf*2+1], mx1);
            float f0 = ex2f(m[mf*2]   - mn0);
            float f1 = ex2f(m[mf*2+1] - mn1);
            float rs0 = 0.0f, rs1 = 0.0f;
            #pragma unroll
            for (int nt = 0; nt < 8; nt++) {
                uint32_t w0 = h2ex2(f16pack(s[mf][nt][0] - mn0, s[mf][nt][1] - mn0));
                uint32_t w1 = h2ex2(f16pack(s[mf][nt][2] - mn1, s[mf][nt][3] - mn1));
                ph[mf][nt][0] = w0;
                ph[mf][nt][1] = w1;
                float2 fa = __half22float2(*(__half2*)&w0);
                float2 fb = __half22float2(*(__half2*)&w1);
                rs0 += fa.x + fa.y;
                rs1 += fb.x + fb.y;
            }
            #pragma unroll
            for (int off = 1; off <= 2; off <<= 1) {
                rs0 += __shfl_xor_sync(0xffffffffu, rs0, off);
                rs1 += __shfl_xor_sync(0xffffffffu, rs1, off);
            }
            l[mf*2]   = l[mf*2]   * f0 + rs0;
            l[mf*2+1] = l[mf*2+1] * f1 + rs1;
            m[mf*2]   = mn0;
            m[mf*2+1] = mn1;
            #pragma unroll
            for (int et = 0; et < 8; et++) {
                o[mf][et][0] *= f0; o[mf][et][1] *= f0;
                o[mf][et][2] *= f1; o[mf][et][3] *= f1;
            }
        }

        // P*V: fp16 1-term
        #pragma unroll
        for (int kt = 0; kt < 4; kt++) {
            uint32_t pa[2][4];
            #pragma unroll
            for (int mf = 0; mf < 2; mf++) {
                pa[mf][0] = ph[mf][2*kt][0];
                pa[mf][1] = ph[mf][2*kt][1];
                pa[mf][2] = ph[mf][2*kt+1][0];
                pa[mf][3] = ph[mf][2*kt+1][1];
            }
            #pragma unroll
            for (int pe = 0; pe < 4; pe++) {
                uint32_t vh4[4];
                ldsm_x4(vh4, smem_u32(Vh + (pe*16 + b4_r)*AQS + kt*16 + b4_c));
                #pragma unroll
                for (int mf = 0; mf < 2; mf++) {
                    mma16816h(o[mf][2*pe],   pa[mf], vh4[0], vh4[1]);
                    mma16816h(o[mf][2*pe+1], pa[mf], vh4[2], vh4[3]);
                }
            }
        }
    }

    // Epilogue: normalize, write fp16 attn output [B,T,D]
    #pragma unroll
    for (int mf = 0; mf < 2; mf++) {
        float inv0 = 1.0f / l[mf*2];
        float inv1 = 1.0f / l[mf*2+1];
        int tq = q0 + w*32 + mf*16 + g;
        #pragma unroll
        for (int et = 0; et < 8; et++) {
            int col = hh*HDD + et*8 + 2*t;
            size_t a0 = ((size_t)b*TT + tq)*DD + col;
            size_t a1 = ((size_t)b*TT + tq + 8)*DD + col;
            *(uint32_t*)&g_aof[a0] = f16pack(o[mf][et][0]*inv0, o[mf][et][1]*inv0);
            *(uint32_t*)&g_aof[a1] = f16pack(o[mf][et][2]*inv1, o[mf][et][3]*inv1);
        }
    }
}

// ============================================================================
// Launch
// ============================================================================
extern "C" void kernel_launch(void* const* d_in, const int* in_sizes, int n_in,
                              void* d_out, int out_size)
{
    const float* x  = (const float*)d_in[0];
    const float* Wq = (const float*)d_in[1];
    const float* Wk = (const float*)d_in[2];
    const float* Wv = (const float*)d_in[3];
    const float* Wo = (const float*)d_in[4];
    const float* bo = (const float*)d_in[5];
    float* out = (float*)d_out;

    cudaFuncSetAttribute(qkv_proj_tc, cudaFuncAttributeMaxDynamicSharedMemorySize,
                         GEMM_SMEM_BYTES);
    cudaFuncSetAttribute(out_gemm_f16, cudaFuncAttributeMaxDynamicSharedMemorySize,
                         F16_PIPE_BYTES);
    cudaFuncSetAttribute(attn_tc, cudaFuncAttributeMaxDynamicSharedMemorySize,
                         ATTN_SMEM_BYTES);

    int nx = MTOT*DD/4, nw = DD*DD/4;
    convert_x_k<<<nx/256, 256>>>((const float4*)x);
    convert_w_k<<<dim3(nw/256, 4), 256>>>((const float4*)Wq, (const float4*)Wk,
                                          (const float4*)Wv, (const float4*)Wo);

    qkv_proj_tc<<<dim3(DD/128, MTOT/128, 3), 128, GEMM_SMEM_BYTES>>>();
    attn_tc<<<dim3(TT/128, BB*HH), 128, ATTN_SMEM_BYTES>>>();
    out_gemm_f16<<<dim3(DD/128, MTOT/128), 128, F16_PIPE_BYTES>>>(bo, out);
}

// round 14
// speedup vs baseline: 6.1409x; 1.0745x over previous
#include <cuda_runtime.h>
#include <cuda_bf16.h>
#include <cuda_fp16.h>
#include <cstdint>
#include <math.h>

#define BB   4
#define TT   2048
#define DD   1024
#define HH   16
#define HDD  64
#define MTOT (BB*TT)   // 8192

typedef __nv_bfloat16  bf16;
typedef __nv_bfloat162 bf162;

// ---- precision-split globals ----
__device__ bf16   g_xh [(size_t)MTOT*DD], g_xl [(size_t)MTOT*DD];  // x bf16 hi/lo (QK proj)
__device__ __half g_xf [(size_t)MTOT*DD];                          // x fp16 (V proj)
__device__ bf16   g_wqh[(size_t)DD*DD],   g_wql[(size_t)DD*DD];
__device__ bf16   g_wkh[(size_t)DD*DD],   g_wkl[(size_t)DD*DD];
__device__ __half g_wvf[(size_t)DD*DD];                            // Wv fp16
__device__ __half g_wof[(size_t)DD*DD];                            // Wo fp16
__device__ bf16   g_qh [(size_t)MTOT*DD];                          // [B,H,T,HD] Q single bf16, prescaled log2e/8
__device__ bf16   g_kh [(size_t)MTOT*DD];                          // [B,H,T,HD] K single bf16
__device__ __half g_vtf[(size_t)MTOT*DD];                          // V^T [B,H,HD,T] fp16
__device__ __half g_aof[(size_t)MTOT*DD];                          // attn out [B,T,D] fp16

// ============================================================================
// Helpers
// ============================================================================
__device__ __forceinline__ uint32_t smem_u32(const void* p) {
    return (uint32_t)__cvta_generic_to_shared(p);
}
__device__ __forceinline__ void ldsm_x4(uint32_t r[4], uint32_t addr) {
    asm volatile("ldmatrix.sync.aligned.m8n8.x4.shared.b16 {%0,%1,%2,%3}, [%4];"
                 : "=r"(r[0]), "=r"(r[1]), "=r"(r[2]), "=r"(r[3]) : "r"(addr));
}
__device__ __forceinline__ void mma16816(float d[4], const uint32_t a[4], const uint32_t b0, const uint32_t b1) {
    asm volatile(
        "mma.sync.aligned.m16n8k16.row.col.f32.bf16.bf16.f32 "
        "{%0,%1,%2,%3}, {%4,%5,%6,%7}, {%8,%9}, {%0,%1,%2,%3};"
        : "+f"(d[0]), "+f"(d[1]), "+f"(d[2]), "+f"(d[3])
        : "r"(a[0]), "r"(a[1]), "r"(a[2]), "r"(a[3]), "r"(b0), "r"(b1));
}
__device__ __forceinline__ void mma16816h(float d[4], const uint32_t a[4], const uint32_t b0, const uint32_t b1) {
    asm volatile(
        "mma.sync.aligned.m16n8k16.row.col.f32.f16.f16.f32 "
        "{%0,%1,%2,%3}, {%4,%5,%6,%7}, {%8,%9}, {%0,%1,%2,%3};"
        : "+f"(d[0]), "+f"(d[1]), "+f"(d[2]), "+f"(d[3])
        : "r"(a[0]), "r"(a[1]), "r"(a[2]), "r"(a[3]), "r"(b0), "r"(b1));
}
__device__ __forceinline__ void split2(float x, float y, bf162& h, bf162& l) {
    bf16 hx = __float2bfloat16(x);
    bf16 hy = __float2bfloat16(y);
    h = __halves2bfloat162(hx, hy);
    l = __halves2bfloat162(__float2bfloat16(x - __bfloat162float(hx)),
                           __float2bfloat16(y - __bfloat162float(hy)));
}
__device__ __forceinline__ uint32_t bf16pack(float x, float y) {
    uint32_t r;
    asm("cvt.rn.bf16x2.f32 %0, %1, %2;" : "=r"(r) : "f"(y), "f"(x));
    return r;
}
__device__ __forceinline__ uint32_t f16pack(float x, float y) {
    uint32_t r;
    asm("cvt.rn.f16x2.f32 %0, %1, %2;" : "=r"(r) : "f"(y), "f"(x));
    return r;
}
__device__ __forceinline__ uint32_t h2ex2(uint32_t x) {
    uint32_t r;
    asm("ex2.approx.f16x2 %0, %1;" : "=r"(r) : "r"(x));
    return r;
}
__device__ __forceinline__ float ex2f(float x) {
    float r;
    asm("ex2.approx.f32 %0, %1;" : "=f"(r) : "f"(x));
    return r;
}
__device__ __forceinline__ void cp16(uint32_t s, const void* g) {
    asm volatile("cp.async.ca.shared.global [%0], [%1], 16;\n" :: "r"(s), "l"(g));
}
#define CP_COMMIT() asm volatile("cp.async.commit_group;\n" ::: "memory")
template<int N> __device__ __forceinline__ void cp_wait() {
    asm volatile("cp.async.wait_group %0;\n" :: "n"(N) : "memory");
}

// ============================================================================
// Convert kernels
// ============================================================================
__global__ __launch_bounds__(256) void convert_x_k(const float4* __restrict__ src)
{
    int i = blockIdx.x * 256 + threadIdx.x;
    float4 v = src[i];
    bf162 h0, l0, h1, l1;
    split2(v.x, v.y, h0, l0);
    split2(v.z, v.w, h1, l1);
    *(bf162*)(g_xh + (size_t)i*4)     = h0;
    *(bf162*)(g_xh + (size_t)i*4 + 2) = h1;
    *(bf162*)(g_xl + (size_t)i*4)     = l0;
    *(bf162*)(g_xl + (size_t)i*4 + 2) = l1;
    *(__half2*)(g_xf + (size_t)i*4)     = __floats2half2_rn(v.x, v.y);
    *(__half2*)(g_xf + (size_t)i*4 + 2) = __floats2half2_rn(v.z, v.w);
}
__global__ __launch_bounds__(256) void convert_w_k(
    const float4* __restrict__ wq, const float4* __restrict__ wk,
    const float4* __restrict__ wv, const float4* __restrict__ wo)
{
    int which = blockIdx.y;
    int i = blockIdx.x * 256 + threadIdx.x;
    if (which < 2) {
        const float4* src = (which == 0) ? wq : wk;
        bf16* ho = (which == 0) ? g_wqh : g_wkh;
        bf16* lo = (which == 0) ? g_wql : g_wkl;
        float4 v = src[i];
        bf162 h0, l0, h1, l1;
        split2(v.x, v.y, h0, l0);
        split2(v.z, v.w, h1, l1);
        *(bf162*)(ho + (size_t)i*4)     = h0;
        *(bf162*)(ho + (size_t)i*4 + 2) = h1;
        *(bf162*)(lo + (size_t)i*4)     = l0;
        *(bf162*)(lo + (size_t)i*4 + 2) = l1;
    } else {
        const float4* src = (which == 2) ? wv : wo;
        __half* ho = (which == 2) ? g_wvf : g_wof;
        float4 v = src[i];
        *(__half2*)(ho + (size_t)i*4)     = __floats2half2_rn(v.x, v.y);
        *(__half2*)(ho + (size_t)i*4 + 2) = __floats2half2_rn(v.z, v.w);
    }
}

// ============================================================================
// GEMM mainloops (bf16 3-term; fp16 1-term). CTA 128x128, 4 warps, 64x64.
// ============================================================================
#define LDKB 40
#define STG_ARR (128*LDKB)
#define STG4    (4*STG_ARR)
#define GEMM_SMEM_BYTES (2*STG4*2)  // 81920

__device__ __forceinline__ void gemm_load_stage(
    const bf16* __restrict__ Ahg, const bf16* __restrict__ Alg,
    const bf16* __restrict__ Bhg, const bf16* __restrict__ Blg,
    int m0, int n0, int k0, bf16* base, int tid)
{
    const bf16* gp[4] = {Ahg, Alg, Bhg, Blg};
    #pragma unroll
    for (int a = 0; a < 4; a++) {
        int row0 = (a < 2) ? m0 : n0;
        bf16* sb = base + a*STG_ARR;
        #pragma unroll
        for (int s = 0; s < 4; s++) {
            int idx = tid + s*128;
            int r = idx >> 2;
            int c = (idx & 3) * 8;
            cp16(smem_u32(sb + r*LDKB + c), gp[a] + (size_t)(row0 + r)*DD + k0 + c);
        }
    }
}

__device__ __forceinline__ void gemm_mainloop(
    const bf16* __restrict__ Ahg, const bf16* __restrict__ Alg,
    const bf16* __restrict__ Bhg, const bf16* __restrict__ Blg,
    int m0, int n0, bf16* smem, float acc[4][8][4])
{
    const int tid  = threadIdx.x;
    const int lane = tid & 31;
    const int warp = tid >> 5;
    const int wm = warp >> 1;
    const int wn = warp & 1;

    const int a_r  = lane & 15;
    const int a_c  = (lane >> 4) << 3;
    const int b4_r = ((lane >> 4) << 3) + (lane & 7);
    const int b4_c = ((lane >> 3) & 1) << 3;

    const int NST = DD / 32;

    gemm_load_stage(Ahg, Alg, Bhg, Blg, m0, n0, 0, smem, tid); CP_COMMIT();

    for (int i = 0; i < NST; i++) {
        __syncthreads();
        if (i + 1 < NST)
            gemm_load_stage(Ahg, Alg, Bhg, Blg, m0, n0, (i+1)*32,
                            smem + ((i+1)&1)*STG4, tid);
        CP_COMMIT();
        cp_wait<1>();
        __syncthreads();

        bf16* Ahs = smem + (i&1)*STG4;
        bf16* Als = Ahs + STG_ARR;
        bf16* Bhs = Als + STG_ARR;
        bf16* Bls = Bhs + STG_ARR;

        #pragma unroll
        for (int kk = 0; kk < 32; kk += 16) {
            uint32_t ah[4][4], al[4][4];
            #pragma unroll
            for (int mt = 0; mt < 4; mt++) {
                ldsm_x4(ah[mt], smem_u32(Ahs + (wm*64 + mt*16 + a_r)*LDKB + kk + a_c));
                ldsm_x4(al[mt], smem_u32(Als + (wm*64 + mt*16 + a_r)*LDKB + kk + a_c));
            }
            #pragma unroll
            for (int p = 0; p < 4; p++) {
                uint32_t bh4[4], bl4[4];
                ldsm_x4(bh4, smem_u32(Bhs + (wn*64 + p*16 + b4_r)*LDKB + kk + b4_c));
                ldsm_x4(bl4, smem_u32(Bls + (wn*64 + p*16 + b4_r)*LDKB + kk + b4_c));
                #pragma unroll
                for (int mt = 0; mt < 4; mt++) {
                    mma16816(acc[mt][2*p],   ah[mt], bh4[0], bh4[1]);
                    mma16816(acc[mt][2*p],   ah[mt], bl4[0], bl4[1]);
                    mma16816(acc[mt][2*p],   al[mt], bh4[0], bh4[1]);
                    mma16816(acc[mt][2*p+1], ah[mt], bh4[2], bh4[3]);
                    mma16816(acc[mt][2*p+1], ah[mt], bl4[2], bl4[3]);
                    mma16816(acc[mt][2*p+1], al[mt], bh4[2], bh4[3]);
                }
            }
        }
    }
}

#define F16_STG   (128*LDKB)
#define F16_STG2  (2*F16_STG)

__device__ __forceinline__ void f16_load_stage(
    const __half* __restrict__ Ag, const __half* __restrict__ Bg,
    int m0, int n0, int k0, __half* base, int tid)
{
    #pragma unroll
    for (int s = 0; s < 4; s++) {
        int idx = tid + s*128;
        int r = idx >> 2;
        int c = (idx & 3) * 8;
        cp16(smem_u32(base + r*LDKB + c), Ag + (size_t)(m0 + r)*DD + k0 + c);
        cp16(smem_u32(base + F16_STG + r*LDKB + c), Bg + (size_t)(n0 + r)*DD + k0 + c);
    }
}

__device__ __forceinline__ void f16_gemm_mainloop(
    const __half* __restrict__ Ag, const __half* __restrict__ Bg,
    int m0, int n0, __half* smem, float acc[4][8][4])
{
    const int tid  = threadIdx.x;
    const int lane = tid & 31;
    const int warp = tid >> 5;
    const int wm = warp >> 1;
    const int wn = warp & 1;

    const int a_r  = lane & 15;
    const int a_c  = (lane >> 4) << 3;
    const int b4_r = ((lane >> 4) << 3) + (lane & 7);
    const int b4_c = ((lane >> 3) & 1) << 3;

    const int NST = DD / 32;

    f16_load_stage(Ag, Bg, m0, n0, 0, smem, tid); CP_COMMIT();

    for (int i = 0; i < NST; i++) {
        __syncthreads();
        if (i + 1 < NST)
            f16_load_stage(Ag, Bg, m0, n0, (i+1)*32, smem + ((i+1)&1)*F16_STG2, tid);
        CP_COMMIT();
        cp_wait<1>();
        __syncthreads();

        __half* As = smem + (i&1)*F16_STG2;
        __half* Bs = As + F16_STG;

        #pragma unroll
        for (int kk = 0; kk < 32; kk += 16) {
            uint32_t a4[4][4];
            #pragma unroll
            for (int mt = 0; mt < 4; mt++)
                ldsm_x4(a4[mt], smem_u32(As + (wm*64 + mt*16 + a_r)*LDKB + kk + a_c));
            #pragma unroll
            for (int p = 0; p < 4; p++) {
                uint32_t b4[4];
                ldsm_x4(b4, smem_u32(Bs + (wn*64 + p*16 + b4_r)*LDKB + kk + b4_c));
                #pragma unroll
                for (int mt = 0; mt < 4; mt++) {
                    mma16816h(acc[mt][2*p],   a4[mt], b4[0], b4[1]);
                    mma16816h(acc[mt][2*p+1], a4[mt], b4[2], b4[3]);
                }
            }
        }
    }
}

// ============================================================================
// Merged QKV projection: grid (8, 64, 3). z=0 Q, z=1 K (bf16 3-term, single-bf16
// out), z=2 V (fp16 1-term, V^T out).
// ============================================================================
__global__ __launch_bounds__(128) void qkv_proj_tc()
{
    extern __shared__ char dsm[];

    const int which = blockIdx.z;
    const int m0 = blockIdx.y * 128;
    const int n0 = blockIdx.x * 128;
    const int tid = threadIdx.x;
    const int bb = m0 >> 11;
    const int mloc = m0 & 2047;

    float acc[4][8][4];
    #pragma unroll
    for (int i = 0; i < 4; i++)
        #pragma unroll
        for (int j = 0; j < 8; j++)
            #pragma unroll
            for (int r = 0; r < 4; r++) acc[i][j][r] = 0.0f;

    const int lane = tid & 31;
    const int warp = tid >> 5;
    const int wm = warp >> 1, wn = warp & 1;
    const int g = lane >> 2, t = lane & 3;

    if (which == 2) {
        __half* fsm = (__half*)dsm;
        f16_gemm_mainloop(g_xf, g_wvf, m0, n0, fsm, acc);

        float* Cs = (float*)dsm;
        __syncthreads();
        #pragma unroll
        for (int mt = 0; mt < 4; mt++) {
            #pragma unroll
            for (int nt = 0; nt < 8; nt++) {
                int row = wm*64 + mt*16 + g;
                int col = wn*64 + nt*8 + 2*t;
                Cs[row*133 + col]       = acc[mt][nt][0];
                Cs[row*133 + col + 1]   = acc[mt][nt][1];
                Cs[(row+8)*133 + col]   = acc[mt][nt][2];
                Cs[(row+8)*133 + col+1] = acc[mt][nt][3];
            }
        }
        __syncthreads();
        for (int idx = tid; idx < 2048; idx += 128) {
            int el  = idx >> 4;
            int tch = (idx & 15) * 8;
            __half hv8[8];
            #pragma unroll
            for (int q = 0; q < 8; q++)
                hv8[q] = __float2half_rn(Cs[(tch + q)*133 + el]);
            int col = n0 + el;
            int hh = col >> 6, e = col & 63;
            size_t rb = (((size_t)bb*HH + hh)*HDD + e)*TT + mloc + tch;
            *(uint4*)&g_vtf[rb] = *(uint4*)hv8;
        }
        return;
    }

    bf16* gsm = (bf16*)dsm;
    const bf16* Bhg = (which == 0) ? g_wqh : g_wkh;
    const bf16* Blg = (which == 0) ? g_wql : g_wkl;
    gemm_mainloop(g_xh, g_xl, Bhg, Blg, m0, n0, gsm, acc);

    // Both Q and K stored single bf16 (Q prescaled by log2e/8)
    const float sc = (which == 0) ? (0.125f * 1.4426950408889634f) : 1.0f;
    bf16* outp = (which == 0) ? g_qh : g_kh;
    #pragma unroll
    for (int mt = 0; mt < 4; mt++) {
        #pragma unroll
        for (int nt = 0; nt < 8; nt++) {
            int row = mloc + wm*64 + mt*16 + g;
            int col = n0 + wn*64 + nt*8 + 2*t;
            int hh = col >> 6, e = col & 63;
            size_t a0 = (((size_t)bb*HH + hh)*TT + row)*HDD + e;
            size_t a1 = (((size_t)bb*HH + hh)*TT + row + 8)*HDD + e;
            *(uint32_t*)&outp[a0] = bf16pack(acc[mt][nt][0]*sc, acc[mt][nt][1]*sc);
            *(uint32_t*)&outp[a1] = bf16pack(acc[mt][nt][2]*sc, acc[mt][nt][3]*sc);
        }
    }
}

// Output projection: out = aof @ Wo^T + bo (fp32 out)
#define F16_PIPE_BYTES (2*F16_STG2*2)  // 40960
__global__ __launch_bounds__(128) void out_gemm_f16(
    const float* __restrict__ bo, float* __restrict__ outp)
{
    extern __shared__ __half fsm[];

    const int m0 = blockIdx.y * 128;
    const int n0 = blockIdx.x * 128;

    float acc[4][8][4];
    #pragma unroll
    for (int i = 0; i < 4; i++)
        #pragma unroll
        for (int j = 0; j < 8; j++)
            #pragma unroll
            for (int r = 0; r < 4; r++) acc[i][j][r] = 0.0f;

    f16_gemm_mainloop(g_aof, g_wof, m0, n0, fsm, acc);

    const int lane = threadIdx.x & 31;
    const int warp = threadIdx.x >> 5;
    const int wm = warp >> 1, wn = warp & 1;
    const int g = lane >> 2, t = lane & 3;

    #pragma unroll
    for (int mt = 0; mt < 4; mt++) {
        #pragma unroll
        for (int nt = 0; nt < 8; nt++) {
            int row = m0 + wm*64 + mt*16 + g;
            int col = n0 + wn*64 + nt*8 + 2*t;
            float bx = bo[col], by = bo[col+1];
            float2 v01 = make_float2(acc[mt][nt][0] + bx, acc[mt][nt][1] + by);
            float2 v23 = make_float2(acc[mt][nt][2] + bx, acc[mt][nt][3] + by);
            *(float2*)&outp[(size_t)row*DD + col]     = v01;
            *(float2*)&outp[(size_t)(row+8)*DD + col] = v23;
        }
    }
}

// ============================================================================
// Flash attention: q-tile 128, 4 warps x 32 rows. QK 1-term (Qh·Kh);
// softmax ex2.f16x2 -> P fragments; PV fp16 1-term. 3 CTAs/SM.
// ============================================================================
#define AQS 72
#define KVARR (64*AQS)
#define ATTN_Q_BYTES (128*AQS*2)                        // 18432 (single Q)
#define ATTN_KV_BYTES (2*2*KVARR*2)                     // 36864
#define ATTN_SMEM_BYTES (ATTN_Q_BYTES + ATTN_KV_BYTES)  // 55296

__device__ __forceinline__ void attn_load_kv(
    const bf16* khb, const __half* vhb,
    int j0, bf16* kvbase, int tid)
{
    bf16* Kh = kvbase;
    bf16* Vh = kvbase + KVARR;   // fp16 payload
    #pragma unroll
    for (int s = 0; s < 4; s++) {
        int idx = tid + s*128;
        int r = idx >> 3;
        int c = (idx & 7) * 8;
        cp16(smem_u32(Kh + r*AQS + c), khb + (size_t)(j0 + r)*HDD + c);
        cp16(smem_u32(Vh + r*AQS + c), vhb + (size_t)r*TT + j0 + c);
    }
}

__global__ __launch_bounds__(128, 3) void attn_tc()
{
    extern __shared__ bf16 asmem[];
    bf16* Qh = asmem;
    bf16* KV = Qh + 128*AQS;

    const int bh = blockIdx.y;
    const int hh = bh & (HH-1);
    const int b  = bh >> 4;
    const int qt = gridDim.x - 1 - blockIdx.x;
    const int q0 = qt * 128;
    const int njt = 2*qt + 2;

    const int tid  = threadIdx.x;
    const int lane = tid & 31;
    const int w    = tid >> 5;
    const int g    = lane >> 2;
    const int t    = lane & 3;

    const bf16* __restrict__ qhb = g_qh  + (size_t)bh * TT * HDD;
    const bf16* __restrict__ khb = g_kh  + (size_t)bh * TT * HDD;
    const __half* __restrict__ vhb = g_vtf + (size_t)bh * HDD * TT;

    for (int idx = tid; idx < 1024; idx += 128) {
        int r = idx >> 3;
        int c = (idx & 7) * 8;
        *(uint4*)(Qh + r*AQS + c) = *(const uint4*)(qhb + (size_t)(q0 + r)*HDD + c);
    }

    attn_load_kv(khb, vhb, 0, KV, tid); CP_COMMIT();

    float o[2][8][4];
    float m[4], l[4];
    #pragma unroll
    for (int mf = 0; mf < 2; mf++)
        #pragma unroll
        for (int et = 0; et < 8; et++)
            #pragma unroll
            for (int r = 0; r < 4; r++) o[mf][et][r] = 0.0f;
    #pragma unroll
    for (int i = 0; i < 4; i++) { m[i] = -1e30f; l[i] = 0.0f; }

    const int a_r  = lane & 15;
    const int a_c  = (lane >> 4) << 3;
    const int b4_r = ((lane >> 4) << 3) + (lane & 7);
    const int b4_c = ((lane >> 3) & 1) << 3;

    const int r0w = q0 + w*32;

    for (int jt = 0; jt < njt; jt++) {
        const int j0 = jt * 64;

        __syncthreads();
        if (jt + 1 < njt)
            attn_load_kv(khb, vhb, (jt+1)*64, KV + ((jt+1)&1)*2*KVARR, tid);
        CP_COMMIT();
        cp_wait<1>();
        __syncthreads();

        if (j0 > r0w + 31) continue;

        bf16* Kh = KV + (jt&1)*2*KVARR;
        bf16* Vh = Kh + KVARR;   // fp16 payload

        // S = Qh Kh^T : 1-term
        float s[2][8][4];
        #pragma unroll
        for (int mf = 0; mf < 2; mf++)
            #pragma unroll
            for (int nt = 0; nt < 8; nt++)
                #pragma unroll
                for (int r = 0; r < 4; r++) s[mf][nt][r] = 0.0f;

        #pragma unroll
        for (int kk = 0; kk < 4; kk++) {
            uint32_t qah[2][4];
            #pragma unroll
            for (int mf = 0; mf < 2; mf++)
                ldsm_x4(qah[mf], smem_u32(Qh + (w*32 + mf*16 + a_r)*AQS + kk*16 + a_c));
            #pragma unroll
            for (int p = 0; p < 4; p++) {
                uint32_t kh4[4];
                ldsm_x4(kh4, smem_u32(Kh + (p*16 + b4_r)*AQS + kk*16 + b4_c));
                #pragma unroll
                for (int mf = 0; mf < 2; mf++) {
                    mma16816(s[mf][2*p],   qah[mf], kh4[0], kh4[1]);
                    mma16816(s[mf][2*p+1], qah[mf], kh4[2], kh4[3]);
                }
            }
        }

        if (j0 + 63 > r0w) {
            #pragma unroll
            for (int mf = 0; mf < 2; mf++) {
                int r0 = r0w + mf*16 + g;
                int r1 = r0 + 8;
                #pragma unroll
                for (int nt = 0; nt < 8; nt++) {
                    int c0 = j0 + nt*8 + 2*t;
                    if (c0     > r0) s[mf][nt][0] = -1e30f;
                    if (c0 + 1 > r0) s[mf][nt][1] = -1e30f;
                    if (c0     > r1) s[mf][nt][2] = -1e30f;
                    if (c0 + 1 > r1) s[mf][nt][3] = -1e30f;
                }
            }
        }

        // Online softmax in log2 domain; ex2.f16x2 output = fp16 P fragments
        uint32_t ph[2][8][2];
        #pragma unroll
        for (int mf = 0; mf < 2; mf++) {
            float mx0 = -1e30f, mx1 = -1e30f;
            #pragma unroll
            for (int nt = 0; nt < 8; nt++) {
                mx0 = fmaxf(mx0, fmaxf(s[mf][nt][0], s[mf][nt][1]));
                mx1 = fmaxf(mx1, fmaxf(s[mf][nt][2], s[mf][nt][3]));
            }
            #pragma unroll
            for (int off = 1; off <= 2; off <<= 1) {
                mx0 = fmaxf(mx0, __shfl_xor_sync(0xffffffffu, mx0, off));
                mx1 = fmaxf(mx1, __shfl_xor_sync(0xffffffffu, mx1, off));
            }
            float mn0 = fmaxf(m[mf*2],   mx0);
            float mn1 = fmaxf(m[mf*2+1], mx1);
            float f0 = ex2f(m[mf*2]   - mn0);
            float f1 = ex2f(m[mf*2+1] - mn1);
            float rs0 = 0.0f, rs1 = 0.0f;
            #pragma unroll
            for (int nt = 0; nt < 8; nt++) {
                uint32_t w0 = h2ex2(f16pack(s[mf][nt][0] - mn0, s[mf][nt][1] - mn0));
                uint32_t w1 = h2ex2(f16pack(s[mf][nt][2] - mn1, s[mf][nt][3] - mn1));
                ph[mf][nt][0] = w0;
                ph[mf][nt][1] = w1;
                float2 fa = __half22float2(*(__half2*)&w0);
                float2 fb = __half22float2(*(__half2*)&w1);
                rs0 += fa.x + fa.y;
                rs1 += fb.x + fb.y;
            }
            #pragma unroll
            for (int off = 1; off <= 2; off <<= 1) {
                rs0 += __shfl_xor_sync(0xffffffffu, rs0, off);
                rs1 += __shfl_xor_sync(0xffffffffu, rs1, off);
            }
            l[mf*2]   = l[mf*2]   * f0 + rs0;
            l[mf*2+1] = l[mf*2+1] * f1 + rs1;
            m[mf*2]   = mn0;
            m[mf*2+1] = mn1;
            #pragma unroll
            for (int et = 0; et < 8; et++) {
                o[mf][et][0] *= f0; o[mf][et][1] *= f0;
                o[mf][et][2] *= f1; o[mf][et][3] *= f1;
            }
        }

        // P*V: fp16 1-term
        #pragma unroll
        for (int kt = 0; kt < 4; kt++) {
            uint32_t pa[2][4];
            #pragma unroll
            for (int mf = 0; mf < 2; mf++) {
                pa[mf][0] = ph[mf][2*kt][0];
                pa[mf][1] = ph[mf][2*kt][1];
                pa[mf][2] = ph[mf][2*kt+1][0];
                pa[mf][3] = ph[mf][2*kt+1][1];
            }
            #pragma unroll
            for (int pe = 0; pe < 4; pe++) {
                uint32_t vh4[4];
                ldsm_x4(vh4, smem_u32(Vh + (pe*16 + b4_r)*AQS + kt*16 + b4_c));
                #pragma unroll
                for (int mf = 0; mf < 2; mf++) {
                    mma16816h(o[mf][2*pe],   pa[mf], vh4[0], vh4[1]);
                    mma16816h(o[mf][2*pe+1], pa[mf], vh4[2], vh4[3]);
                }
            }
        }
    }

    // Epilogue: normalize, write fp16 attn output [B,T,D]
    #pragma unroll
    for (int mf = 0; mf < 2; mf++) {
        float inv0 = 1.0f / l[mf*2];
        float inv1 = 1.0f / l[mf*2+1];
        int tq = q0 + w*32 + mf*16 + g;
        #pragma unroll
        for (int et = 0; et < 8; et++) {
            int col = hh*HDD + et*8 + 2*t;
            size_t a0 = ((size_t)b*TT + tq)*DD + col;
            size_t a1 = ((size_t)b*TT + tq + 8)*DD + col;
            *(uint32_t*)&g_aof[a0] = f16pack(o[mf][et][0]*inv0, o[mf][et][1]*inv0);
            *(uint32_t*)&g_aof[a1] = f16pack(o[mf][et][2]*inv1, o[mf][et][3]*inv1);
        }
    }
}

// ============================================================================
// Launch
// ============================================================================
extern "C" void kernel_launch(void* const* d_in, const int* in_sizes, int n_in,
                              void* d_out, int out_size)
{
    const float* x  = (const float*)d_in[0];
    const float* Wq = (const float*)d_in[1];
    const float* Wk = (const float*)d_in[2];
    const float* Wv = (const float*)d_in[3];
    const float* Wo = (const float*)d_in[4];
    const float* bo = (const float*)d_in[5];
    float* out = (float*)d_out;

    cudaFuncSetAttribute(qkv_proj_tc, cudaFuncAttributeMaxDynamicSharedMemorySize,
                         GEMM_SMEM_BYTES);
    cudaFuncSetAttribute(out_gemm_f16, cudaFuncAttributeMaxDynamicSharedMemorySize,
                         F16_PIPE_BYTES);
    cudaFuncSetAttribute(attn_tc, cudaFuncAttributeMaxDynamicSharedMemorySize,
                         ATTN_SMEM_BYTES);

    int nx = MTOT*DD/4, nw = DD*DD/4;
    convert_x_k<<<nx/256, 256>>>((const float4*)x);
    convert_w_k<<<dim3(nw/256, 4), 256>>>((const float4*)Wq, (const float4*)Wk,
                                          (const float4*)Wv, (const float4*)Wo);

    qkv_proj_tc<<<dim3(DD/128, MTOT/128, 3), 128, GEMM_SMEM_BYTES>>>();
    attn_tc<<<dim3(TT/128, BB*HH), 128, ATTN_SMEM_BYTES>>>();
    out_gemm_f16<<<dim3(DD/128, MTOT/128), 128, F16_PIPE_BYTES>>>(bo, out);
}

// round 15
// speedup vs baseline: 7.2087x; 1.1739x over previous
#include <cuda_runtime.h>
#include <cuda_bf16.h>
#include <cuda_fp16.h>
#include <cstdint>
#include <math.h>

#define BB   4
#define TT   2048
#define DD   1024
#define HH   16
#define HDD  64
#define MTOT (BB*TT)   // 8192

typedef __nv_bfloat16  bf16;
typedef __nv_bfloat162 bf162;

// ---- precision-split globals ----
__device__ __half g_xf [(size_t)MTOT*DD], g_xfl[(size_t)MTOT*DD];  // x fp16 hi/lo
__device__ __half g_wqf[(size_t)DD*DD];                            // Wq fp16
__device__ __half g_wkf[(size_t)DD*DD];                            // Wk fp16
__device__ __half g_wvf[(size_t)DD*DD];                            // Wv fp16
__device__ __half g_wof[(size_t)DD*DD];                            // Wo fp16
__device__ bf16   g_qh [(size_t)MTOT*DD];                          // [B,H,T,HD] Q bf16, prescaled log2e/8
__device__ bf16   g_kh [(size_t)MTOT*DD];                          // [B,H,T,HD] K bf16
__device__ __half g_vtf[(size_t)MTOT*DD];                          // V^T [B,H,HD,T] fp16
__device__ __half g_aof[(size_t)MTOT*DD];                          // attn out [B,T,D] fp16

// ============================================================================
// Helpers
// ============================================================================
__device__ __forceinline__ uint32_t smem_u32(const void* p) {
    return (uint32_t)__cvta_generic_to_shared(p);
}
__device__ __forceinline__ void ldsm_x4(uint32_t r[4], uint32_t addr) {
    asm volatile("ldmatrix.sync.aligned.m8n8.x4.shared.b16 {%0,%1,%2,%3}, [%4];"
                 : "=r"(r[0]), "=r"(r[1]), "=r"(r[2]), "=r"(r[3]) : "r"(addr));
}
__device__ __forceinline__ void mma16816(float d[4], const uint32_t a[4], const uint32_t b0, const uint32_t b1) {
    asm volatile(
        "mma.sync.aligned.m16n8k16.row.col.f32.bf16.bf16.f32 "
        "{%0,%1,%2,%3}, {%4,%5,%6,%7}, {%8,%9}, {%0,%1,%2,%3};"
        : "+f"(d[0]), "+f"(d[1]), "+f"(d[2]), "+f"(d[3])
        : "r"(a[0]), "r"(a[1]), "r"(a[2]), "r"(a[3]), "r"(b0), "r"(b1));
}
__device__ __forceinline__ void mma16816h(float d[4], const uint32_t a[4], const uint32_t b0, const uint32_t b1) {
    asm volatile(
        "mma.sync.aligned.m16n8k16.row.col.f32.f16.f16.f32 "
        "{%0,%1,%2,%3}, {%4,%5,%6,%7}, {%8,%9}, {%0,%1,%2,%3};"
        : "+f"(d[0]), "+f"(d[1]), "+f"(d[2]), "+f"(d[3])
        : "r"(a[0]), "r"(a[1]), "r"(a[2]), "r"(a[3]), "r"(b0), "r"(b1));
}
__device__ __forceinline__ uint32_t bf16pack(float x, float y) {
    uint32_t r;
    asm("cvt.rn.bf16x2.f32 %0, %1, %2;" : "=r"(r) : "f"(y), "f"(x));
    return r;
}
__device__ __forceinline__ uint32_t f16pack(float x, float y) {
    uint32_t r;
    asm("cvt.rn.f16x2.f32 %0, %1, %2;" : "=r"(r) : "f"(y), "f"(x));
    return r;
}
__device__ __forceinline__ uint32_t h2ex2(uint32_t x) {
    uint32_t r;
    asm("ex2.approx.f16x2 %0, %1;" : "=r"(r) : "r"(x));
    return r;
}
__device__ __forceinline__ float ex2f(float x) {
    float r;
    asm("ex2.approx.f32 %0, %1;" : "=f"(r) : "f"(x));
    return r;
}
__device__ __forceinline__ void cp16(uint32_t s, const void* g) {
    asm volatile("cp.async.ca.shared.global [%0], [%1], 16;\n" :: "r"(s), "l"(g));
}
#define CP_COMMIT() asm volatile("cp.async.commit_group;\n" ::: "memory")
template<int N> __device__ __forceinline__ void cp_wait() {
    asm volatile("cp.async.wait_group %0;\n" :: "n"(N) : "memory");
}

// ============================================================================
// Convert kernels: x -> fp16 hi/lo; weights -> single fp16
// ============================================================================
__global__ __launch_bounds__(256) void convert_x_k(const float4* __restrict__ src)
{
    int i = blockIdx.x * 256 + threadIdx.x;
    float4 v = src[i];
    __half hx = __float2half_rn(v.x), hy = __float2half_rn(v.y);
    __half hz = __float2half_rn(v.z), hw = __float2half_rn(v.w);
    *(__half2*)(g_xf  + (size_t)i*4)     = __halves2half2(hx, hy);
    *(__half2*)(g_xf  + (size_t)i*4 + 2) = __halves2half2(hz, hw);
    *(__half2*)(g_xfl + (size_t)i*4)     = __floats2half2_rn(v.x - __half2float(hx),
                                                             v.y - __half2float(hy));
    *(__half2*)(g_xfl + (size_t)i*4 + 2) = __floats2half2_rn(v.z - __half2float(hz),
                                                             v.w - __half2float(hw));
}
__global__ __launch_bounds__(256) void convert_w_k(
    const float4* __restrict__ wq, const float4* __restrict__ wk,
    const float4* __restrict__ wv, const float4* __restrict__ wo)
{
    int which = blockIdx.y;
    const float4* src = (which == 0) ? wq : (which == 1) ? wk : (which == 2) ? wv : wo;
    __half* ho = (which == 0) ? g_wqf : (which == 1) ? g_wkf : (which == 2) ? g_wvf : g_wof;
    int i = blockIdx.x * 256 + threadIdx.x;
    float4 v = src[i];
    *(__half2*)(ho + (size_t)i*4)     = __floats2half2_rn(v.x, v.y);
    *(__half2*)(ho + (size_t)i*4 + 2) = __floats2half2_rn(v.z, v.w);
}

// ============================================================================
// fp16 GEMM mainloops. CTA 128x128, 4 warps, warp tile 64x64, 2-stage cp.async.
//  - 2-term: A fp16 hi/lo, B fp16 (Q/K projections)
//  - 1-term: A fp16, B fp16 (V projection, out projection)
// ============================================================================
#define LDKB 40
#define F16_STG   (128*LDKB)
#define F16_STG2  (2*F16_STG)          // 1-term stage: A + B
#define F16_STG3  (3*F16_STG)          // 2-term stage: Ah + Al + B
#define F16_PIPE_BYTES  (2*F16_STG2*2) // 40960
#define F16_PIPE3_BYTES (2*F16_STG3*2) // 61440
#define QKV_SMEM_BYTES  69632          // max(pipe3, pipe1, Cs 128x133 fp32)

__device__ __forceinline__ void f16_load_stage(
    const __half* __restrict__ Ag, const __half* __restrict__ Bg,
    int m0, int n0, int k0, __half* base, int tid)
{
    #pragma unroll
    for (int s = 0; s < 4; s++) {
        int idx = tid + s*128;
        int r = idx >> 2;
        int c = (idx & 3) * 8;
        cp16(smem_u32(base + r*LDKB + c), Ag + (size_t)(m0 + r)*DD + k0 + c);
        cp16(smem_u32(base + F16_STG + r*LDKB + c), Bg + (size_t)(n0 + r)*DD + k0 + c);
    }
}

__device__ __forceinline__ void f16_gemm_mainloop(
    const __half* __restrict__ Ag, const __half* __restrict__ Bg,
    int m0, int n0, __half* smem, float acc[4][8][4])
{
    const int tid  = threadIdx.x;
    const int lane = tid & 31;
    const int warp = tid >> 5;
    const int wm = warp >> 1;
    const int wn = warp & 1;

    const int a_r  = lane & 15;
    const int a_c  = (lane >> 4) << 3;
    const int b4_r = ((lane >> 4) << 3) + (lane & 7);
    const int b4_c = ((lane >> 3) & 1) << 3;

    const int NST = DD / 32;

    f16_load_stage(Ag, Bg, m0, n0, 0, smem, tid); CP_COMMIT();

    for (int i = 0; i < NST; i++) {
        __syncthreads();
        if (i + 1 < NST)
            f16_load_stage(Ag, Bg, m0, n0, (i+1)*32, smem + ((i+1)&1)*F16_STG2, tid);
        CP_COMMIT();
        cp_wait<1>();
        __syncthreads();

        __half* As = smem + (i&1)*F16_STG2;
        __half* Bs = As + F16_STG;

        #pragma unroll
        for (int kk = 0; kk < 32; kk += 16) {
            uint32_t a4[4][4];
            #pragma unroll
            for (int mt = 0; mt < 4; mt++)
                ldsm_x4(a4[mt], smem_u32(As + (wm*64 + mt*16 + a_r)*LDKB + kk + a_c));
            #pragma unroll
            for (int p = 0; p < 4; p++) {
                uint32_t b4[4];
                ldsm_x4(b4, smem_u32(Bs + (wn*64 + p*16 + b4_r)*LDKB + kk + b4_c));
                #pragma unroll
                for (int mt = 0; mt < 4; mt++) {
                    mma16816h(acc[mt][2*p],   a4[mt], b4[0], b4[1]);
                    mma16816h(acc[mt][2*p+1], a4[mt], b4[2], b4[3]);
                }
            }
        }
    }
}

__device__ __forceinline__ void f16_load_stage3(
    const __half* __restrict__ Ahg, const __half* __restrict__ Alg,
    const __half* __restrict__ Bg,
    int m0, int n0, int k0, __half* base, int tid)
{
    #pragma unroll
    for (int s = 0; s < 4; s++) {
        int idx = tid + s*128;
        int r = idx >> 2;
        int c = (idx & 3) * 8;
        cp16(smem_u32(base + r*LDKB + c),              Ahg + (size_t)(m0 + r)*DD + k0 + c);
        cp16(smem_u32(base + F16_STG + r*LDKB + c),    Alg + (size_t)(m0 + r)*DD + k0 + c);
        cp16(smem_u32(base + 2*F16_STG + r*LDKB + c),  Bg  + (size_t)(n0 + r)*DD + k0 + c);
    }
}

__device__ __forceinline__ void f16_gemm2_mainloop(
    const __half* __restrict__ Ahg, const __half* __restrict__ Alg,
    const __half* __restrict__ Bg,
    int m0, int n0, __half* smem, float acc[4][8][4])
{
    const int tid  = threadIdx.x;
    const int lane = tid & 31;
    const int warp = tid >> 5;
    const int wm = warp >> 1;
    const int wn = warp & 1;

    const int a_r  = lane & 15;
    const int a_c  = (lane >> 4) << 3;
    const int b4_r = ((lane >> 4) << 3) + (lane & 7);
    const int b4_c = ((lane >> 3) & 1) << 3;

    const int NST = DD / 32;

    f16_load_stage3(Ahg, Alg, Bg, m0, n0, 0, smem, tid); CP_COMMIT();

    for (int i = 0; i < NST; i++) {
        __syncthreads();
        if (i + 1 < NST)
            f16_load_stage3(Ahg, Alg, Bg, m0, n0, (i+1)*32,
                            smem + ((i+1)&1)*F16_STG3, tid);
        CP_COMMIT();
        cp_wait<1>();
        __syncthreads();

        __half* Ahs = smem + (i&1)*F16_STG3;
        __half* Als = Ahs + F16_STG;
        __half* Bs  = Als + F16_STG;

        #pragma unroll
        for (int kk = 0; kk < 32; kk += 16) {
            uint32_t ah[4][4], al[4][4];
            #pragma unroll
            for (int mt = 0; mt < 4; mt++) {
                ldsm_x4(ah[mt], smem_u32(Ahs + (wm*64 + mt*16 + a_r)*LDKB + kk + a_c));
                ldsm_x4(al[mt], smem_u32(Als + (wm*64 + mt*16 + a_r)*LDKB + kk + a_c));
            }
            #pragma unroll
            for (int p = 0; p < 4; p++) {
                uint32_t b4[4];
                ldsm_x4(b4, smem_u32(Bs + (wn*64 + p*16 + b4_r)*LDKB + kk + b4_c));
                #pragma unroll
                for (int mt = 0; mt < 4; mt++) {
                    mma16816h(acc[mt][2*p],   ah[mt], b4[0], b4[1]);
                    mma16816h(acc[mt][2*p],   al[mt], b4[0], b4[1]);
                    mma16816h(acc[mt][2*p+1], ah[mt], b4[2], b4[3]);
                    mma16816h(acc[mt][2*p+1], al[mt], b4[2], b4[3]);
                }
            }
        }
    }
}

// ============================================================================
// Merged QKV projection: grid (8, 64, 3). z=0 Q, z=1 K (fp16 2-term, bf16 out),
// z=2 V (fp16 1-term, V^T out).
// ============================================================================
__global__ __launch_bounds__(128) void qkv_proj_tc()
{
    extern __shared__ char dsm[];

    const int which = blockIdx.z;
    const int m0 = blockIdx.y * 128;
    const int n0 = blockIdx.x * 128;
    const int tid = threadIdx.x;
    const int bb = m0 >> 11;
    const int mloc = m0 & 2047;

    float acc[4][8][4];
    #pragma unroll
    for (int i = 0; i < 4; i++)
        #pragma unroll
        for (int j = 0; j < 8; j++)
            #pragma unroll
            for (int r = 0; r < 4; r++) acc[i][j][r] = 0.0f;

    const int lane = tid & 31;
    const int warp = tid >> 5;
    const int wm = warp >> 1, wn = warp & 1;
    const int g = lane >> 2, t = lane & 3;

    if (which == 2) {
        __half* fsm = (__half*)dsm;
        f16_gemm_mainloop(g_xf, g_wvf, m0, n0, fsm, acc);

        float* Cs = (float*)dsm;
        __syncthreads();
        #pragma unroll
        for (int mt = 0; mt < 4; mt++) {
            #pragma unroll
            for (int nt = 0; nt < 8; nt++) {
                int row = wm*64 + mt*16 + g;
                int col = wn*64 + nt*8 + 2*t;
                Cs[row*133 + col]       = acc[mt][nt][0];
                Cs[row*133 + col + 1]   = acc[mt][nt][1];
                Cs[(row+8)*133 + col]   = acc[mt][nt][2];
                Cs[(row+8)*133 + col+1] = acc[mt][nt][3];
            }
        }
        __syncthreads();
        for (int idx = tid; idx < 2048; idx += 128) {
            int el  = idx >> 4;
            int tch = (idx & 15) * 8;
            __half hv8[8];
            #pragma unroll
            for (int q = 0; q < 8; q++)
                hv8[q] = __float2half_rn(Cs[(tch + q)*133 + el]);
            int col = n0 + el;
            int hh = col >> 6, e = col & 63;
            size_t rb = (((size_t)bb*HH + hh)*HDD + e)*TT + mloc + tch;
            *(uint4*)&g_vtf[rb] = *(uint4*)hv8;
        }
        return;
    }

    __half* fsm = (__half*)dsm;
    const __half* Bg = (which == 0) ? g_wqf : g_wkf;
    f16_gemm2_mainloop(g_xf, g_xfl, Bg, m0, n0, fsm, acc);

    // Q prescaled by log2e/8; both Q and K stored single bf16
    const float sc = (which == 0) ? (0.125f * 1.4426950408889634f) : 1.0f;
    bf16* outp = (which == 0) ? g_qh : g_kh;
    #pragma unroll
    for (int mt = 0; mt < 4; mt++) {
        #pragma unroll
        for (int nt = 0; nt < 8; nt++) {
            int row = mloc + wm*64 + mt*16 + g;
            int col = n0 + wn*64 + nt*8 + 2*t;
            int hh = col >> 6, e = col & 63;
            size_t a0 = (((size_t)bb*HH + hh)*TT + row)*HDD + e;
            size_t a1 = (((size_t)bb*HH + hh)*TT + row + 8)*HDD + e;
            *(uint32_t*)&outp[a0] = bf16pack(acc[mt][nt][0]*sc, acc[mt][nt][1]*sc);
            *(uint32_t*)&outp[a1] = bf16pack(acc[mt][nt][2]*sc, acc[mt][nt][3]*sc);
        }
    }
}

// Output projection: out = aof @ Wo^T + bo (fp32 out)
__global__ __launch_bounds__(128) void out_gemm_f16(
    const float* __restrict__ bo, float* __restrict__ outp)
{
    extern __shared__ __half fsm[];

    const int m0 = blockIdx.y * 128;
    const int n0 = blockIdx.x * 128;

    float acc[4][8][4];
    #pragma unroll
    for (int i = 0; i < 4; i++)
        #pragma unroll
        for (int j = 0; j < 8; j++)
            #pragma unroll
            for (int r = 0; r < 4; r++) acc[i][j][r] = 0.0f;

    f16_gemm_mainloop(g_aof, g_wof, m0, n0, fsm, acc);

    const int lane = threadIdx.x & 31;
    const int warp = threadIdx.x >> 5;
    const int wm = warp >> 1, wn = warp & 1;
    const int g = lane >> 2, t = lane & 3;

    #pragma unroll
    for (int mt = 0; mt < 4; mt++) {
        #pragma unroll
        for (int nt = 0; nt < 8; nt++) {
            int row = m0 + wm*64 + mt*16 + g;
            int col = n0 + wn*64 + nt*8 + 2*t;
            float bx = bo[col], by = bo[col+1];
            float2 v01 = make_float2(acc[mt][nt][0] + bx, acc[mt][nt][1] + by);
            float2 v23 = make_float2(acc[mt][nt][2] + bx, acc[mt][nt][3] + by);
            *(float2*)&outp[(size_t)row*DD + col]     = v01;
            *(float2*)&outp[(size_t)(row+8)*DD + col] = v23;
        }
    }
}

// ============================================================================
// Flash attention (unchanged from R14 @157us): q-tile 128, 4 warps x 32 rows.
// QK 1-term bf16; softmax ex2.f16x2 -> P; PV fp16 1-term. 3 CTAs/SM.
// ============================================================================
#define AQS 72
#define KVARR (64*AQS)
#define ATTN_Q_BYTES (128*AQS*2)                        // 18432
#define ATTN_KV_BYTES (2*2*KVARR*2)                     // 36864
#define ATTN_SMEM_BYTES (ATTN_Q_BYTES + ATTN_KV_BYTES)  // 55296

__device__ __forceinline__ void attn_load_kv(
    const bf16* khb, const __half* vhb,
    int j0, bf16* kvbase, int tid)
{
    bf16* Kh = kvbase;
    bf16* Vh = kvbase + KVARR;   // fp16 payload
    #pragma unroll
    for (int s = 0; s < 4; s++) {
        int idx = tid + s*128;
        int r = idx >> 3;
        int c = (idx & 7) * 8;
        cp16(smem_u32(Kh + r*AQS + c), khb + (size_t)(j0 + r)*HDD + c);
        cp16(smem_u32(Vh + r*AQS + c), vhb + (size_t)r*TT + j0 + c);
    }
}

__global__ __launch_bounds__(128, 3) void attn_tc()
{
    extern __shared__ bf16 asmem[];
    bf16* Qh = asmem;
    bf16* KV = Qh + 128*AQS;

    const int bh = blockIdx.y;
    const int hh = bh & (HH-1);
    const int b  = bh >> 4;
    const int qt = gridDim.x - 1 - blockIdx.x;
    const int q0 = qt * 128;
    const int njt = 2*qt + 2;

    const int tid  = threadIdx.x;
    const int lane = tid & 31;
    const int w    = tid >> 5;
    const int g    = lane >> 2;
    const int t    = lane & 3;

    const bf16* __restrict__ qhb = g_qh  + (size_t)bh * TT * HDD;
    const bf16* __restrict__ khb = g_kh  + (size_t)bh * TT * HDD;
    const __half* __restrict__ vhb = g_vtf + (size_t)bh * HDD * TT;

    for (int idx = tid; idx < 1024; idx += 128) {
        int r = idx >> 3;
        int c = (idx & 7) * 8;
        *(uint4*)(Qh + r*AQS + c) = *(const uint4*)(qhb + (size_t)(q0 + r)*HDD + c);
    }

    attn_load_kv(khb, vhb, 0, KV, tid); CP_COMMIT();

    float o[2][8][4];
    float m[4], l[4];
    #pragma unroll
    for (int mf = 0; mf < 2; mf++)
        #pragma unroll
        for (int et = 0; et < 8; et++)
            #pragma unroll
            for (int r = 0; r < 4; r++) o[mf][et][r] = 0.0f;
    #pragma unroll
    for (int i = 0; i < 4; i++) { m[i] = -1e30f; l[i] = 0.0f; }

    const int a_r  = lane & 15;
    const int a_c  = (lane >> 4) << 3;
    const int b4_r = ((lane >> 4) << 3) + (lane & 7);
    const int b4_c = ((lane >> 3) & 1) << 3;

    const int r0w = q0 + w*32;

    for (int jt = 0; jt < njt; jt++) {
        const int j0 = jt * 64;

        __syncthreads();
        if (jt + 1 < njt)
            attn_load_kv(khb, vhb, (jt+1)*64, KV + ((jt+1)&1)*2*KVARR, tid);
        CP_COMMIT();
        cp_wait<1>();
        __syncthreads();

        if (j0 > r0w + 31) continue;

        bf16* Kh = KV + (jt&1)*2*KVARR;
        bf16* Vh = Kh + KVARR;   // fp16 payload

        float s[2][8][4];
        #pragma unroll
        for (int mf = 0; mf < 2; mf++)
            #pragma unroll
            for (int nt = 0; nt < 8; nt++)
                #pragma unroll
                for (int r = 0; r < 4; r++) s[mf][nt][r] = 0.0f;

        #pragma unroll
        for (int kk = 0; kk < 4; kk++) {
            uint32_t qah[2][4];
            #pragma unroll
            for (int mf = 0; mf < 2; mf++)
                ldsm_x4(qah[mf], smem_u32(Qh + (w*32 + mf*16 + a_r)*AQS + kk*16 + a_c));
            #pragma unroll
            for (int p = 0; p < 4; p++) {
                uint32_t kh4[4];
                ldsm_x4(kh4, smem_u32(Kh + (p*16 + b4_r)*AQS + kk*16 + b4_c));
                #pragma unroll
                for (int mf = 0; mf < 2; mf++) {
                    mma16816(s[mf][2*p],   qah[mf], kh4[0], kh4[1]);
                    mma16816(s[mf][2*p+1], qah[mf], kh4[2], kh4[3]);
                }
            }
        }

        if (j0 + 63 > r0w) {
            #pragma unroll
            for (int mf = 0; mf < 2; mf++) {
                int r0 = r0w + mf*16 + g;
                int r1 = r0 + 8;
                #pragma unroll
                for (int nt = 0; nt < 8; nt++) {
                    int c0 = j0 + nt*8 + 2*t;
                    if (c0     > r0) s[mf][nt][0] = -1e30f;
                    if (c0 + 1 > r0) s[mf][nt][1] = -1e30f;
                    if (c0     > r1) s[mf][nt][2] = -1e30f;
                    if (c0 + 1 > r1) s[mf][nt][3] = -1e30f;
                }
            }
        }

        uint32_t ph[2][8][2];
        #pragma unroll
        for (int mf = 0; mf < 2; mf++) {
            float mx0 = -1e30f, mx1 = -1e30f;
            #pragma unroll
            for (int nt = 0; nt < 8; nt++) {
                mx0 = fmaxf(mx0, fmaxf(s[mf][nt][0], s[mf][nt][1]));
                mx1 = fmaxf(mx1, fmaxf(s[mf][nt][2], s[mf][nt][3]));
            }
            #pragma unroll
            for (int off = 1; off <= 2; off <<= 1) {
                mx0 = fmaxf(mx0, __shfl_xor_sync(0xffffffffu, mx0, off));
                mx1 = fmaxf(mx1, __shfl_xor_sync(0xffffffffu, mx1, off));
            }
            float mn0 = fmaxf(m[mf*2],   mx0);
            float mn1 = fmaxf(m[mf*2+1], mx1);
            float f0 = ex2f(m[mf*2]   - mn0);
            float f1 = ex2f(m[mf*2+1] - mn1);
            float rs0 = 0.0f, rs1 = 0.0f;
            #pragma unroll
            for (int nt = 0; nt < 8; nt++) {
                uint32_t w0 = h2ex2(f16pack(s[mf][nt][0] - mn0, s[mf][nt][1] - mn0));
                uint32_t w1 = h2ex2(f16pack(s[mf][nt][2] - mn1, s[mf][nt][3] - mn1));
                ph[mf][nt][0] = w0;
                ph[mf][nt][1] = w1;
                float2 fa = __half22float2(*(__half2*)&w0);
                float2 fb = __half22float2(*(__half2*)&w1);
                rs0 += fa.x + fa.y;
                rs1 += fb.x + fb.y;
            }
            #pragma unroll
            for (int off = 1; off <= 2; off <<= 1) {
                rs0 += __shfl_xor_sync(0xffffffffu, rs0, off);
                rs1 += __shfl_xor_sync(0xffffffffu, rs1, off);
            }
            l[mf*2]   = l[mf*2]   * f0 + rs0;
            l[mf*2+1] = l[mf*2+1] * f1 + rs1;
            m[mf*2]   = mn0;
            m[mf*2+1] = mn1;
            #pragma unroll
            for (int et = 0; et < 8; et++) {
                o[mf][et][0] *= f0; o[mf][et][1] *= f0;
                o[mf][et][2] *= f1; o[mf][et][3] *= f1;
            }
        }

        #pragma unroll
        for (int kt = 0; kt < 4; kt++) {
            uint32_t pa[2][4];
            #pragma unroll
            for (int mf = 0; mf < 2; mf++) {
                pa[mf][0] = ph[mf][2*kt][0];
                pa[mf][1] = ph[mf][2*kt][1];
                pa[mf][2] = ph[mf][2*kt+1][0];
                pa[mf][3] = ph[mf][2*kt+1][1];
            }
            #pragma unroll
            for (int pe = 0; pe < 4; pe++) {
                uint32_t vh4[4];
                ldsm_x4(vh4, smem_u32(Vh + (pe*16 + b4_r)*AQS + kt*16 + b4_c));
                #pragma unroll
                for (int mf = 0; mf < 2; mf++) {
                    mma16816h(o[mf][2*pe],   pa[mf], vh4[0], vh4[1]);
                    mma16816h(o[mf][2*pe+1], pa[mf], vh4[2], vh4[3]);
                }
            }
        }
    }

    #pragma unroll
    for (int mf = 0; mf < 2; mf++) {
        float inv0 = 1.0f / l[mf*2];
        float inv1 = 1.0f / l[mf*2+1];
        int tq = q0 + w*32 + mf*16 + g;
        #pragma unroll
        for (int et = 0; et < 8; et++) {
            int col = hh*HDD + et*8 + 2*t;
            size_t a0 = ((size_t)b*TT + tq)*DD + col;
            size_t a1 = ((size_t)b*TT + tq + 8)*DD + col;
            *(uint32_t*)&g_aof[a0] = f16pack(o[mf][et][0]*inv0, o[mf][et][1]*inv0);
            *(uint32_t*)&g_aof[a1] = f16pack(o[mf][et][2]*inv1, o[mf][et][3]*inv1);
        }
    }
}

// ============================================================================
// Launch
// ============================================================================
extern "C" void kernel_launch(void* const* d_in, const int* in_sizes, int n_in,
                              void* d_out, int out_size)
{
    const float* x  = (const float*)d_in[0];
    const float* Wq = (const float*)d_in[1];
    const float* Wk = (const float*)d_in[2];
    const float* Wv = (const float*)d_in[3];
    const float* Wo = (const float*)d_in[4];
    const float* bo = (const float*)d_in[5];
    float* out = (float*)d_out;

    cudaFuncSetAttribute(qkv_proj_tc, cudaFuncAttributeMaxDynamicSharedMemorySize,
                         QKV_SMEM_BYTES);
    cudaFuncSetAttribute(out_gemm_f16, cudaFuncAttributeMaxDynamicSharedMemorySize,
                         F16_PIPE_BYTES);
    cudaFuncSetAttribute(attn_tc, cudaFuncAttributeMaxDynamicSharedMemorySize,
                         ATTN_SMEM_BYTES);

    int nx = MTOT*DD/4, nw = DD*DD/4;
    convert_x_k<<<nx/256, 256>>>((const float4*)x);
    convert_w_k<<<dim3(nw/256, 4), 256>>>((const float4*)Wq, (const float4*)Wk,
                                          (const float4*)Wv, (const float4*)Wo);

    qkv_proj_tc<<<dim3(DD/128, MTOT/128, 3), 128, QKV_SMEM_BYTES>>>();
    attn_tc<<<dim3(TT/128, BB*HH), 128, ATTN_SMEM_BYTES>>>();
    out_gemm_f16<<<dim3(DD/128, MTOT/128), 128, F16_PIPE_BYTES>>>(bo, out);
}

// round 16
// speedup vs baseline: 7.2315x; 1.0032x over previous
#include <cuda_runtime.h>
#include <cuda_bf16.h>
#include <cuda_fp16.h>
#include <cstdint>
#include <math.h>

#define BB   4
#define TT   2048
#define DD   1024
#define HH   16
#define HDD  64
#define MTOT (BB*TT)   // 8192

typedef __nv_bfloat16  bf16;
typedef __nv_bfloat162 bf162;

// ---- precision-split globals ----
__device__ __half g_xf [(size_t)MTOT*DD], g_xfl[(size_t)MTOT*DD];  // x fp16 hi/lo
__device__ __half g_wqf[(size_t)DD*DD];
__device__ __half g_wkf[(size_t)DD*DD];
__device__ __half g_wvf[(size_t)DD*DD];
__device__ __half g_wof[(size_t)DD*DD];
__device__ bf16   g_qh [(size_t)MTOT*DD];                          // [B,H,T,HD] Q bf16, prescaled log2e/8
__device__ bf16   g_kh [(size_t)MTOT*DD];                          // [B,H,T,HD] K bf16
__device__ __half g_vtf[(size_t)MTOT*DD];                          // V^T [B,H,HD,T] fp16
__device__ __half g_aof[(size_t)MTOT*DD];                          // attn out [B,T,D] fp16

// ============================================================================
// Helpers
// ============================================================================
__device__ __forceinline__ uint32_t smem_u32(const void* p) {
    return (uint32_t)__cvta_generic_to_shared(p);
}
__device__ __forceinline__ void ldsm_x4(uint32_t r[4], uint32_t addr) {
    asm volatile("ldmatrix.sync.aligned.m8n8.x4.shared.b16 {%0,%1,%2,%3}, [%4];"
                 : "=r"(r[0]), "=r"(r[1]), "=r"(r[2]), "=r"(r[3]) : "r"(addr));
}
__device__ __forceinline__ void mma16816(float d[4], const uint32_t a[4], const uint32_t b0, const uint32_t b1) {
    asm volatile(
        "mma.sync.aligned.m16n8k16.row.col.f32.bf16.bf16.f32 "
        "{%0,%1,%2,%3}, {%4,%5,%6,%7}, {%8,%9}, {%0,%1,%2,%3};"
        : "+f"(d[0]), "+f"(d[1]), "+f"(d[2]), "+f"(d[3])
        : "r"(a[0]), "r"(a[1]), "r"(a[2]), "r"(a[3]), "r"(b0), "r"(b1));
}
__device__ __forceinline__ void mma16816h(float d[4], const uint32_t a[4], const uint32_t b0, const uint32_t b1) {
    asm volatile(
        "mma.sync.aligned.m16n8k16.row.col.f32.f16.f16.f32 "
        "{%0,%1,%2,%3}, {%4,%5,%6,%7}, {%8,%9}, {%0,%1,%2,%3};"
        : "+f"(d[0]), "+f"(d[1]), "+f"(d[2]), "+f"(d[3])
        : "r"(a[0]), "r"(a[1]), "r"(a[2]), "r"(a[3]), "r"(b0), "r"(b1));
}
__device__ __forceinline__ uint32_t bf16pack(float x, float y) {
    uint32_t r;
    asm("cvt.rn.bf16x2.f32 %0, %1, %2;" : "=r"(r) : "f"(y), "f"(x));
    return r;
}
__device__ __forceinline__ uint32_t f16pack(float x, float y) {
    uint32_t r;
    asm("cvt.rn.f16x2.f32 %0, %1, %2;" : "=r"(r) : "f"(y), "f"(x));
    return r;
}
__device__ __forceinline__ uint32_t h2ex2(uint32_t x) {
    uint32_t r;
    asm("ex2.approx.f16x2 %0, %1;" : "=r"(r) : "r"(x));
    return r;
}
__device__ __forceinline__ float ex2f(float x) {
    float r;
    asm("ex2.approx.f32 %0, %1;" : "=f"(r) : "f"(x));
    return r;
}
__device__ __forceinline__ void cp16(uint32_t s, const void* g) {
    asm volatile("cp.async.ca.shared.global [%0], [%1], 16;\n" :: "r"(s), "l"(g));
}
#define CP_COMMIT() asm volatile("cp.async.commit_group;\n" ::: "memory")
template<int N> __device__ __forceinline__ void cp_wait() {
    asm volatile("cp.async.wait_group %0;\n" :: "n"(N) : "memory");
}

// ============================================================================
// Convert kernels
// ============================================================================
__global__ __launch_bounds__(256) void convert_x_k(const float4* __restrict__ src)
{
    int i = blockIdx.x * 256 + threadIdx.x;
    float4 v = src[i];
    __half hx = __float2half_rn(v.x), hy = __float2half_rn(v.y);
    __half hz = __float2half_rn(v.z), hw = __float2half_rn(v.w);
    *(__half2*)(g_xf  + (size_t)i*4)     = __halves2half2(hx, hy);
    *(__half2*)(g_xf  + (size_t)i*4 + 2) = __halves2half2(hz, hw);
    *(__half2*)(g_xfl + (size_t)i*4)     = __floats2half2_rn(v.x - __half2float(hx),
                                                             v.y - __half2float(hy));
    *(__half2*)(g_xfl + (size_t)i*4 + 2) = __floats2half2_rn(v.z - __half2float(hz),
                                                             v.w - __half2float(hw));
}
__global__ __launch_bounds__(256) void convert_w_k(
    const float4* __restrict__ wq, const float4* __restrict__ wk,
    const float4* __restrict__ wv, const float4* __restrict__ wo)
{
    int which = blockIdx.y;
    const float4* src = (which == 0) ? wq : (which == 1) ? wk : (which == 2) ? wv : wo;
    __half* ho = (which == 0) ? g_wqf : (which == 1) ? g_wkf : (which == 2) ? g_wvf : g_wof;
    int i = blockIdx.x * 256 + threadIdx.x;
    float4 v = src[i];
    *(__half2*)(ho + (size_t)i*4)     = __floats2half2_rn(v.x, v.y);
    *(__half2*)(ho + (size_t)i*4 + 2) = __floats2half2_rn(v.z, v.w);
}

// ============================================================================
// fp16 GEMM mainloops (unchanged from R15)
// ============================================================================
#define LDKB 40
#define F16_STG   (128*LDKB)
#define F16_STG2  (2*F16_STG)
#define F16_STG3  (3*F16_STG)
#define F16_PIPE_BYTES  (2*F16_STG2*2) // 40960
#define QKV_SMEM_BYTES  69632

__device__ __forceinline__ void f16_load_stage(
    const __half* __restrict__ Ag, const __half* __restrict__ Bg,
    int m0, int n0, int k0, __half* base, int tid)
{
    #pragma unroll
    for (int s = 0; s < 4; s++) {
        int idx = tid + s*128;
        int r = idx >> 2;
        int c = (idx & 3) * 8;
        cp16(smem_u32(base + r*LDKB + c), Ag + (size_t)(m0 + r)*DD + k0 + c);
        cp16(smem_u32(base + F16_STG + r*LDKB + c), Bg + (size_t)(n0 + r)*DD + k0 + c);
    }
}

__device__ __forceinline__ void f16_gemm_mainloop(
    const __half* __restrict__ Ag, const __half* __restrict__ Bg,
    int m0, int n0, __half* smem, float acc[4][8][4])
{
    const int tid  = threadIdx.x;
    const int lane = tid & 31;
    const int warp = tid >> 5;
    const int wm = warp >> 1;
    const int wn = warp & 1;

    const int a_r  = lane & 15;
    const int a_c  = (lane >> 4) << 3;
    const int b4_r = ((lane >> 4) << 3) + (lane & 7);
    const int b4_c = ((lane >> 3) & 1) << 3;

    const int NST = DD / 32;

    f16_load_stage(Ag, Bg, m0, n0, 0, smem, tid); CP_COMMIT();

    for (int i = 0; i < NST; i++) {
        __syncthreads();
        if (i + 1 < NST)
            f16_load_stage(Ag, Bg, m0, n0, (i+1)*32, smem + ((i+1)&1)*F16_STG2, tid);
        CP_COMMIT();
        cp_wait<1>();
        __syncthreads();

        __half* As = smem + (i&1)*F16_STG2;
        __half* Bs = As + F16_STG;

        #pragma unroll
        for (int kk = 0; kk < 32; kk += 16) {
            uint32_t a4[4][4];
            #pragma unroll
            for (int mt = 0; mt < 4; mt++)
                ldsm_x4(a4[mt], smem_u32(As + (wm*64 + mt*16 + a_r)*LDKB + kk + a_c));
            #pragma unroll
            for (int p = 0; p < 4; p++) {
                uint32_t b4[4];
                ldsm_x4(b4, smem_u32(Bs + (wn*64 + p*16 + b4_r)*LDKB + kk + b4_c));
                #pragma unroll
                for (int mt = 0; mt < 4; mt++) {
                    mma16816h(acc[mt][2*p],   a4[mt], b4[0], b4[1]);
                    mma16816h(acc[mt][2*p+1], a4[mt], b4[2], b4[3]);
                }
            }
        }
    }
}

__device__ __forceinline__ void f16_load_stage3(
    const __half* __restrict__ Ahg, const __half* __restrict__ Alg,
    const __half* __restrict__ Bg,
    int m0, int n0, int k0, __half* base, int tid)
{
    #pragma unroll
    for (int s = 0; s < 4; s++) {
        int idx = tid + s*128;
        int r = idx >> 2;
        int c = (idx & 3) * 8;
        cp16(smem_u32(base + r*LDKB + c),              Ahg + (size_t)(m0 + r)*DD + k0 + c);
        cp16(smem_u32(base + F16_STG + r*LDKB + c),    Alg + (size_t)(m0 + r)*DD + k0 + c);
        cp16(smem_u32(base + 2*F16_STG + r*LDKB + c),  Bg  + (size_t)(n0 + r)*DD + k0 + c);
    }
}

__device__ __forceinline__ void f16_gemm2_mainloop(
    const __half* __restrict__ Ahg, const __half* __restrict__ Alg,
    const __half* __restrict__ Bg,
    int m0, int n0, __half* smem, float acc[4][8][4])
{
    const int tid  = threadIdx.x;
    const int lane = tid & 31;
    const int warp = tid >> 5;
    const int wm = warp >> 1;
    const int wn = warp & 1;

    const int a_r  = lane & 15;
    const int a_c  = (lane >> 4) << 3;
    const int b4_r = ((lane >> 4) << 3) + (lane & 7);
    const int b4_c = ((lane >> 3) & 1) << 3;

    const int NST = DD / 32;

    f16_load_stage3(Ahg, Alg, Bg, m0, n0, 0, smem, tid); CP_COMMIT();

    for (int i = 0; i < NST; i++) {
        __syncthreads();
        if (i + 1 < NST)
            f16_load_stage3(Ahg, Alg, Bg, m0, n0, (i+1)*32,
                            smem + ((i+1)&1)*F16_STG3, tid);
        CP_COMMIT();
        cp_wait<1>();
        __syncthreads();

        __half* Ahs = smem + (i&1)*F16_STG3;
        __half* Als = Ahs + F16_STG;
        __half* Bs  = Als + F16_STG;

        #pragma unroll
        for (int kk = 0; kk < 32; kk += 16) {
            uint32_t ah[4][4], al[4][4];
            #pragma unroll
            for (int mt = 0; mt < 4; mt++) {
                ldsm_x4(ah[mt], smem_u32(Ahs + (wm*64 + mt*16 + a_r)*LDKB + kk + a_c));
                ldsm_x4(al[mt], smem_u32(Als + (wm*64 + mt*16 + a_r)*LDKB + kk + a_c));
            }
            #pragma unroll
            for (int p = 0; p < 4; p++) {
                uint32_t b4[4];
                ldsm_x4(b4, smem_u32(Bs + (wn*64 + p*16 + b4_r)*LDKB + kk + b4_c));
                #pragma unroll
                for (int mt = 0; mt < 4; mt++) {
                    mma16816h(acc[mt][2*p],   ah[mt], b4[0], b4[1]);
                    mma16816h(acc[mt][2*p],   al[mt], b4[0], b4[1]);
                    mma16816h(acc[mt][2*p+1], ah[mt], b4[2], b4[3]);
                    mma16816h(acc[mt][2*p+1], al[mt], b4[2], b4[3]);
                }
            }
        }
    }
}

// ============================================================================
// Merged QKV projection (unchanged from R15)
// ============================================================================
__global__ __launch_bounds__(128) void qkv_proj_tc()
{
    extern __shared__ char dsm[];

    const int which = blockIdx.z;
    const int m0 = blockIdx.y * 128;
    const int n0 = blockIdx.x * 128;
    const int tid = threadIdx.x;
    const int bb = m0 >> 11;
    const int mloc = m0 & 2047;

    float acc[4][8][4];
    #pragma unroll
    for (int i = 0; i < 4; i++)
        #pragma unroll
        for (int j = 0; j < 8; j++)
            #pragma unroll
            for (int r = 0; r < 4; r++) acc[i][j][r] = 0.0f;

    const int lane = tid & 31;
    const int warp = tid >> 5;
    const int wm = warp >> 1, wn = warp & 1;
    const int g = lane >> 2, t = lane & 3;

    if (which == 2) {
        __half* fsm = (__half*)dsm;
        f16_gemm_mainloop(g_xf, g_wvf, m0, n0, fsm, acc);

        float* Cs = (float*)dsm;
        __syncthreads();
        #pragma unroll
        for (int mt = 0; mt < 4; mt++) {
            #pragma unroll
            for (int nt = 0; nt < 8; nt++) {
                int row = wm*64 + mt*16 + g;
                int col = wn*64 + nt*8 + 2*t;
                Cs[row*133 + col]       = acc[mt][nt][0];
                Cs[row*133 + col + 1]   = acc[mt][nt][1];
                Cs[(row+8)*133 + col]   = acc[mt][nt][2];
                Cs[(row+8)*133 + col+1] = acc[mt][nt][3];
            }
        }
        __syncthreads();
        for (int idx = tid; idx < 2048; idx += 128) {
            int el  = idx >> 4;
            int tch = (idx & 15) * 8;
            __half hv8[8];
            #pragma unroll
            for (int q = 0; q < 8; q++)
                hv8[q] = __float2half_rn(Cs[(tch + q)*133 + el]);
            int col = n0 + el;
            int hh = col >> 6, e = col & 63;
            size_t rb = (((size_t)bb*HH + hh)*HDD + e)*TT + mloc + tch;
            *(uint4*)&g_vtf[rb] = *(uint4*)hv8;
        }
        return;
    }

    __half* fsm = (__half*)dsm;
    const __half* Bg = (which == 0) ? g_wqf : g_wkf;
    f16_gemm2_mainloop(g_xf, g_xfl, Bg, m0, n0, fsm, acc);

    const float sc = (which == 0) ? (0.125f * 1.4426950408889634f) : 1.0f;
    bf16* outp = (which == 0) ? g_qh : g_kh;
    #pragma unroll
    for (int mt = 0; mt < 4; mt++) {
        #pragma unroll
        for (int nt = 0; nt < 8; nt++) {
            int row = mloc + wm*64 + mt*16 + g;
            int col = n0 + wn*64 + nt*8 + 2*t;
            int hh = col >> 6, e = col & 63;
            size_t a0 = (((size_t)bb*HH + hh)*TT + row)*HDD + e;
            size_t a1 = (((size_t)bb*HH + hh)*TT + row + 8)*HDD + e;
            *(uint32_t*)&outp[a0] = bf16pack(acc[mt][nt][0]*sc, acc[mt][nt][1]*sc);
            *(uint32_t*)&outp[a1] = bf16pack(acc[mt][nt][2]*sc, acc[mt][nt][3]*sc);
        }
    }
}

// Output projection (unchanged)
__global__ __launch_bounds__(128) void out_gemm_f16(
    const float* __restrict__ bo, float* __restrict__ outp)
{
    extern __shared__ __half fsm[];

    const int m0 = blockIdx.y * 128;
    const int n0 = blockIdx.x * 128;

    float acc[4][8][4];
    #pragma unroll
    for (int i = 0; i < 4; i++)
        #pragma unroll
        for (int j = 0; j < 8; j++)
            #pragma unroll
            for (int r = 0; r < 4; r++) acc[i][j][r] = 0.0f;

    f16_gemm_mainloop(g_aof, g_wof, m0, n0, fsm, acc);

    const int lane = threadIdx.x & 31;
    const int warp = threadIdx.x >> 5;
    const int wm = warp >> 1, wn = warp & 1;
    const int g = lane >> 2, t = lane & 3;

    #pragma unroll
    for (int mt = 0; mt < 4; mt++) {
        #pragma unroll
        for (int nt = 0; nt < 8; nt++) {
            int row = m0 + wm*64 + mt*16 + g;
            int col = n0 + wn*64 + nt*8 + 2*t;
            float bx = bo[col], by = bo[col+1];
            float2 v01 = make_float2(acc[mt][nt][0] + bx, acc[mt][nt][1] + by);
            float2 v23 = make_float2(acc[mt][nt][2] + bx, acc[mt][nt][3] + by);
            *(float2*)&outp[(size_t)row*DD + col]     = v01;
            *(float2*)&outp[(size_t)(row+8)*DD + col] = v23;
        }
    }
}

// ============================================================================
// Flash attention: 256 threads, 8 warps x 16 rows, q-tile 128.
// QK 1-term bf16; softmax ex2.f16x2 -> P; PV fp16 1-term.
// __launch_bounds__(256, 2): 2 CTAs/SM = 4 warps/SMSP.
// Same arithmetic per row as R15 (bit-identical numerics).
// ============================================================================
#define AQS 72
#define KVARR (64*AQS)
#define ATTN_Q_BYTES (128*AQS*2)                        // 18432
#define ATTN_KV_BYTES (2*2*KVARR*2)                     // 36864
#define ATTN_SMEM_BYTES (ATTN_Q_BYTES + ATTN_KV_BYTES)  // 55296

__device__ __forceinline__ void attn_load_kv(
    const bf16* khb, const __half* vhb,
    int j0, bf16* kvbase, int tid)
{
    bf16* Kh = kvbase;
    bf16* Vh = kvbase + KVARR;   // fp16 payload
    #pragma unroll
    for (int s = 0; s < 2; s++) {
        int idx = tid + s*256;
        int r = idx >> 3;
        int c = (idx & 7) * 8;
        cp16(smem_u32(Kh + r*AQS + c), khb + (size_t)(j0 + r)*HDD + c);
        cp16(smem_u32(Vh + r*AQS + c), vhb + (size_t)r*TT + j0 + c);
    }
}

__global__ __launch_bounds__(256, 2) void attn_tc()
{
    extern __shared__ bf16 asmem[];
    bf16* Qh = asmem;
    bf16* KV = Qh + 128*AQS;

    const int bh = blockIdx.y;
    const int hh = bh & (HH-1);
    const int b  = bh >> 4;
    const int qt = gridDim.x - 1 - blockIdx.x;
    const int q0 = qt * 128;
    const int njt = 2*qt + 2;

    const int tid  = threadIdx.x;
    const int lane = tid & 31;
    const int w    = tid >> 5;      // 0..7; warp rows q0 + w*16 .. +15
    const int g    = lane >> 2;
    const int t    = lane & 3;

    const bf16* __restrict__ qhb = g_qh  + (size_t)bh * TT * HDD;
    const bf16* __restrict__ khb = g_kh  + (size_t)bh * TT * HDD;
    const __half* __restrict__ vhb = g_vtf + (size_t)bh * HDD * TT;

    for (int idx = tid; idx < 1024; idx += 256) {
        int r = idx >> 3;
        int c = (idx & 7) * 8;
        *(uint4*)(Qh + r*AQS + c) = *(const uint4*)(qhb + (size_t)(q0 + r)*HDD + c);
    }

    attn_load_kv(khb, vhb, 0, KV, tid); CP_COMMIT();

    float o[8][4];
    float m[2], l[2];
    #pragma unroll
    for (int et = 0; et < 8; et++)
        #pragma unroll
        for (int r = 0; r < 4; r++) o[et][r] = 0.0f;
    m[0] = m[1] = -1e30f;
    l[0] = l[1] = 0.0f;

    const int a_r  = lane & 15;
    const int a_c  = (lane >> 4) << 3;
    const int b4_r = ((lane >> 4) << 3) + (lane & 7);
    const int b4_c = ((lane >> 3) & 1) << 3;

    const int r0w = q0 + w*16;

    for (int jt = 0; jt < njt; jt++) {
        const int j0 = jt * 64;

        __syncthreads();
        if (jt + 1 < njt)
            attn_load_kv(khb, vhb, (jt+1)*64, KV + ((jt+1)&1)*2*KVARR, tid);
        CP_COMMIT();
        cp_wait<1>();
        __syncthreads();

        if (j0 > r0w + 15) continue;   // fully masked for this warp

        bf16* Kh = KV + (jt&1)*2*KVARR;
        bf16* Vh = Kh + KVARR;   // fp16 payload

        // S = Qh Kh^T : 1-term
        float s[8][4];
        #pragma unroll
        for (int nt = 0; nt < 8; nt++)
            #pragma unroll
            for (int r = 0; r < 4; r++) s[nt][r] = 0.0f;

        #pragma unroll
        for (int kk = 0; kk < 4; kk++) {
            uint32_t qah[4];
            ldsm_x4(qah, smem_u32(Qh + (w*16 + a_r)*AQS + kk*16 + a_c));
            #pragma unroll
            for (int p = 0; p < 4; p++) {
                uint32_t kh4[4];
                ldsm_x4(kh4, smem_u32(Kh + (p*16 + b4_r)*AQS + kk*16 + b4_c));
                mma16816(s[2*p],   qah, kh4[0], kh4[1]);
                mma16816(s[2*p+1], qah, kh4[2], kh4[3]);
            }
        }

        if (j0 + 63 > r0w) {
            int r0 = r0w + g;
            int r1 = r0 + 8;
            #pragma unroll
            for (int nt = 0; nt < 8; nt++) {
                int c0 = j0 + nt*8 + 2*t;
                if (c0     > r0) s[nt][0] = -1e30f;
                if (c0 + 1 > r0) s[nt][1] = -1e30f;
                if (c0     > r1) s[nt][2] = -1e30f;
                if (c0 + 1 > r1) s[nt][3] = -1e30f;
            }
        }

        // Online softmax in log2 domain; ex2.f16x2 output = fp16 P fragments
        uint32_t ph[8][2];
        {
            float mx0 = -1e30f, mx1 = -1e30f;
            #pragma unroll
            for (int nt = 0; nt < 8; nt++) {
                mx0 = fmaxf(mx0, fmaxf(s[nt][0], s[nt][1]));
                mx1 = fmaxf(mx1, fmaxf(s[nt][2], s[nt][3]));
            }
            #pragma unroll
            for (int off = 1; off <= 2; off <<= 1) {
                mx0 = fmaxf(mx0, __shfl_xor_sync(0xffffffffu, mx0, off));
                mx1 = fmaxf(mx1, __shfl_xor_sync(0xffffffffu, mx1, off));
            }
            float mn0 = fmaxf(m[0], mx0);
            float mn1 = fmaxf(m[1], mx1);
            float f0 = ex2f(m[0] - mn0);
            float f1 = ex2f(m[1] - mn1);
            float rs0 = 0.0f, rs1 = 0.0f;
            #pragma unroll
            for (int nt = 0; nt < 8; nt++) {
                uint32_t w0 = h2ex2(f16pack(s[nt][0] - mn0, s[nt][1] - mn0));
                uint32_t w1 = h2ex2(f16pack(s[nt][2] - mn1, s[nt][3] - mn1));
                ph[nt][0] = w0;
                ph[nt][1] = w1;
                float2 fa = __half22float2(*(__half2*)&w0);
                float2 fb = __half22float2(*(__half2*)&w1);
                rs0 += fa.x + fa.y;
                rs1 += fb.x + fb.y;
            }
            #pragma unroll
            for (int off = 1; off <= 2; off <<= 1) {
                rs0 += __shfl_xor_sync(0xffffffffu, rs0, off);
                rs1 += __shfl_xor_sync(0xffffffffu, rs1, off);
            }
            l[0] = l[0] * f0 + rs0;
            l[1] = l[1] * f1 + rs1;
            m[0] = mn0;
            m[1] = mn1;
            #pragma unroll
            for (int et = 0; et < 8; et++) {
                o[et][0] *= f0; o[et][1] *= f0;
                o[et][2] *= f1; o[et][3] *= f1;
            }
        }

        // P*V: fp16 1-term
        #pragma unroll
        for (int kt = 0; kt < 4; kt++) {
            uint32_t pa[4];
            pa[0] = ph[2*kt][0];
            pa[1] = ph[2*kt][1];
            pa[2] = ph[2*kt+1][0];
            pa[3] = ph[2*kt+1][1];
            #pragma unroll
            for (int pe = 0; pe < 4; pe++) {
                uint32_t vh4[4];
                ldsm_x4(vh4, smem_u32(Vh + (pe*16 + b4_r)*AQS + kt*16 + b4_c));
                mma16816h(o[2*pe],   pa, vh4[0], vh4[1]);
                mma16816h(o[2*pe+1], pa, vh4[2], vh4[3]);
            }
        }
    }

    // Epilogue: normalize, write fp16 attn output [B,T,D]
    {
        float inv0 = 1.0f / l[0];
        float inv1 = 1.0f / l[1];
        int tq = q0 + w*16 + g;
        #pragma unroll
        for (int et = 0; et < 8; et++) {
            int col = hh*HDD + et*8 + 2*t;
            size_t a0 = ((size_t)b*TT + tq)*DD + col;
            size_t a1 = ((size_t)b*TT + tq + 8)*DD + col;
            *(uint32_t*)&g_aof[a0] = f16pack(o[et][0]*inv0, o[et][1]*inv0);
            *(uint32_t*)&g_aof[a1] = f16pack(o[et][2]*inv1, o[et][3]*inv1);
        }
    }
}

// ============================================================================
// Launch
// ============================================================================
extern "C" void kernel_launch(void* const* d_in, const int* in_sizes, int n_in,
                              void* d_out, int out_size)
{
    const float* x  = (const float*)d_in[0];
    const float* Wq = (const float*)d_in[1];
    const float* Wk = (const float*)d_in[2];
    const float* Wv = (const float*)d_in[3];
    const float* Wo = (const float*)d_in[4];
    const float* bo = (const float*)d_in[5];
    float* out = (float*)d_out;

    cudaFuncSetAttribute(qkv_proj_tc, cudaFuncAttributeMaxDynamicSharedMemorySize,
                         QKV_SMEM_BYTES);
    cudaFuncSetAttribute(out_gemm_f16, cudaFuncAttributeMaxDynamicSharedMemorySize,
                         F16_PIPE_BYTES);
    cudaFuncSetAttribute(attn_tc, cudaFuncAttributeMaxDynamicSharedMemorySize,
                         ATTN_SMEM_BYTES);

    int nx = MTOT*DD/4, nw = DD*DD/4;
    convert_x_k<<<nx/256, 256>>>((const float4*)x);
    convert_w_k<<<dim3(nw/256, 4), 256>>>((const float4*)Wq, (const float4*)Wk,
                                          (const float4*)Wv, (const float4*)Wo);

    qkv_proj_tc<<<dim3(DD/128, MTOT/128, 3), 128, QKV_SMEM_BYTES>>>();
    attn_tc<<<dim3(TT/128, BB*HH), 256, ATTN_SMEM_BYTES>>>();
    out_gemm_f16<<<dim3(DD/128, MTOT/128), 128, F16_PIPE_BYTES>>>(bo, out);
}

// round 17
// speedup vs baseline: 7.3071x; 1.0104x over previous
#include <cuda_runtime.h>
#include <cuda_bf16.h>
#include <cuda_fp16.h>
#include <cstdint>
#include <math.h>

#define BB   4
#define TT   2048
#define DD   1024
#define HH   16
#define HDD  64
#define MTOT (BB*TT)   // 8192

typedef __nv_bfloat16  bf16;
typedef __nv_bfloat162 bf162;

// ---- precision-split globals ----
__device__ __half g_xf [(size_t)MTOT*DD], g_xfl[(size_t)MTOT*DD];  // x fp16 hi/lo
__device__ __half g_wqf[(size_t)DD*DD];
__device__ __half g_wkf[(size_t)DD*DD];
__device__ __half g_wvf[(size_t)DD*DD];
__device__ __half g_wof[(size_t)DD*DD];
__device__ bf16   g_qh [(size_t)MTOT*DD];                          // [B,H,T,HD] Q bf16, prescaled log2e/8
__device__ bf16   g_kh [(size_t)MTOT*DD];                          // [B,H,T,HD] K bf16
__device__ __half g_vtf[(size_t)MTOT*DD];                          // V^T [B,H,HD,T] fp16
__device__ __half g_aof[(size_t)MTOT*DD];                          // attn out [B,T,D] fp16

// ============================================================================
// Helpers
// ============================================================================
__device__ __forceinline__ uint32_t smem_u32(const void* p) {
    return (uint32_t)__cvta_generic_to_shared(p);
}
__device__ __forceinline__ void ldsm_x4(uint32_t r[4], uint32_t addr) {
    asm volatile("ldmatrix.sync.aligned.m8n8.x4.shared.b16 {%0,%1,%2,%3}, [%4];"
                 : "=r"(r[0]), "=r"(r[1]), "=r"(r[2]), "=r"(r[3]) : "r"(addr));
}
__device__ __forceinline__ void mma16816(float d[4], const uint32_t a[4], const uint32_t b0, const uint32_t b1) {
    asm volatile(
        "mma.sync.aligned.m16n8k16.row.col.f32.bf16.bf16.f32 "
        "{%0,%1,%2,%3}, {%4,%5,%6,%7}, {%8,%9}, {%0,%1,%2,%3};"
        : "+f"(d[0]), "+f"(d[1]), "+f"(d[2]), "+f"(d[3])
        : "r"(a[0]), "r"(a[1]), "r"(a[2]), "r"(a[3]), "r"(b0), "r"(b1));
}
__device__ __forceinline__ void mma16816h(float d[4], const uint32_t a[4], const uint32_t b0, const uint32_t b1) {
    asm volatile(
        "mma.sync.aligned.m16n8k16.row.col.f32.f16.f16.f32 "
        "{%0,%1,%2,%3}, {%4,%5,%6,%7}, {%8,%9}, {%0,%1,%2,%3};"
        : "+f"(d[0]), "+f"(d[1]), "+f"(d[2]), "+f"(d[3])
        : "r"(a[0]), "r"(a[1]), "r"(a[2]), "r"(a[3]), "r"(b0), "r"(b1));
}
__device__ __forceinline__ uint32_t bf16pack(float x, float y) {
    uint32_t r;
    asm("cvt.rn.bf16x2.f32 %0, %1, %2;" : "=r"(r) : "f"(y), "f"(x));
    return r;
}
__device__ __forceinline__ uint32_t f16pack(float x, float y) {
    uint32_t r;
    asm("cvt.rn.f16x2.f32 %0, %1, %2;" : "=r"(r) : "f"(y), "f"(x));
    return r;
}
__device__ __forceinline__ uint32_t h2ex2(uint32_t x) {
    uint32_t r;
    asm("ex2.approx.f16x2 %0, %1;" : "=r"(r) : "r"(x));
    return r;
}
__device__ __forceinline__ float ex2f(float x) {
    float r;
    asm("ex2.approx.f32 %0, %1;" : "=f"(r) : "f"(x));
    return r;
}
__device__ __forceinline__ void cp16(uint32_t s, const void* g) {
    asm volatile("cp.async.ca.shared.global [%0], [%1], 16;\n" :: "r"(s), "l"(g));
}
#define CP_COMMIT() asm volatile("cp.async.commit_group;\n" ::: "memory")
template<int N> __device__ __forceinline__ void cp_wait() {
    asm volatile("cp.async.wait_group %0;\n" :: "n"(N) : "memory");
}

// ============================================================================
// Fused convert kernel: blocks [0, NXB) = x hi/lo; then 4 weight segments.
// ============================================================================
#define NXB (MTOT*DD/4/256)   // 8192
#define NWB (DD*DD/4/256)     // 1024

__global__ __launch_bounds__(256) void convert_all_k(
    const float4* __restrict__ x,
    const float4* __restrict__ wq, const float4* __restrict__ wk,
    const float4* __restrict__ wv, const float4* __restrict__ wo)
{
    int bx = blockIdx.x;
    if (bx < NXB) {
        int i = bx * 256 + threadIdx.x;
        float4 v = x[i];
        __half hx = __float2half_rn(v.x), hy = __float2half_rn(v.y);
        __half hz = __float2half_rn(v.z), hw = __float2half_rn(v.w);
        *(__half2*)(g_xf  + (size_t)i*4)     = __halves2half2(hx, hy);
        *(__half2*)(g_xf  + (size_t)i*4 + 2) = __halves2half2(hz, hw);
        *(__half2*)(g_xfl + (size_t)i*4)     = __floats2half2_rn(v.x - __half2float(hx),
                                                                 v.y - __half2float(hy));
        *(__half2*)(g_xfl + (size_t)i*4 + 2) = __floats2half2_rn(v.z - __half2float(hz),
                                                                 v.w - __half2float(hw));
    } else {
        int which = (bx - NXB) / NWB;
        int i = ((bx - NXB) % NWB) * 256 + threadIdx.x;
        const float4* src = (which == 0) ? wq : (which == 1) ? wk : (which == 2) ? wv : wo;
        __half* ho = (which == 0) ? g_wqf : (which == 1) ? g_wkf : (which == 2) ? g_wvf : g_wof;
        float4 v = src[i];
        *(__half2*)(ho + (size_t)i*4)     = __floats2half2_rn(v.x, v.y);
        *(__half2*)(ho + (size_t)i*4 + 2) = __floats2half2_rn(v.z, v.w);
    }
}

// ============================================================================
// fp16 GEMM mainloops (unchanged from R15/R16)
// ============================================================================
#define LDKB 40
#define F16_STG   (128*LDKB)
#define F16_STG2  (2*F16_STG)
#define F16_STG3  (3*F16_STG)
#define F16_PIPE_BYTES  (2*F16_STG2*2) // 40960
#define QKV_SMEM_BYTES  69632

__device__ __forceinline__ void f16_load_stage(
    const __half* __restrict__ Ag, const __half* __restrict__ Bg,
    int m0, int n0, int k0, __half* base, int tid)
{
    #pragma unroll
    for (int s = 0; s < 4; s++) {
        int idx = tid + s*128;
        int r = idx >> 2;
        int c = (idx & 3) * 8;
        cp16(smem_u32(base + r*LDKB + c), Ag + (size_t)(m0 + r)*DD + k0 + c);
        cp16(smem_u32(base + F16_STG + r*LDKB + c), Bg + (size_t)(n0 + r)*DD + k0 + c);
    }
}

__device__ __forceinline__ void f16_gemm_mainloop(
    const __half* __restrict__ Ag, const __half* __restrict__ Bg,
    int m0, int n0, __half* smem, float acc[4][8][4])
{
    const int tid  = threadIdx.x;
    const int lane = tid & 31;
    const int warp = tid >> 5;
    const int wm = warp >> 1;
    const int wn = warp & 1;

    const int a_r  = lane & 15;
    const int a_c  = (lane >> 4) << 3;
    const int b4_r = ((lane >> 4) << 3) + (lane & 7);
    const int b4_c = ((lane >> 3) & 1) << 3;

    const int NST = DD / 32;

    f16_load_stage(Ag, Bg, m0, n0, 0, smem, tid); CP_COMMIT();

    for (int i = 0; i < NST; i++) {
        __syncthreads();
        if (i + 1 < NST)
            f16_load_stage(Ag, Bg, m0, n0, (i+1)*32, smem + ((i+1)&1)*F16_STG2, tid);
        CP_COMMIT();
        cp_wait<1>();
        __syncthreads();

        __half* As = smem + (i&1)*F16_STG2;
        __half* Bs = As + F16_STG;

        #pragma unroll
        for (int kk = 0; kk < 32; kk += 16) {
            uint32_t a4[4][4];
            #pragma unroll
            for (int mt = 0; mt < 4; mt++)
                ldsm_x4(a4[mt], smem_u32(As + (wm*64 + mt*16 + a_r)*LDKB + kk + a_c));
            #pragma unroll
            for (int p = 0; p < 4; p++) {
                uint32_t b4[4];
                ldsm_x4(b4, smem_u32(Bs + (wn*64 + p*16 + b4_r)*LDKB + kk + b4_c));
                #pragma unroll
                for (int mt = 0; mt < 4; mt++) {
                    mma16816h(acc[mt][2*p],   a4[mt], b4[0], b4[1]);
                    mma16816h(acc[mt][2*p+1], a4[mt], b4[2], b4[3]);
                }
            }
        }
    }
}

__device__ __forceinline__ void f16_load_stage3(
    const __half* __restrict__ Ahg, const __half* __restrict__ Alg,
    const __half* __restrict__ Bg,
    int m0, int n0, int k0, __half* base, int tid)
{
    #pragma unroll
    for (int s = 0; s < 4; s++) {
        int idx = tid + s*128;
        int r = idx >> 2;
        int c = (idx & 3) * 8;
        cp16(smem_u32(base + r*LDKB + c),              Ahg + (size_t)(m0 + r)*DD + k0 + c);
        cp16(smem_u32(base + F16_STG + r*LDKB + c),    Alg + (size_t)(m0 + r)*DD + k0 + c);
        cp16(smem_u32(base + 2*F16_STG + r*LDKB + c),  Bg  + (size_t)(n0 + r)*DD + k0 + c);
    }
}

__device__ __forceinline__ void f16_gemm2_mainloop(
    const __half* __restrict__ Ahg, const __half* __restrict__ Alg,
    const __half* __restrict__ Bg,
    int m0, int n0, __half* smem, float acc[4][8][4])
{
    const int tid  = threadIdx.x;
    const int lane = tid & 31;
    const int warp = tid >> 5;
    const int wm = warp >> 1;
    const int wn = warp & 1;

    const int a_r  = lane & 15;
    const int a_c  = (lane >> 4) << 3;
    const int b4_r = ((lane >> 4) << 3) + (lane & 7);
    const int b4_c = ((lane >> 3) & 1) << 3;

    const int NST = DD / 32;

    f16_load_stage3(Ahg, Alg, Bg, m0, n0, 0, smem, tid); CP_COMMIT();

    for (int i = 0; i < NST; i++) {
        __syncthreads();
        if (i + 1 < NST)
            f16_load_stage3(Ahg, Alg, Bg, m0, n0, (i+1)*32,
                            smem + ((i+1)&1)*F16_STG3, tid);
        CP_COMMIT();
        cp_wait<1>();
        __syncthreads();

        __half* Ahs = smem + (i&1)*F16_STG3;
        __half* Als = Ahs + F16_STG;
        __half* Bs  = Als + F16_STG;

        #pragma unroll
        for (int kk = 0; kk < 32; kk += 16) {
            uint32_t ah[4][4], al[4][4];
            #pragma unroll
            for (int mt = 0; mt < 4; mt++) {
                ldsm_x4(ah[mt], smem_u32(Ahs + (wm*64 + mt*16 + a_r)*LDKB + kk + a_c));
                ldsm_x4(al[mt], smem_u32(Als + (wm*64 + mt*16 + a_r)*LDKB + kk + a_c));
            }
            #pragma unroll
            for (int p = 0; p < 4; p++) {
                uint32_t b4[4];
                ldsm_x4(b4, smem_u32(Bs + (wn*64 + p*16 + b4_r)*LDKB + kk + b4_c));
                #pragma unroll
                for (int mt = 0; mt < 4; mt++) {
                    mma16816h(acc[mt][2*p],   ah[mt], b4[0], b4[1]);
                    mma16816h(acc[mt][2*p],   al[mt], b4[0], b4[1]);
                    mma16816h(acc[mt][2*p+1], ah[mt], b4[2], b4[3]);
                    mma16816h(acc[mt][2*p+1], al[mt], b4[2], b4[3]);
                }
            }
        }
    }
}

// ============================================================================
// Merged QKV projection (unchanged)
// ============================================================================
__global__ __launch_bounds__(128) void qkv_proj_tc()
{
    extern __shared__ char dsm[];

    const int which = blockIdx.z;
    const int m0 = blockIdx.y * 128;
    const int n0 = blockIdx.x * 128;
    const int tid = threadIdx.x;
    const int bb = m0 >> 11;
    const int mloc = m0 & 2047;

    float acc[4][8][4];
    #pragma unroll
    for (int i = 0; i < 4; i++)
        #pragma unroll
        for (int j = 0; j < 8; j++)
            #pragma unroll
            for (int r = 0; r < 4; r++) acc[i][j][r] = 0.0f;

    const int lane = tid & 31;
    const int warp = tid >> 5;
    const int wm = warp >> 1, wn = warp & 1;
    const int g = lane >> 2, t = lane & 3;

    if (which == 2) {
        __half* fsm = (__half*)dsm;
        f16_gemm_mainloop(g_xf, g_wvf, m0, n0, fsm, acc);

        float* Cs = (float*)dsm;
        __syncthreads();
        #pragma unroll
        for (int mt = 0; mt < 4; mt++) {
            #pragma unroll
            for (int nt = 0; nt < 8; nt++) {
                int row = wm*64 + mt*16 + g;
                int col = wn*64 + nt*8 + 2*t;
                Cs[row*133 + col]       = acc[mt][nt][0];
                Cs[row*133 + col + 1]   = acc[mt][nt][1];
                Cs[(row+8)*133 + col]   = acc[mt][nt][2];
                Cs[(row+8)*133 + col+1] = acc[mt][nt][3];
            }
        }
        __syncthreads();
        for (int idx = tid; idx < 2048; idx += 128) {
            int el  = idx >> 4;
            int tch = (idx & 15) * 8;
            __half hv8[8];
            #pragma unroll
            for (int q = 0; q < 8; q++)
                hv8[q] = __float2half_rn(Cs[(tch + q)*133 + el]);
            int col = n0 + el;
            int hh = col >> 6, e = col & 63;
            size_t rb = (((size_t)bb*HH + hh)*HDD + e)*TT + mloc + tch;
            *(uint4*)&g_vtf[rb] = *(uint4*)hv8;
        }
        return;
    }

    __half* fsm = (__half*)dsm;
    const __half* Bg = (which == 0) ? g_wqf : g_wkf;
    f16_gemm2_mainloop(g_xf, g_xfl, Bg, m0, n0, fsm, acc);

    const float sc = (which == 0) ? (0.125f * 1.4426950408889634f) : 1.0f;
    bf16* outp = (which == 0) ? g_qh : g_kh;
    #pragma unroll
    for (int mt = 0; mt < 4; mt++) {
        #pragma unroll
        for (int nt = 0; nt < 8; nt++) {
            int row = mloc + wm*64 + mt*16 + g;
            int col = n0 + wn*64 + nt*8 + 2*t;
            int hh = col >> 6, e = col & 63;
            size_t a0 = (((size_t)bb*HH + hh)*TT + row)*HDD + e;
            size_t a1 = (((size_t)bb*HH + hh)*TT + row + 8)*HDD + e;
            *(uint32_t*)&outp[a0] = bf16pack(acc[mt][nt][0]*sc, acc[mt][nt][1]*sc);
            *(uint32_t*)&outp[a1] = bf16pack(acc[mt][nt][2]*sc, acc[mt][nt][3]*sc);
        }
    }
}

// Output projection (unchanged)
__global__ __launch_bounds__(128) void out_gemm_f16(
    const float* __restrict__ bo, float* __restrict__ outp)
{
    extern __shared__ __half fsm[];

    const int m0 = blockIdx.y * 128;
    const int n0 = blockIdx.x * 128;

    float acc[4][8][4];
    #pragma unroll
    for (int i = 0; i < 4; i++)
        #pragma unroll
        for (int j = 0; j < 8; j++)
            #pragma unroll
            for (int r = 0; r < 4; r++) acc[i][j][r] = 0.0f;

    f16_gemm_mainloop(g_aof, g_wof, m0, n0, fsm, acc);

    const int lane = threadIdx.x & 31;
    const int warp = threadIdx.x >> 5;
    const int wm = warp >> 1, wn = warp & 1;
    const int g = lane >> 2, t = lane & 3;

    #pragma unroll
    for (int mt = 0; mt < 4; mt++) {
        #pragma unroll
        for (int nt = 0; nt < 8; nt++) {
            int row = m0 + wm*64 + mt*16 + g;
            int col = n0 + wn*64 + nt*8 + 2*t;
            float bx = bo[col], by = bo[col+1];
            float2 v01 = make_float2(acc[mt][nt][0] + bx, acc[mt][nt][1] + by);
            float2 v23 = make_float2(acc[mt][nt][2] + bx, acc[mt][nt][3] + by);
            *(float2*)&outp[(size_t)row*DD + col]     = v01;
            *(float2*)&outp[(size_t)(row+8)*DD + col] = v23;
        }
    }
}

// ============================================================================
// Flash attention: 256 threads, 8 warps x 16 rows, q-tile 128.
// Q fragments persistent in registers; ex2/pack fused into PV loop
// (bit-identical value sequence to R16). 2 CTAs/SM.
// ============================================================================
#define AQS 72
#define KVARR (64*AQS)
#define ATTN_Q_BYTES (128*AQS*2)                        // 18432
#define ATTN_KV_BYTES (2*2*KVARR*2)                     // 36864
#define ATTN_SMEM_BYTES (ATTN_Q_BYTES + ATTN_KV_BYTES)  // 55296

__device__ __forceinline__ void attn_load_kv(
    const bf16* khb, const __half* vhb,
    int j0, bf16* kvbase, int tid)
{
    bf16* Kh = kvbase;
    bf16* Vh = kvbase + KVARR;   // fp16 payload
    #pragma unroll
    for (int s = 0; s < 2; s++) {
        int idx = tid + s*256;
        int r = idx >> 3;
        int c = (idx & 7) * 8;
        cp16(smem_u32(Kh + r*AQS + c), khb + (size_t)(j0 + r)*HDD + c);
        cp16(smem_u32(Vh + r*AQS + c), vhb + (size_t)r*TT + j0 + c);
    }
}

__global__ __launch_bounds__(256, 2) void attn_tc()
{
    extern __shared__ bf16 asmem[];
    bf16* Qh = asmem;
    bf16* KV = Qh + 128*AQS;

    const int bh = blockIdx.y;
    const int hh = bh & (HH-1);
    const int b  = bh >> 4;
    const int qt = gridDim.x - 1 - blockIdx.x;
    const int q0 = qt * 128;
    const int njt = 2*qt + 2;

    const int tid  = threadIdx.x;
    const int lane = tid & 31;
    const int w    = tid >> 5;
    const int g    = lane >> 2;
    const int t    = lane & 3;

    const bf16* __restrict__ qhb = g_qh  + (size_t)bh * TT * HDD;
    const bf16* __restrict__ khb = g_kh  + (size_t)bh * TT * HDD;
    const __half* __restrict__ vhb = g_vtf + (size_t)bh * HDD * TT;

    for (int idx = tid; idx < 1024; idx += 256) {
        int r = idx >> 3;
        int c = (idx & 7) * 8;
        *(uint4*)(Qh + r*AQS + c) = *(const uint4*)(qhb + (size_t)(q0 + r)*HDD + c);
    }

    attn_load_kv(khb, vhb, 0, KV, tid); CP_COMMIT();

    const int a_r  = lane & 15;
    const int a_c  = (lane >> 4) << 3;
    const int b4_r = ((lane >> 4) << 3) + (lane & 7);
    const int b4_c = ((lane >> 3) & 1) << 3;

    // Persistent Q fragments: load once (loop-invariant across jt)
    __syncthreads();
    uint32_t qf[4][4];
    #pragma unroll
    for (int kk = 0; kk < 4; kk++)
        ldsm_x4(qf[kk], smem_u32(Qh + (w*16 + a_r)*AQS + kk*16 + a_c));

    float o[8][4];
    float m[2], l[2];
    #pragma unroll
    for (int et = 0; et < 8; et++)
        #pragma unroll
        for (int r = 0; r < 4; r++) o[et][r] = 0.0f;
    m[0] = m[1] = -1e30f;
    l[0] = l[1] = 0.0f;

    const int r0w = q0 + w*16;

    for (int jt = 0; jt < njt; jt++) {
        const int j0 = jt * 64;

        __syncthreads();
        if (jt + 1 < njt)
            attn_load_kv(khb, vhb, (jt+1)*64, KV + ((jt+1)&1)*2*KVARR, tid);
        CP_COMMIT();
        cp_wait<1>();
        __syncthreads();

        if (j0 > r0w + 15) continue;

        bf16* Kh = KV + (jt&1)*2*KVARR;
        bf16* Vh = Kh + KVARR;   // fp16 payload

        // S = Qh Kh^T : 1-term (Q from registers)
        float s[8][4];
        #pragma unroll
        for (int nt = 0; nt < 8; nt++)
            #pragma unroll
            for (int r = 0; r < 4; r++) s[nt][r] = 0.0f;

        #pragma unroll
        for (int kk = 0; kk < 4; kk++) {
            #pragma unroll
            for (int p = 0; p < 4; p++) {
                uint32_t kh4[4];
                ldsm_x4(kh4, smem_u32(Kh + (p*16 + b4_r)*AQS + kk*16 + b4_c));
                mma16816(s[2*p],   qf[kk], kh4[0], kh4[1]);
                mma16816(s[2*p+1], qf[kk], kh4[2], kh4[3]);
            }
        }

        if (j0 + 63 > r0w) {
            int r0 = r0w + g;
            int r1 = r0 + 8;
            #pragma unroll
            for (int nt = 0; nt < 8; nt++) {
                int c0 = j0 + nt*8 + 2*t;
                if (c0     > r0) s[nt][0] = -1e30f;
                if (c0 + 1 > r0) s[nt][1] = -1e30f;
                if (c0     > r1) s[nt][2] = -1e30f;
                if (c0 + 1 > r1) s[nt][3] = -1e30f;
            }
        }

        // Max-reduce + o rescale (same order as before)
        float mn0, mn1;
        {
            float mx0 = -1e30f, mx1 = -1e30f;
            #pragma unroll
            for (int nt = 0; nt < 8; nt++) {
                mx0 = fmaxf(mx0, fmaxf(s[nt][0], s[nt][1]));
                mx1 = fmaxf(mx1, fmaxf(s[nt][2], s[nt][3]));
            }
            #pragma unroll
            for (int off = 1; off <= 2; off <<= 1) {
                mx0 = fmaxf(mx0, __shfl_xor_sync(0xffffffffu, mx0, off));
                mx1 = fmaxf(mx1, __shfl_xor_sync(0xffffffffu, mx1, off));
            }
            mn0 = fmaxf(m[0], mx0);
            mn1 = fmaxf(m[1], mx1);
            float f0 = ex2f(m[0] - mn0);
            float f1 = ex2f(m[1] - mn1);
            m[0] = mn0;
            m[1] = mn1;
            l[0] *= f0;
            l[1] *= f1;
            #pragma unroll
            for (int et = 0; et < 8; et++) {
                o[et][0] *= f0; o[et][1] *= f0;
                o[et][2] *= f1; o[et][3] *= f1;
            }
        }

        // Fused ex2/pack + PV: P fragments computed just-in-time.
        // rs accumulation order matches the previous nt=0..7 sequence exactly.
        float rs0 = 0.0f, rs1 = 0.0f;
        #pragma unroll
        for (int kt = 0; kt < 4; kt++) {
            uint32_t pa[4];
            {
                int nt = 2*kt;
                uint32_t w0 = h2ex2(f16pack(s[nt][0] - mn0, s[nt][1] - mn0));
                uint32_t w1 = h2ex2(f16pack(s[nt][2] - mn1, s[nt][3] - mn1));
                pa[0] = w0; pa[1] = w1;
                float2 fa = __half22float2(*(__half2*)&w0);
                float2 fb = __half22float2(*(__half2*)&w1);
                rs0 += fa.x + fa.y;
                rs1 += fb.x + fb.y;
                nt = 2*kt + 1;
                w0 = h2ex2(f16pack(s[nt][0] - mn0, s[nt][1] - mn0));
                w1 = h2ex2(f16pack(s[nt][2] - mn1, s[nt][3] - mn1));
                pa[2] = w0; pa[3] = w1;
                fa = __half22float2(*(__half2*)&w0);
                fb = __half22float2(*(__half2*)&w1);
                rs0 += fa.x + fa.y;
                rs1 += fb.x + fb.y;
            }
            #pragma unroll
            for (int pe = 0; pe < 4; pe++) {
                uint32_t vh4[4];
                ldsm_x4(vh4, smem_u32(Vh + (pe*16 + b4_r)*AQS + kt*16 + b4_c));
                mma16816h(o[2*pe],   pa, vh4[0], vh4[1]);
                mma16816h(o[2*pe+1], pa, vh4[2], vh4[3]);
            }
        }
        #pragma unroll
        for (int off = 1; off <= 2; off <<= 1) {
            rs0 += __shfl_xor_sync(0xffffffffu, rs0, off);
            rs1 += __shfl_xor_sync(0xffffffffu, rs1, off);
        }
        l[0] += rs0;
        l[1] += rs1;
    }

    // Epilogue
    {
        float inv0 = 1.0f / l[0];
        float inv1 = 1.0f / l[1];
        int tq = q0 + w*16 + g;
        #pragma unroll
        for (int et = 0; et < 8; et++) {
            int col = hh*HDD + et*8 + 2*t;
            size_t a0 = ((size_t)b*TT + tq)*DD + col;
            size_t a1 = ((size_t)b*TT + tq + 8)*DD + col;
            *(uint32_t*)&g_aof[a0] = f16pack(o[et][0]*inv0, o[et][1]*inv0);
            *(uint32_t*)&g_aof[a1] = f16pack(o[et][2]*inv1, o[et][3]*inv1);
        }
    }
}

// ============================================================================
// Launch
// ============================================================================
extern "C" void kernel_launch(void* const* d_in, const int* in_sizes, int n_in,
                              void* d_out, int out_size)
{
    const float* x  = (const float*)d_in[0];
    const float* Wq = (const float*)d_in[1];
    const float* Wk = (const float*)d_in[2];
    const float* Wv = (const float*)d_in[3];
    const float* Wo = (const float*)d_in[4];
    const float* bo = (const float*)d_in[5];
    float* out = (float*)d_out;

    cudaFuncSetAttribute(qkv_proj_tc, cudaFuncAttributeMaxDynamicSharedMemorySize,
                         QKV_SMEM_BYTES);
    cudaFuncSetAttribute(out_gemm_f16, cudaFuncAttributeMaxDynamicSharedMemorySize,
                         F16_PIPE_BYTES);
    cudaFuncSetAttribute(attn_tc, cudaFuncAttributeMaxDynamicSharedMemorySize,
                         ATTN_SMEM_BYTES);

    convert_all_k<<<NXB + 4*NWB, 256>>>((const float4*)x,
                                        (const float4*)Wq, (const float4*)Wk,
                                        (const float4*)Wv, (const float4*)Wo);

    qkv_proj_tc<<<dim3(DD/128, MTOT/128, 3), 128, QKV_SMEM_BYTES>>>();
    attn_tc<<<dim3(TT/128, BB*HH), 256, ATTN_SMEM_BYTES>>>();
    out_gemm_f16<<<dim3(DD/128, MTOT/128), 128, F16_PIPE_BYTES>>>(bo, out);
}